// round 8
// baseline (speedup 1.0000x reference)
#include <cuda_runtime.h>
#include <cuda_bf16.h>
#include <math.h>
#include <stdint.h>

#define BATCH 4
#define NPT   8192
#define KNN   32

// ---------------- scratch (__device__ globals; no allocations allowed) ------
__device__ int   g_idx1[BATCH*NPT*KNN];
__device__ int   g_idx2[BATCH*NPT*KNN];
__device__ float g_x  [BATCH*NPT*9];
__device__ float g_ys1[BATCH*NPT*64];
__device__ float g_zc1[BATCH*NPT*64];
__device__ float g_x1 [BATCH*NPT*64];
__device__ float g_ys2[BATCH*NPT*64];
__device__ float g_zc2[BATCH*NPT*64];
__device__ float g_x2 [BATCH*NPT*64];

__device__ __forceinline__ float leakyf(float x) { return x >= 0.f ? x : 0.2f * x; }

// ---------------- KNN with exact stable top-k (ties -> lowest index) --------
// Score computed in the reference's fp32 association order:
//   xx    = (x*x + y*y) + z*z                      (plain rounded ops)
//   dot   = fma(z, z', fma(y, y', x*x'))           (GEMM K-chain)
//   inner = -2 * dot
//   s     = ((-xx_q) - inner) - xx_c
// Heap entries are 64-bit keys (sortable_f32(s) << 32) | ~index so every
// comparison implements lexicographic (score, -index) — identical tie
// semantics to jax.lax.top_k (stable, lowest index wins).
#define KNN_BLK  64
#define KNN_TILE 128

__device__ __forceinline__ unsigned f32key(float s) {
    unsigned b = __float_as_uint(s);
    return (b & 0x80000000u) ? ~b : (b | 0x80000000u);
}

__global__ void knn_kernel(const float* __restrict__ coords, int sn, int sc,
                           long bstride, int* __restrict__ out_idx)
{
    __shared__ float4 tile[KNN_TILE];   // (x, y, z, xx)
    __shared__ unsigned long long hk[KNN * KNN_BLK];

    const int tid = threadIdx.x;
    const int b   = blockIdx.y;
    const int q   = blockIdx.x * KNN_BLK + tid;
    const float* cb = coords + (long)b * bstride;

    const float qx = cb[(long)q * sn + 0 * sc];
    const float qy = cb[(long)q * sn + 1 * sc];
    const float qz = cb[(long)q * sn + 2 * sc];
    const float xxq = __fadd_rn(__fadd_rn(__fmul_rn(qx, qx), __fmul_rn(qy, qy)),
                                __fmul_rn(qz, qz));
    const float nxxq = -xxq;

    #pragma unroll
    for (int j = 0; j < KNN; j++) hk[j * KNN_BLK + tid] = 0ull;
    unsigned long long rootk = 0ull;

    for (int base = 0; base < NPT; base += KNN_TILE) {
        __syncthreads();
        for (int i = tid; i < KNN_TILE; i += KNN_BLK) {
            int n = base + i;
            float cx = cb[(long)n * sn];
            float cy = cb[(long)n * sn + sc];
            float cz = cb[(long)n * sn + 2 * sc];
            float xx = __fadd_rn(__fadd_rn(__fmul_rn(cx, cx), __fmul_rn(cy, cy)),
                                 __fmul_rn(cz, cz));
            tile[i] = make_float4(cx, cy, cz, xx);
        }
        __syncthreads();
        #pragma unroll 4
        for (int j = 0; j < KNN_TILE; j++) {
            float4 c = tile[j];
            float dot   = __fmaf_rn(qz, c.z, __fmaf_rn(qy, c.y, __fmul_rn(qx, c.x)));
            float inner = __fmul_rn(-2.f, dot);
            float s     = __fsub_rn(__fsub_rn(nxxq, inner), c.w);
            unsigned long long key =
                ((unsigned long long)f32key(s) << 32) | (unsigned)(~(base + j));
            if (key > rootk) {
                // replace min-root, sift down (depth <= 5 for 32 nodes)
                int i2 = 0;
                #pragma unroll
                for (int lvl = 0; lvl < 5; lvl++) {
                    int l = 2 * i2 + 1;
                    if (l >= KNN) break;
                    int m = l;
                    unsigned long long dm = hk[l * KNN_BLK + tid];
                    int r = l + 1;
                    if (r < KNN) {
                        unsigned long long dr = hk[r * KNN_BLK + tid];
                        if (dr < dm) { m = r; dm = dr; }
                    }
                    if (dm >= key) break;
                    hk[i2 * KNN_BLK + tid] = dm;
                    i2 = m;
                }
                hk[i2 * KNN_BLK + tid] = key;
                rootk = hk[tid];
            }
        }
    }
    int* op = out_idx + (long)(b * NPT + q) * KNN;
    #pragma unroll
    for (int j = 0; j < KNN; j++)
        op[j] = (int)(~(unsigned)hk[j * KNN_BLK + tid]);
}

// --------- geometry (cov eig features, double precision) + saliency + x ----
#define GEO_BLK 64

__global__ void geom_kernel(const float* __restrict__ points,
                            const int*   __restrict__ idx,
                            const float* __restrict__ sal_w1,
                            const float* __restrict__ sal_g, const float* __restrict__ sal_b,
                            const float* __restrict__ sal_m, const float* __restrict__ sal_v,
                            const float* __restrict__ sal_w2, const float* __restrict__ sal_b2,
                            float* __restrict__ xout)
{
    __shared__ float sx[KNN * GEO_BLK], sy[KNN * GEO_BLK], sz[KNN * GEO_BLK];
    const int tid = threadIdx.x;
    const int b   = blockIdx.y;
    const int q   = blockIdx.x * GEO_BLK + tid;
    const float* pb = points + (long)b * 3 * NPT;
    const int* ip = idx + (long)(b * NPT + q) * KNN;

    double mx = 0, my = 0, mz = 0;
    #pragma unroll
    for (int k = 0; k < KNN; k++) {
        int j = ip[k];
        float nx = pb[j], ny = pb[NPT + j], nz = pb[2 * NPT + j];
        sx[k * GEO_BLK + tid] = nx; sy[k * GEO_BLK + tid] = ny; sz[k * GEO_BLK + tid] = nz;
        mx += nx; my += ny; mz += nz;
    }
    mx *= (1.0 / KNN); my *= (1.0 / KNN); mz *= (1.0 / KNN);

    double cxx = 0, cxy = 0, cxz = 0, cyy = 0, cyz = 0, czz = 0;
    #pragma unroll
    for (int k = 0; k < KNN; k++) {
        double dx = (double)sx[k * GEO_BLK + tid] - mx;
        double dy = (double)sy[k * GEO_BLK + tid] - my;
        double dz = (double)sz[k * GEO_BLK + tid] - mz;
        cxx += dx * dx; cxy += dx * dy; cxz += dx * dz;
        cyy += dy * dy; cyz += dy * dz; czz += dz * dz;
    }
    const double invk = 1.0 / KNN;
    cxx *= invk; cxy *= invk; cxz *= invk; cyy *= invk; cyz *= invk; czz *= invk;

    // closed-form symmetric 3x3 eigenvalues
    double q3 = (cxx + cyy + czz) / 3.0;
    double p1 = cxy * cxy + cxz * cxz + cyz * cyz;
    double p2 = (cxx - q3) * (cxx - q3) + (cyy - q3) * (cyy - q3) + (czz - q3) * (czz - q3) + 2.0 * p1;
    double p = sqrt(p2 / 6.0);
    double e1, e2, e3;
    if (p < 1e-150) { e1 = e2 = e3 = q3; }
    else {
        double inv = 1.0 / p;
        double b00 = (cxx - q3) * inv, b11 = (cyy - q3) * inv, b22 = (czz - q3) * inv;
        double b01 = cxy * inv, b02 = cxz * inv, b12 = cyz * inv;
        double detB = b00 * (b11 * b22 - b12 * b12) - b01 * (b01 * b22 - b12 * b02)
                    + b02 * (b01 * b12 - b11 * b02);
        double r = 0.5 * detB;
        r = fmin(1.0, fmax(-1.0, r));
        double phi = acos(r) / 3.0;
        e1 = q3 + 2.0 * p * cos(phi);
        e3 = q3 + 2.0 * p * cos(phi + 2.0943951023931953);
        e2 = 3.0 * q3 - e1 - e3;
    }
    double l0 = e3, l1 = e2, l2 = e1;
    const double eps = 1e-8;
    float geomf[5];
    geomf[0] = (float)((l2 - l1) / (l2 + eps));         // linearity
    geomf[1] = (float)((l1 - l0) / (l2 + eps));         // planarity
    geomf[2] = (float)(l0 / (l2 + eps));                // sphericity
    geomf[3] = (float)(l0 / (l0 + l1 + l2 + eps));      // curvature
    geomf[4] = (float)((l2 - l0) / (l2 + eps));         // anisotropy

    // saliency MLP (5 -> 16 -> 1, sigmoid)
    float dot = 0.f;
    #pragma unroll
    for (int o = 0; o < 16; o++) {
        float h = 0.f;
        #pragma unroll
        for (int f = 0; f < 5; f++) h = fmaf(sal_w1[o * 5 + f], geomf[f], h);
        float s = sal_g[o] * rsqrtf(sal_v[o] + 1e-5f);
        float t = sal_b[o] - sal_m[o] * s;
        h = leakyf(fmaf(h, s, t));
        dot = fmaf(h, sal_w2[o], dot);
    }
    float sal = 1.f / (1.f + expf(-(dot + sal_b2[0])));

    float* xr = xout + (long)(b * NPT + q) * 9;
    xr[0] = pb[q]; xr[1] = pb[NPT + q]; xr[2] = pb[2 * NPT + q];
    xr[3] = geomf[0]; xr[4] = geomf[1]; xr[5] = geomf[2]; xr[6] = geomf[3]; xr[7] = geomf[4];
    xr[8] = sal;
}

// ------- per-node edge_conv precompute: ys = s*(Wd x), zc = s*((Wc-Wd)x)+t --
template<int CIN>
__global__ void convpre_kernel(const float* __restrict__ xin,
                               const float* __restrict__ w,   // (64, 2*CIN)
                               const float* __restrict__ bng, const float* __restrict__ bnb,
                               const float* __restrict__ bnm, const float* __restrict__ bnv,
                               float* __restrict__ ys, float* __restrict__ zc)
{
    long T = (long)blockIdx.x * blockDim.x + threadIdx.x;
    int  o = (int)(T & 63);
    long p = T >> 6;
    if (p >= (long)BATCH * NPT) return;
    const float* xr = xin + p * CIN;
    const float* wd = w + (long)o * 2 * CIN;
    const float* wc = wd + CIN;
    float ad = 0.f, ac = 0.f;
    #pragma unroll
    for (int c = 0; c < CIN; c++) {
        float xv = xr[c];
        float a = wd[c];
        ad = fmaf(a, xv, ad);
        ac = fmaf(wc[c] - a, xv, ac);
    }
    float s = bng[o] * rsqrtf(bnv[o] + 1e-5f);
    float t = bnb[o] - bnm[o] * s;
    ys[p * 64 + o] = s * ad;
    zc[p * 64 + o] = fmaf(s, ac, t);
}

// ------- edge_conv reduce: x_out[i] = leaky(max_k (ys[idx[i,k]] + zc[i])) ---
__global__ void edge_reduce_kernel(const float* __restrict__ ys, const float* __restrict__ zc,
                                   const int* __restrict__ idx, float* __restrict__ xout)
{
    long warp = ((long)blockIdx.x * blockDim.x + threadIdx.x) >> 5;
    int  lane = threadIdx.x & 31;
    if (warp >= (long)BATCH * NPT) return;
    const long bbase = (warp >> 13) << 13;   // batch base: idx values are per-batch
    int myj = idx[warp * KNN + lane];
    const float2* ysp = (const float2*)ys;
    float2 z = ((const float2*)zc)[warp * 32 + lane];
    float2 best = make_float2(-3.4e38f, -3.4e38f);
    #pragma unroll
    for (int k = 0; k < KNN; k++) {
        long j = bbase + __shfl_sync(0xffffffffu, myj, k);
        float2 v = ysp[j * 32 + lane];
        best.x = fmaxf(best.x, v.x + z.x);
        best.y = fmaxf(best.y, v.y + z.y);
    }
    best.x = leakyf(best.x);
    best.y = leakyf(best.y);
    ((float2*)xout)[warp * 32 + lane] = best;
}

// --------- classifier: h = leaky(bn(g@W1^T)); logits = h@W2^T + b2 ---------
#define CLS_GRID 256
#define CLS_PPB  ((BATCH*NPT)/CLS_GRID)   // 128 points per block

__global__ void cls_kernel(const float* __restrict__ x1, const float* __restrict__ x2,
                           const float* __restrict__ w1,
                           const float* __restrict__ bg, const float* __restrict__ bb,
                           const float* __restrict__ bm, const float* __restrict__ bv,
                           const float* __restrict__ w2, const float* __restrict__ b2,
                           float* __restrict__ out)
{
    extern __shared__ float sm[];
    float* WsT  = sm;               // [128][256] transposed, bank-conflict-free
    float* Ts   = WsT + 128 * 256;  // 256
    float* W2s  = Ts + 256;         // 2*256
    float* gbuf = W2s + 512;        // 128
    float* red  = gbuf + 128;       // 16

    const int tid = threadIdx.x;    // 256 threads, tid == output channel o
    {
        float s = bg[tid] * rsqrtf(bv[tid] + 1e-5f);
        Ts[tid] = bb[tid] - bm[tid] * s;
        for (int c = 0; c < 128; c++) WsT[c * 256 + tid] = w1[tid * 128 + c] * s;
        W2s[tid] = w2[tid]; W2s[256 + tid] = w2[256 + tid];
    }
    __syncthreads();

    for (int it = 0; it < CLS_PPB; it++) {
        long P = (long)blockIdx.x * CLS_PPB + it;
        if (tid < 64)       gbuf[tid] = x1[P * 64 + tid];
        else if (tid < 128) gbuf[tid] = x2[P * 64 + tid - 64];
        __syncthreads();

        float acc = Ts[tid];
        #pragma unroll 8
        for (int c = 0; c < 128; c++) acc = fmaf(WsT[c * 256 + tid], gbuf[c], acc);
        float h = leakyf(acc);
        float p0 = h * W2s[tid], p1 = h * W2s[256 + tid];
        #pragma unroll
        for (int off = 16; off; off >>= 1) {
            p0 += __shfl_down_sync(0xffffffffu, p0, off);
            p1 += __shfl_down_sync(0xffffffffu, p1, off);
        }
        int w = tid >> 5;
        if ((tid & 31) == 0) { red[w] = p0; red[8 + w] = p1; }
        __syncthreads();
        if (tid == 0) {
            float l0 = b2[0], l1 = b2[1];
            #pragma unroll
            for (int i = 0; i < 8; i++) { l0 += red[i]; l1 += red[8 + i]; }
            long bbatch = P / NPT, nn = P % NPT;
            out[bbatch * 2 * NPT + nn]       = l0;
            out[bbatch * 2 * NPT + NPT + nn] = l1;
        }
        __syncthreads();
    }
}

// ---------------------------------------------------------------------------
extern "C" void kernel_launch(void* const* d_in, const int* in_sizes, int n_in,
                              void* d_out, int out_size)
{
    const float* points  = (const float*)d_in[0];
    const float* sal_w1  = (const float*)d_in[1];
    const float* sal_g   = (const float*)d_in[2];
    const float* sal_b   = (const float*)d_in[3];
    const float* sal_m   = (const float*)d_in[4];
    const float* sal_v   = (const float*)d_in[5];
    const float* sal_w2  = (const float*)d_in[6];
    const float* sal_b2  = (const float*)d_in[7];
    const float* c1_w    = (const float*)d_in[8];
    const float* c1_g    = (const float*)d_in[9];
    const float* c1_b    = (const float*)d_in[10];
    const float* c1_m    = (const float*)d_in[11];
    const float* c1_v    = (const float*)d_in[12];
    const float* c2_w    = (const float*)d_in[13];
    const float* c2_g    = (const float*)d_in[14];
    const float* c2_b    = (const float*)d_in[15];
    const float* c2_m    = (const float*)d_in[16];
    const float* c2_v    = (const float*)d_in[17];
    const float* cls_w1  = (const float*)d_in[18];
    const float* cls_g   = (const float*)d_in[19];
    const float* cls_b   = (const float*)d_in[20];
    const float* cls_m   = (const float*)d_in[21];
    const float* cls_v   = (const float*)d_in[22];
    const float* cls_w2  = (const float*)d_in[23];
    const float* cls_b2  = (const float*)d_in[24];
    float* out = (float*)d_out;

    int*   idx1; cudaGetSymbolAddress((void**)&idx1, g_idx1);
    int*   idx2; cudaGetSymbolAddress((void**)&idx2, g_idx2);
    float* xf  ; cudaGetSymbolAddress((void**)&xf , g_x  );
    float* ys1 ; cudaGetSymbolAddress((void**)&ys1, g_ys1);
    float* zc1 ; cudaGetSymbolAddress((void**)&zc1, g_zc1);
    float* x1  ; cudaGetSymbolAddress((void**)&x1 , g_x1 );
    float* ys2 ; cudaGetSymbolAddress((void**)&ys2, g_ys2);
    float* zc2 ; cudaGetSymbolAddress((void**)&zc2, g_zc2);
    float* x2  ; cudaGetSymbolAddress((void**)&x2 , g_x2 );

    dim3 knn_grid(NPT / KNN_BLK, BATCH);

    // 1) knn on raw points (points layout (B,3,N): sn=1, sc=N)
    knn_kernel<<<knn_grid, KNN_BLK>>>(points, 1, NPT, (long)3 * NPT, idx1);

    // 2) geometry + saliency -> x (B,N,9)
    geom_kernel<<<dim3(NPT / GEO_BLK, BATCH), GEO_BLK>>>(
        points, idx1, sal_w1, sal_g, sal_b, sal_m, sal_v, sal_w2, sal_b2, xf);

    // 3) edge_conv1 precompute + reduce -> x1
    {
        long total = (long)BATCH * NPT * 64;
        convpre_kernel<9><<<(unsigned)(total / 128), 128>>>(xf, c1_w, c1_g, c1_b, c1_m, c1_v, ys1, zc1);
        edge_reduce_kernel<<<(BATCH * NPT) / 4, 128>>>(ys1, zc1, idx1, x1);
    }

    // 4) knn on x1[...,0:3] (layout (B,N,64): sn=64, sc=1)
    knn_kernel<<<knn_grid, KNN_BLK>>>(x1, 64, 1, (long)NPT * 64, idx2);

    // 5) edge_conv2 precompute + reduce -> x2
    {
        long total = (long)BATCH * NPT * 64;
        convpre_kernel<64><<<(unsigned)(total / 128), 128>>>(x1, c2_w, c2_g, c2_b, c2_m, c2_v, ys2, zc2);
        edge_reduce_kernel<<<(BATCH * NPT) / 4, 128>>>(ys2, zc2, idx2, x2);
    }

    // 6) classifier
    {
        size_t smem = (128 * 256 + 256 + 512 + 128 + 16) * sizeof(float);
        cudaFuncSetAttribute(cls_kernel, cudaFuncAttributeMaxDynamicSharedMemorySize, (int)smem);
        cls_kernel<<<CLS_GRID, 256, smem>>>(x1, x2, cls_w1,
                                            cls_g, cls_b, cls_m, cls_v,
                                            cls_w2, cls_b2, out);
    }
}

// round 11
// speedup vs baseline: 1.2237x; 1.2237x over previous
#include <cuda_runtime.h>
#include <cuda_bf16.h>
#include <math.h>
#include <stdint.h>

#define BATCH 4
#define NPT   8192
#define KNN   32

#define GRES  16
#define NCELL (GRES*GRES*GRES)   // 4096
#define TPT   64                 // points per tile
#define NTILE (NPT/TPT)          // 128

// ---------------- scratch (__device__ globals; no allocations allowed) ------
__device__ int    g_idx1[BATCH*NPT*KNN];
__device__ int    g_idx2[BATCH*NPT*KNN];
__device__ float  g_x  [BATCH*NPT*9];
__device__ float  g_ys1[BATCH*NPT*64];
__device__ float  g_zc1[BATCH*NPT*64];
__device__ float  g_x1 [BATCH*NPT*64];
__device__ float  g_ys2[BATCH*NPT*64];
__device__ float  g_zc2[BATCH*NPT*64];
__device__ float  g_x2 [BATCH*NPT*64];
// knn spatial-structure scratch (reused by knn1 then knn2)
__device__ float4 g_pts4[BATCH*NPT];
__device__ int    g_pid [BATCH*NPT];
__device__ int    g_cellid[BATCH*NPT];
__device__ int    g_hist  [BATCH*NCELL];
__device__ int    g_cstart[BATCH*NCELL];
__device__ int    g_cursor[BATCH*NCELL];
__device__ float  g_tlo[BATCH*NTILE*3];
__device__ float  g_thi[BATCH*NTILE*3];
__device__ float  g_tmx[BATCH*NTILE];
__device__ float  g_blo[BATCH*3];
__device__ float  g_bhi[BATCH*3];

__device__ __forceinline__ float leakyf(float x) { return x >= 0.f ? x : 0.2f * x; }

// sortable key helpers: lexicographic (score, -index), identical tie semantics
// to jax.lax.top_k (stable, lowest index wins).
__device__ __forceinline__ unsigned f32key(float s) {
    unsigned b = __float_as_uint(s);
    return (b & 0x80000000u) ? ~b : (b | 0x80000000u);
}
__device__ __forceinline__ float unkey(unsigned k) {
    unsigned b = (k & 0x80000000u) ? (k ^ 0x80000000u) : ~k;
    return __uint_as_float(b);
}

__device__ __forceinline__ int spread4(int v) {
    return (v & 1) | ((v & 2) << 2) | ((v & 4) << 4) | ((v & 8) << 6);
}
__device__ __forceinline__ int morton3(int x, int y, int z) {
    return spread4(x) | (spread4(y) << 1) | (spread4(z) << 2);
}

// ---------------- stage A: per-batch coordinate bounds (+ zero counters) ----
__global__ void bounds_kernel(const float* __restrict__ coords, int sn, int sc,
                              long bstride)
{
    __shared__ float slo[3][256], shi[3][256];
    const int b = blockIdx.x, tid = threadIdx.x;
    const float* cb = coords + (long)b * bstride;
    float l0 = 3.4e38f, l1 = 3.4e38f, l2 = 3.4e38f;
    float h0 = -3.4e38f, h1 = -3.4e38f, h2 = -3.4e38f;
    for (int n = tid; n < NPT; n += 256) {
        float x = cb[(long)n * sn], y = cb[(long)n * sn + sc], z = cb[(long)n * sn + 2 * sc];
        l0 = fminf(l0, x); h0 = fmaxf(h0, x);
        l1 = fminf(l1, y); h1 = fmaxf(h1, y);
        l2 = fminf(l2, z); h2 = fmaxf(h2, z);
    }
    slo[0][tid] = l0; slo[1][tid] = l1; slo[2][tid] = l2;
    shi[0][tid] = h0; shi[1][tid] = h1; shi[2][tid] = h2;
    __syncthreads();
    for (int off = 128; off; off >>= 1) {
        if (tid < off) {
            #pragma unroll
            for (int a = 0; a < 3; a++) {
                slo[a][tid] = fminf(slo[a][tid], slo[a][tid + off]);
                shi[a][tid] = fmaxf(shi[a][tid], shi[a][tid + off]);
            }
        }
        __syncthreads();
    }
    if (tid < 3) { g_blo[b * 3 + tid] = slo[tid][0]; g_bhi[b * 3 + tid] = shi[tid][0]; }
    for (int i = tid; i < NCELL; i += 256) {
        g_hist[b * NCELL + i] = 0;
        g_cursor[b * NCELL + i] = 0;
    }
}

// ---------------- stage B: cell ids + histogram -----------------------------
__global__ void cellcount_kernel(const float* __restrict__ coords, int sn, int sc,
                                 long bstride)
{
    const int b = blockIdx.y;
    const int n = blockIdx.x * 256 + threadIdx.x;
    const float* cb = coords + (long)b * bstride;
    float x = cb[(long)n * sn], y = cb[(long)n * sn + sc], z = cb[(long)n * sn + 2 * sc];
    float lo0 = g_blo[b * 3], lo1 = g_blo[b * 3 + 1], lo2 = g_blo[b * 3 + 2];
    float s0 = (float)GRES / fmaxf(g_bhi[b * 3]     - lo0, 1e-30f);
    float s1 = (float)GRES / fmaxf(g_bhi[b * 3 + 1] - lo1, 1e-30f);
    float s2 = (float)GRES / fmaxf(g_bhi[b * 3 + 2] - lo2, 1e-30f);
    int cx = min(GRES - 1, max(0, (int)((x - lo0) * s0)));
    int cy = min(GRES - 1, max(0, (int)((y - lo1) * s1)));
    int cz = min(GRES - 1, max(0, (int)((z - lo2) * s2)));
    int cell = morton3(cx, cy, cz);
    g_cellid[b * NPT + n] = cell;
    atomicAdd(&g_hist[b * NCELL + cell], 1);
}

// ---------------- stage C: per-batch exclusive scan over 4096 cells ---------
__global__ void scan_kernel()
{
    __shared__ int ss[1024];
    const int b = blockIdx.x, tid = threadIdx.x;
    int v[4]; int base = tid * 4; int s = 0;
    #pragma unroll
    for (int i = 0; i < 4; i++) { v[i] = g_hist[b * NCELL + base + i]; s += v[i]; }
    ss[tid] = s;
    __syncthreads();
    for (int off = 1; off < 1024; off <<= 1) {
        int t = (tid >= off) ? ss[tid - off] : 0;
        __syncthreads();
        ss[tid] += t;
        __syncthreads();
    }
    int ex = ss[tid] - s;
    #pragma unroll
    for (int i = 0; i < 4; i++) { g_cstart[b * NCELL + base + i] = ex; ex += v[i]; }
}

// ---------------- stage D: scatter into Morton order ------------------------
__global__ void scatter_kernel(const float* __restrict__ coords, int sn, int sc,
                               long bstride)
{
    const int b = blockIdx.y;
    const int n = blockIdx.x * 256 + threadIdx.x;
    const float* cb = coords + (long)b * bstride;
    float x = cb[(long)n * sn], y = cb[(long)n * sn + sc], z = cb[(long)n * sn + 2 * sc];
    int cell = g_cellid[b * NPT + n];
    int pos = g_cstart[b * NCELL + cell] + atomicAdd(&g_cursor[b * NCELL + cell], 1);
    float xx = __fadd_rn(__fadd_rn(__fmul_rn(x, x), __fmul_rn(y, y)), __fmul_rn(z, z));
    g_pts4[b * NPT + pos] = make_float4(x, y, z, xx);
    g_pid[b * NPT + pos] = n;
}

// ---------------- stage E: per-tile AABB + max xx ---------------------------
__global__ void tilestats_kernel()
{
    __shared__ float r[7][TPT];
    const int b = blockIdx.y, t = blockIdx.x, tid = threadIdx.x;
    float4 p = g_pts4[b * NPT + t * TPT + tid];
    r[0][tid] = p.x; r[1][tid] = p.y; r[2][tid] = p.z;
    r[3][tid] = p.x; r[4][tid] = p.y; r[5][tid] = p.z;
    r[6][tid] = p.w;
    __syncthreads();
    for (int off = TPT / 2; off; off >>= 1) {
        if (tid < off) {
            r[0][tid] = fminf(r[0][tid], r[0][tid + off]);
            r[1][tid] = fminf(r[1][tid], r[1][tid + off]);
            r[2][tid] = fminf(r[2][tid], r[2][tid + off]);
            r[3][tid] = fmaxf(r[3][tid], r[3][tid + off]);
            r[4][tid] = fmaxf(r[4][tid], r[4][tid + off]);
            r[5][tid] = fmaxf(r[5][tid], r[5][tid + off]);
            r[6][tid] = fmaxf(r[6][tid], r[6][tid + off]);
        }
        __syncthreads();
    }
    if (tid < 3) {
        g_tlo[(b * NTILE + t) * 3 + tid] = r[tid][0];
        g_thi[(b * NTILE + t) * 3 + tid] = r[3 + tid][0];
    }
    if (tid == 3) g_tmx[b * NTILE + t] = r[6][0];
}

// ---------------- stage F: pruned exact KNN query ---------------------------
// Scores/keys bitwise identical to the brute-force version; tiles skipped only
// when provably unable to contain a top-32 member. FULL coverage: the spiral
// runs 2*NTILE steps (off <= NTILE) so every tile is visited or culled for
// every starting tile t0. Output sorted by key desc (== top_k order).
#define QBLK 64

__global__ void knn_query_kernel(int* __restrict__ out_idx)
{
    __shared__ unsigned long long hk[KNN * QBLK];
    const int tid = threadIdx.x;
    const int b = blockIdx.y;
    const int p = blockIdx.x * QBLK + tid;

    const float4 q = g_pts4[b * NPT + p];
    const int qid = g_pid[b * NPT + p];
    const float nxxq = -q.w;

    #pragma unroll
    for (int j = 0; j < KNN; j++) hk[j * QBLK + tid] = 0ull;
    unsigned long long rootk = 0ull;
    float root_s = -3.4e38f;

    const int t0 = p / TPT;
    for (int sstep = 0; sstep < 2 * NTILE; sstep++) {
        int off = (sstep + 1) >> 1;
        int t = (sstep & 1) ? t0 + off : t0 - off;
        if ((unsigned)t >= NTILE) continue;

        // conservative AABB cull
        const float* tl = &g_tlo[(b * NTILE + t) * 3];
        const float* th = &g_thi[(b * NTILE + t) * 3];
        float d2 = 0.f;
        {
            float d = fmaxf(fmaxf(tl[0] - q.x, q.x - th[0]), 0.f); d2 = fmaf(d, d, d2);
            d = fmaxf(fmaxf(tl[1] - q.y, q.y - th[1]), 0.f);       d2 = fmaf(d, d, d2);
            d = fmaxf(fmaxf(tl[2] - q.z, q.z - th[2]), 0.f);       d2 = fmaf(d, d, d2);
        }
        float margin = fmaf(2e-6f, q.w + g_tmx[b * NTILE + t], 1e-6f);
        if (d2 * 0.999999f > -root_s + margin) continue;

        const int cbase = b * NPT + t * TPT;
        for (int j = 0; j < TPT; j++) {
            float4 c = __ldg(&g_pts4[cbase + j]);
            float dot   = __fmaf_rn(q.z, c.z, __fmaf_rn(q.y, c.y, __fmul_rn(q.x, c.x)));
            float inner = __fmul_rn(-2.f, dot);
            float sc_   = __fsub_rn(__fsub_rn(nxxq, inner), c.w);
            if (sc_ >= root_s) {
                int cid = __ldg(&g_pid[cbase + j]);
                unsigned long long key =
                    ((unsigned long long)f32key(sc_) << 32) | (unsigned)(~cid);
                if (key > rootk) {
                    int i2 = 0;
                    #pragma unroll
                    for (int lvl = 0; lvl < 5; lvl++) {
                        int l = 2 * i2 + 1;
                        if (l >= KNN) break;
                        int m = l;
                        unsigned long long dm = hk[l * QBLK + tid];
                        int r = l + 1;
                        if (r < KNN) {
                            unsigned long long dr = hk[r * QBLK + tid];
                            if (dr < dm) { m = r; dm = dr; }
                        }
                        if (dm >= key) break;
                        hk[i2 * QBLK + tid] = dm;
                        i2 = m;
                    }
                    hk[i2 * QBLK + tid] = key;
                    rootk = hk[tid];
                    root_s = (rootk == 0ull) ? -3.4e38f
                                             : unkey((unsigned)(rootk >> 32));
                }
            }
        }
    }

    // in-place heapsort (min-heap) -> hk[0..31] descending by key
    for (int m = KNN - 1; m > 0; m--) {
        unsigned long long vm = hk[m * QBLK + tid];
        hk[m * QBLK + tid] = hk[tid];
        int i2 = 0;
        while (true) {
            int l = 2 * i2 + 1;
            if (l >= m) break;
            int mm = l;
            unsigned long long dm = hk[l * QBLK + tid];
            int r = l + 1;
            if (r < m) {
                unsigned long long dr = hk[r * QBLK + tid];
                if (dr < dm) { mm = r; dm = dr; }
            }
            if (dm >= vm) break;
            hk[i2 * QBLK + tid] = dm;
            i2 = mm;
        }
        hk[i2 * QBLK + tid] = vm;
    }

    int* op = out_idx + (long)(b * NPT + qid) * KNN;
    #pragma unroll
    for (int j = 0; j < KNN; j++)
        op[j] = (int)(~(unsigned)hk[j * QBLK + tid]);
}

// --------- geometry (cov eig features, double precision) + saliency + x ----
#define GEO_BLK 64

__global__ void geom_kernel(const float* __restrict__ points,
                            const int*   __restrict__ idx,
                            const float* __restrict__ sal_w1,
                            const float* __restrict__ sal_g, const float* __restrict__ sal_b,
                            const float* __restrict__ sal_m, const float* __restrict__ sal_v,
                            const float* __restrict__ sal_w2, const float* __restrict__ sal_b2,
                            float* __restrict__ xout)
{
    __shared__ float sx[KNN * GEO_BLK], sy[KNN * GEO_BLK], sz[KNN * GEO_BLK];
    const int tid = threadIdx.x;
    const int b   = blockIdx.y;
    const int q   = blockIdx.x * GEO_BLK + tid;
    const float* pb = points + (long)b * 3 * NPT;
    const int* ip = idx + (long)(b * NPT + q) * KNN;

    double mx = 0, my = 0, mz = 0;
    #pragma unroll
    for (int k = 0; k < KNN; k++) {
        int j = ip[k];
        float nx = pb[j], ny = pb[NPT + j], nz = pb[2 * NPT + j];
        sx[k * GEO_BLK + tid] = nx; sy[k * GEO_BLK + tid] = ny; sz[k * GEO_BLK + tid] = nz;
        mx += nx; my += ny; mz += nz;
    }
    mx *= (1.0 / KNN); my *= (1.0 / KNN); mz *= (1.0 / KNN);

    double cxx = 0, cxy = 0, cxz = 0, cyy = 0, cyz = 0, czz = 0;
    #pragma unroll
    for (int k = 0; k < KNN; k++) {
        double dx = (double)sx[k * GEO_BLK + tid] - mx;
        double dy = (double)sy[k * GEO_BLK + tid] - my;
        double dz = (double)sz[k * GEO_BLK + tid] - mz;
        cxx += dx * dx; cxy += dx * dy; cxz += dx * dz;
        cyy += dy * dy; cyz += dy * dz; czz += dz * dz;
    }
    const double invk = 1.0 / KNN;
    cxx *= invk; cxy *= invk; cxz *= invk; cyy *= invk; cyz *= invk; czz *= invk;

    double q3 = (cxx + cyy + czz) / 3.0;
    double p1 = cxy * cxy + cxz * cxz + cyz * cyz;
    double p2 = (cxx - q3) * (cxx - q3) + (cyy - q3) * (cyy - q3) + (czz - q3) * (czz - q3) + 2.0 * p1;
    double p = sqrt(p2 / 6.0);
    double e1, e2, e3;
    if (p < 1e-150) { e1 = e2 = e3 = q3; }
    else {
        double inv = 1.0 / p;
        double b00 = (cxx - q3) * inv, b11 = (cyy - q3) * inv, b22 = (czz - q3) * inv;
        double b01 = cxy * inv, b02 = cxz * inv, b12 = cyz * inv;
        double detB = b00 * (b11 * b22 - b12 * b12) - b01 * (b01 * b22 - b12 * b02)
                    + b02 * (b01 * b12 - b11 * b02);
        double r = 0.5 * detB;
        r = fmin(1.0, fmax(-1.0, r));
        double phi = acos(r) / 3.0;
        e1 = q3 + 2.0 * p * cos(phi);
        e3 = q3 + 2.0 * p * cos(phi + 2.0943951023931953);
        e2 = 3.0 * q3 - e1 - e3;
    }
    double l0 = e3, l1 = e2, l2 = e1;
    const double eps = 1e-8;
    float geomf[5];
    geomf[0] = (float)((l2 - l1) / (l2 + eps));
    geomf[1] = (float)((l1 - l0) / (l2 + eps));
    geomf[2] = (float)(l0 / (l2 + eps));
    geomf[3] = (float)(l0 / (l0 + l1 + l2 + eps));
    geomf[4] = (float)((l2 - l0) / (l2 + eps));

    float dot = 0.f;
    #pragma unroll
    for (int o = 0; o < 16; o++) {
        float h = 0.f;
        #pragma unroll
        for (int f = 0; f < 5; f++) h = fmaf(sal_w1[o * 5 + f], geomf[f], h);
        float s = sal_g[o] * rsqrtf(sal_v[o] + 1e-5f);
        float t = sal_b[o] - sal_m[o] * s;
        h = leakyf(fmaf(h, s, t));
        dot = fmaf(h, sal_w2[o], dot);
    }
    float sal = 1.f / (1.f + expf(-(dot + sal_b2[0])));

    float* xr = xout + (long)(b * NPT + q) * 9;
    xr[0] = pb[q]; xr[1] = pb[NPT + q]; xr[2] = pb[2 * NPT + q];
    xr[3] = geomf[0]; xr[4] = geomf[1]; xr[5] = geomf[2]; xr[6] = geomf[3]; xr[7] = geomf[4];
    xr[8] = sal;
}

// ------- per-node edge_conv precompute: ys = s*(Wd x), zc = s*((Wc-Wd)x)+t --
template<int CIN>
__global__ void convpre_kernel(const float* __restrict__ xin,
                               const float* __restrict__ w,
                               const float* __restrict__ bng, const float* __restrict__ bnb,
                               const float* __restrict__ bnm, const float* __restrict__ bnv,
                               float* __restrict__ ys, float* __restrict__ zc)
{
    long T = (long)blockIdx.x * blockDim.x + threadIdx.x;
    int  o = (int)(T & 63);
    long p = T >> 6;
    if (p >= (long)BATCH * NPT) return;
    const float* xr = xin + p * CIN;
    const float* wd = w + (long)o * 2 * CIN;
    const float* wc = wd + CIN;
    float ad = 0.f, ac = 0.f;
    #pragma unroll
    for (int c = 0; c < CIN; c++) {
        float xv = xr[c];
        float a = wd[c];
        ad = fmaf(a, xv, ad);
        ac = fmaf(wc[c] - a, xv, ac);
    }
    float s = bng[o] * rsqrtf(bnv[o] + 1e-5f);
    float t = bnb[o] - bnm[o] * s;
    ys[p * 64 + o] = s * ad;
    zc[p * 64 + o] = fmaf(s, ac, t);
}

// ------- edge_conv reduce: x_out[i] = leaky(max_k (ys[idx[i,k]] + zc[i])) ---
__global__ void edge_reduce_kernel(const float* __restrict__ ys, const float* __restrict__ zc,
                                   const int* __restrict__ idx, float* __restrict__ xout)
{
    long warp = ((long)blockIdx.x * blockDim.x + threadIdx.x) >> 5;
    int  lane = threadIdx.x & 31;
    if (warp >= (long)BATCH * NPT) return;
    const long bbase = (warp >> 13) << 13;
    int myj = idx[warp * KNN + lane];
    const float2* ysp = (const float2*)ys;
    float2 z = ((const float2*)zc)[warp * 32 + lane];
    float2 best = make_float2(-3.4e38f, -3.4e38f);
    #pragma unroll
    for (int k = 0; k < KNN; k++) {
        long j = bbase + __shfl_sync(0xffffffffu, myj, k);
        float2 v = ysp[j * 32 + lane];
        best.x = fmaxf(best.x, v.x + z.x);
        best.y = fmaxf(best.y, v.y + z.y);
    }
    best.x = leakyf(best.x);
    best.y = leakyf(best.y);
    ((float2*)xout)[warp * 32 + lane] = best;
}

// --------- classifier: h = leaky(bn(g@W1^T)); logits = h@W2^T + b2 ---------
#define CLS_GRID 256
#define CLS_PPB  ((BATCH*NPT)/CLS_GRID)

__global__ void cls_kernel(const float* __restrict__ x1, const float* __restrict__ x2,
                           const float* __restrict__ w1,
                           const float* __restrict__ bg, const float* __restrict__ bb,
                           const float* __restrict__ bm, const float* __restrict__ bv,
                           const float* __restrict__ w2, const float* __restrict__ b2,
                           float* __restrict__ out)
{
    extern __shared__ float sm[];
    float* WsT  = sm;
    float* Ts   = WsT + 128 * 256;
    float* W2s  = Ts + 256;
    float* gbuf = W2s + 512;
    float* red  = gbuf + 128;

    const int tid = threadIdx.x;
    {
        float s = bg[tid] * rsqrtf(bv[tid] + 1e-5f);
        Ts[tid] = bb[tid] - bm[tid] * s;
        for (int c = 0; c < 128; c++) WsT[c * 256 + tid] = w1[tid * 128 + c] * s;
        W2s[tid] = w2[tid]; W2s[256 + tid] = w2[256 + tid];
    }
    __syncthreads();

    for (int it = 0; it < CLS_PPB; it++) {
        long P = (long)blockIdx.x * CLS_PPB + it;
        if (tid < 64)       gbuf[tid] = x1[P * 64 + tid];
        else if (tid < 128) gbuf[tid] = x2[P * 64 + tid - 64];
        __syncthreads();

        float acc = Ts[tid];
        #pragma unroll 8
        for (int c = 0; c < 128; c++) acc = fmaf(WsT[c * 256 + tid], gbuf[c], acc);
        float h = leakyf(acc);
        float p0 = h * W2s[tid], p1 = h * W2s[256 + tid];
        #pragma unroll
        for (int off = 16; off; off >>= 1) {
            p0 += __shfl_down_sync(0xffffffffu, p0, off);
            p1 += __shfl_down_sync(0xffffffffu, p1, off);
        }
        int w = tid >> 5;
        if ((tid & 31) == 0) { red[w] = p0; red[8 + w] = p1; }
        __syncthreads();
        if (tid == 0) {
            float l0 = b2[0], l1 = b2[1];
            #pragma unroll
            for (int i = 0; i < 8; i++) { l0 += red[i]; l1 += red[8 + i]; }
            long bbatch = P / NPT, nn = P % NPT;
            out[bbatch * 2 * NPT + nn]       = l0;
            out[bbatch * 2 * NPT + NPT + nn] = l1;
        }
        __syncthreads();
    }
}

// ---------------------------------------------------------------------------
static void run_knn(const float* coords, int sn, int sc, long bstride, int* out_idx)
{
    bounds_kernel<<<BATCH, 256>>>(coords, sn, sc, bstride);
    cellcount_kernel<<<dim3(NPT / 256, BATCH), 256>>>(coords, sn, sc, bstride);
    scan_kernel<<<BATCH, 1024>>>();
    scatter_kernel<<<dim3(NPT / 256, BATCH), 256>>>(coords, sn, sc, bstride);
    tilestats_kernel<<<dim3(NTILE, BATCH), TPT>>>();
    knn_query_kernel<<<dim3(NPT / QBLK, BATCH), QBLK>>>(out_idx);
}

extern "C" void kernel_launch(void* const* d_in, const int* in_sizes, int n_in,
                              void* d_out, int out_size)
{
    const float* points  = (const float*)d_in[0];
    const float* sal_w1  = (const float*)d_in[1];
    const float* sal_g   = (const float*)d_in[2];
    const float* sal_b   = (const float*)d_in[3];
    const float* sal_m   = (const float*)d_in[4];
    const float* sal_v   = (const float*)d_in[5];
    const float* sal_w2  = (const float*)d_in[6];
    const float* sal_b2  = (const float*)d_in[7];
    const float* c1_w    = (const float*)d_in[8];
    const float* c1_g    = (const float*)d_in[9];
    const float* c1_b    = (const float*)d_in[10];
    const float* c1_m    = (const float*)d_in[11];
    const float* c1_v    = (const float*)d_in[12];
    const float* c2_w    = (const float*)d_in[13];
    const float* c2_g    = (const float*)d_in[14];
    const float* c2_b    = (const float*)d_in[15];
    const float* c2_m    = (const float*)d_in[16];
    const float* c2_v    = (const float*)d_in[17];
    const float* cls_w1  = (const float*)d_in[18];
    const float* cls_g   = (const float*)d_in[19];
    const float* cls_b   = (const float*)d_in[20];
    const float* cls_m   = (const float*)d_in[21];
    const float* cls_v   = (const float*)d_in[22];
    const float* cls_w2  = (const float*)d_in[23];
    const float* cls_b2  = (const float*)d_in[24];
    float* out = (float*)d_out;

    int*   idx1; cudaGetSymbolAddress((void**)&idx1, g_idx1);
    int*   idx2; cudaGetSymbolAddress((void**)&idx2, g_idx2);
    float* xf  ; cudaGetSymbolAddress((void**)&xf , g_x  );
    float* ys1 ; cudaGetSymbolAddress((void**)&ys1, g_ys1);
    float* zc1 ; cudaGetSymbolAddress((void**)&zc1, g_zc1);
    float* x1  ; cudaGetSymbolAddress((void**)&x1 , g_x1 );
    float* ys2 ; cudaGetSymbolAddress((void**)&ys2, g_ys2);
    float* zc2 ; cudaGetSymbolAddress((void**)&zc2, g_zc2);
    float* x2  ; cudaGetSymbolAddress((void**)&x2 , g_x2 );

    // 1) knn on raw points (layout (B,3,N): sn=1, sc=N)
    run_knn(points, 1, NPT, (long)3 * NPT, idx1);

    // 2) geometry + saliency -> x (B,N,9)
    geom_kernel<<<dim3(NPT / GEO_BLK, BATCH), GEO_BLK>>>(
        points, idx1, sal_w1, sal_g, sal_b, sal_m, sal_v, sal_w2, sal_b2, xf);

    // 3) edge_conv1 -> x1
    {
        long total = (long)BATCH * NPT * 64;
        convpre_kernel<9><<<(unsigned)(total / 128), 128>>>(xf, c1_w, c1_g, c1_b, c1_m, c1_v, ys1, zc1);
        edge_reduce_kernel<<<(BATCH * NPT) / 4, 128>>>(ys1, zc1, idx1, x1);
    }

    // 4) knn on x1[...,0:3] (layout (B,N,64): sn=64, sc=1)
    run_knn(x1, 64, 1, (long)NPT * 64, idx2);

    // 5) edge_conv2 -> x2
    {
        long total = (long)BATCH * NPT * 64;
        convpre_kernel<64><<<(unsigned)(total / 128), 128>>>(x1, c2_w, c2_g, c2_b, c2_m, c2_v, ys2, zc2);
        edge_reduce_kernel<<<(BATCH * NPT) / 4, 128>>>(ys2, zc2, idx2, x2);
    }

    // 6) classifier
    {
        size_t smem = (128 * 256 + 256 + 512 + 128 + 16) * sizeof(float);
        cudaFuncSetAttribute(cls_kernel, cudaFuncAttributeMaxDynamicSharedMemorySize, (int)smem);
        cls_kernel<<<CLS_GRID, 256, smem>>>(x1, x2, cls_w1,
                                            cls_g, cls_b, cls_m, cls_v,
                                            cls_w2, cls_b2, out);
    }
}

// round 12
// speedup vs baseline: 1.4304x; 1.1689x over previous
#include <cuda_runtime.h>
#include <cuda_bf16.h>
#include <math.h>
#include <stdint.h>

#define BATCH 4
#define NPT   8192
#define KNN   32

#define GRES  16
#define NCELL (GRES*GRES*GRES)   // 4096
#define TPT   64                 // points per tile
#define NTILE (NPT/TPT)          // 128
#define SUBP  16                 // points per subtile
#define NSUB  4                  // subtiles per tile

// ---------------- scratch (__device__ globals; no allocations allowed) ------
__device__ int    g_idx1[BATCH*NPT*KNN];
__device__ int    g_idx2[BATCH*NPT*KNN];
__device__ float  g_x  [BATCH*NPT*9];
__device__ float  g_ys1[BATCH*NPT*64];
__device__ float  g_zc1[BATCH*NPT*64];
__device__ float  g_x1 [BATCH*NPT*64];
__device__ float  g_ys2[BATCH*NPT*64];
__device__ float  g_zc2[BATCH*NPT*64];
__device__ float  g_x2 [BATCH*NPT*64];
// knn spatial-structure scratch (reused by knn1 then knn2)
__device__ float4 g_pts4[BATCH*NPT];
__device__ int    g_pid [BATCH*NPT];
__device__ int    g_cellid[BATCH*NPT];
__device__ int    g_hist  [BATCH*NCELL];
__device__ int    g_cstart[BATCH*NCELL];
__device__ int    g_cursor[BATCH*NCELL];
__device__ float4 g_tlo4[BATCH*NTILE];          // tile lo.xyz, w = tile max xx
__device__ float4 g_thi4[BATCH*NTILE];          // tile hi.xyz
__device__ float4 g_slo4[BATCH*NTILE*NSUB];     // subtile lo.xyz
__device__ float4 g_shi4[BATCH*NTILE*NSUB];     // subtile hi.xyz, w = subtile max xx
__device__ float  g_blo[BATCH*3];
__device__ float  g_bhi[BATCH*3];

__device__ __forceinline__ float leakyf(float x) { return x >= 0.f ? x : 0.2f * x; }

// sortable key helpers: lexicographic (score, -index), identical tie semantics
// to jax.lax.top_k (stable, lowest index wins).
__device__ __forceinline__ unsigned f32key(float s) {
    unsigned b = __float_as_uint(s);
    return (b & 0x80000000u) ? ~b : (b | 0x80000000u);
}
__device__ __forceinline__ float unkey(unsigned k) {
    unsigned b = (k & 0x80000000u) ? (k ^ 0x80000000u) : ~k;
    return __uint_as_float(b);
}

__device__ __forceinline__ int spread4(int v) {
    return (v & 1) | ((v & 2) << 2) | ((v & 4) << 4) | ((v & 8) << 6);
}
__device__ __forceinline__ int morton3(int x, int y, int z) {
    return spread4(x) | (spread4(y) << 1) | (spread4(z) << 2);
}

// ---------------- stage A: per-batch coordinate bounds (+ zero counters) ----
__global__ void bounds_kernel(const float* __restrict__ coords, int sn, int sc,
                              long bstride)
{
    __shared__ float slo[3][256], shi[3][256];
    const int b = blockIdx.x, tid = threadIdx.x;
    const float* cb = coords + (long)b * bstride;
    float l0 = 3.4e38f, l1 = 3.4e38f, l2 = 3.4e38f;
    float h0 = -3.4e38f, h1 = -3.4e38f, h2 = -3.4e38f;
    for (int n = tid; n < NPT; n += 256) {
        float x = cb[(long)n * sn], y = cb[(long)n * sn + sc], z = cb[(long)n * sn + 2 * sc];
        l0 = fminf(l0, x); h0 = fmaxf(h0, x);
        l1 = fminf(l1, y); h1 = fmaxf(h1, y);
        l2 = fminf(l2, z); h2 = fmaxf(h2, z);
    }
    slo[0][tid] = l0; slo[1][tid] = l1; slo[2][tid] = l2;
    shi[0][tid] = h0; shi[1][tid] = h1; shi[2][tid] = h2;
    __syncthreads();
    for (int off = 128; off; off >>= 1) {
        if (tid < off) {
            #pragma unroll
            for (int a = 0; a < 3; a++) {
                slo[a][tid] = fminf(slo[a][tid], slo[a][tid + off]);
                shi[a][tid] = fmaxf(shi[a][tid], shi[a][tid + off]);
            }
        }
        __syncthreads();
    }
    if (tid < 3) { g_blo[b * 3 + tid] = slo[tid][0]; g_bhi[b * 3 + tid] = shi[tid][0]; }
    for (int i = tid; i < NCELL; i += 256) {
        g_hist[b * NCELL + i] = 0;
        g_cursor[b * NCELL + i] = 0;
    }
}

// ---------------- stage B: cell ids + histogram -----------------------------
__global__ void cellcount_kernel(const float* __restrict__ coords, int sn, int sc,
                                 long bstride)
{
    const int b = blockIdx.y;
    const int n = blockIdx.x * 256 + threadIdx.x;
    const float* cb = coords + (long)b * bstride;
    float x = cb[(long)n * sn], y = cb[(long)n * sn + sc], z = cb[(long)n * sn + 2 * sc];
    float lo0 = g_blo[b * 3], lo1 = g_blo[b * 3 + 1], lo2 = g_blo[b * 3 + 2];
    float s0 = (float)GRES / fmaxf(g_bhi[b * 3]     - lo0, 1e-30f);
    float s1 = (float)GRES / fmaxf(g_bhi[b * 3 + 1] - lo1, 1e-30f);
    float s2 = (float)GRES / fmaxf(g_bhi[b * 3 + 2] - lo2, 1e-30f);
    int cx = min(GRES - 1, max(0, (int)((x - lo0) * s0)));
    int cy = min(GRES - 1, max(0, (int)((y - lo1) * s1)));
    int cz = min(GRES - 1, max(0, (int)((z - lo2) * s2)));
    int cell = morton3(cx, cy, cz);
    g_cellid[b * NPT + n] = cell;
    atomicAdd(&g_hist[b * NCELL + cell], 1);
}

// ---------------- stage C: per-batch exclusive scan over 4096 cells ---------
__global__ void scan_kernel()
{
    __shared__ int ss[1024];
    const int b = blockIdx.x, tid = threadIdx.x;
    int v[4]; int base = tid * 4; int s = 0;
    #pragma unroll
    for (int i = 0; i < 4; i++) { v[i] = g_hist[b * NCELL + base + i]; s += v[i]; }
    ss[tid] = s;
    __syncthreads();
    for (int off = 1; off < 1024; off <<= 1) {
        int t = (tid >= off) ? ss[tid - off] : 0;
        __syncthreads();
        ss[tid] += t;
        __syncthreads();
    }
    int ex = ss[tid] - s;
    #pragma unroll
    for (int i = 0; i < 4; i++) { g_cstart[b * NCELL + base + i] = ex; ex += v[i]; }
}

// ---------------- stage D: scatter into Morton order ------------------------
__global__ void scatter_kernel(const float* __restrict__ coords, int sn, int sc,
                               long bstride)
{
    const int b = blockIdx.y;
    const int n = blockIdx.x * 256 + threadIdx.x;
    const float* cb = coords + (long)b * bstride;
    float x = cb[(long)n * sn], y = cb[(long)n * sn + sc], z = cb[(long)n * sn + 2 * sc];
    int cell = g_cellid[b * NPT + n];
    int pos = g_cstart[b * NCELL + cell] + atomicAdd(&g_cursor[b * NCELL + cell], 1);
    float xx = __fadd_rn(__fadd_rn(__fmul_rn(x, x), __fmul_rn(y, y)), __fmul_rn(z, z));
    g_pts4[b * NPT + pos] = make_float4(x, y, z, xx);
    g_pid[b * NPT + pos] = n;
}

// ---------------- stage E: per-tile AABB + per-subtile AABBs ----------------
__global__ void tilestats_kernel()
{
    __shared__ float r[7][TPT];
    const int b = blockIdx.y, t = blockIdx.x, tid = threadIdx.x;
    float4 p = g_pts4[b * NPT + t * TPT + tid];

    // subtile (16-point) AABB via shfl within 16-lane groups
    {
        float lx = p.x, hx = p.x, ly = p.y, hy = p.y, lz = p.z, hz = p.z, mw = p.w;
        #pragma unroll
        for (int off = 8; off; off >>= 1) {
            lx = fminf(lx, __shfl_xor_sync(0xffffffffu, lx, off, 16));
            hx = fmaxf(hx, __shfl_xor_sync(0xffffffffu, hx, off, 16));
            ly = fminf(ly, __shfl_xor_sync(0xffffffffu, ly, off, 16));
            hy = fmaxf(hy, __shfl_xor_sync(0xffffffffu, hy, off, 16));
            lz = fminf(lz, __shfl_xor_sync(0xffffffffu, lz, off, 16));
            hz = fmaxf(hz, __shfl_xor_sync(0xffffffffu, hz, off, 16));
            mw = fmaxf(mw, __shfl_xor_sync(0xffffffffu, mw, off, 16));
        }
        if ((tid & 15) == 0) {
            int sub = tid >> 4;
            g_slo4[(b * NTILE + t) * NSUB + sub] = make_float4(lx, ly, lz, 0.f);
            g_shi4[(b * NTILE + t) * NSUB + sub] = make_float4(hx, hy, hz, mw);
        }
    }

    r[0][tid] = p.x; r[1][tid] = p.y; r[2][tid] = p.z;
    r[3][tid] = p.x; r[4][tid] = p.y; r[5][tid] = p.z;
    r[6][tid] = p.w;
    __syncthreads();
    for (int off = TPT / 2; off; off >>= 1) {
        if (tid < off) {
            r[0][tid] = fminf(r[0][tid], r[0][tid + off]);
            r[1][tid] = fminf(r[1][tid], r[1][tid + off]);
            r[2][tid] = fminf(r[2][tid], r[2][tid + off]);
            r[3][tid] = fmaxf(r[3][tid], r[3][tid + off]);
            r[4][tid] = fmaxf(r[4][tid], r[4][tid + off]);
            r[5][tid] = fmaxf(r[5][tid], r[5][tid + off]);
            r[6][tid] = fmaxf(r[6][tid], r[6][tid + off]);
        }
        __syncthreads();
    }
    if (tid == 0) {
        g_tlo4[b * NTILE + t] = make_float4(r[0][0], r[1][0], r[2][0], r[6][0]);
        g_thi4[b * NTILE + t] = make_float4(r[3][0], r[4][0], r[5][0], 0.f);
    }
}

// ---------------- stage F: pruned exact KNN query ---------------------------
// Scores/keys bitwise identical to the brute-force version; tiles/subtiles
// skipped only when provably unable to contain a top-32 member (conservative
// margin >= 4x the fp32 score-vs-true-distance bound). Full spiral coverage.
// Output sorted by key desc (== top_k order).
#define QBLK 64

__global__ void knn_query_kernel(int* __restrict__ out_idx)
{
    __shared__ unsigned long long hk[KNN * QBLK];      // 16 KB
    __shared__ float4 s_tA[NTILE];                     // tile lo.xyz, w=tmx
    __shared__ float4 s_tB[NTILE];                     // tile hi.xyz
    __shared__ float4 s_slo[NTILE * NSUB];             // 8 KB
    __shared__ float4 s_shi[NTILE * NSUB];             // 8 KB

    const int tid = threadIdx.x;
    const int b = blockIdx.y;
    const int p = blockIdx.x * QBLK + tid;

    // cooperative preload of culling structures
    for (int i = tid; i < NTILE; i += QBLK) {
        s_tA[i] = g_tlo4[b * NTILE + i];
        s_tB[i] = g_thi4[b * NTILE + i];
    }
    for (int i = tid; i < NTILE * NSUB; i += QBLK) {
        s_slo[i] = g_slo4[b * NTILE * NSUB + i];
        s_shi[i] = g_shi4[b * NTILE * NSUB + i];
    }

    const float4 q = g_pts4[b * NPT + p];
    const int qid = g_pid[b * NPT + p];
    const float nxxq = -q.w;

    #pragma unroll
    for (int j = 0; j < KNN; j++) hk[j * QBLK + tid] = 0ull;
    unsigned long long rootk = 0ull;
    float root_s = -3.4e38f;
    __syncthreads();

    const int t0 = p / TPT;
    for (int sstep = 0; sstep < 2 * NTILE; sstep++) {
        int off = (sstep + 1) >> 1;
        int t = (sstep & 1) ? t0 + off : t0 - off;
        if ((unsigned)t >= NTILE) continue;

        // coarse tile cull
        float4 tA = s_tA[t], tB = s_tB[t];
        float d2 = 0.f;
        {
            float d = fmaxf(fmaxf(tA.x - q.x, q.x - tB.x), 0.f); d2 = fmaf(d, d, d2);
            d = fmaxf(fmaxf(tA.y - q.y, q.y - tB.y), 0.f);       d2 = fmaf(d, d, d2);
            d = fmaxf(fmaxf(tA.z - q.z, q.z - tB.z), 0.f);       d2 = fmaf(d, d, d2);
        }
        float margin = fmaf(2e-6f, q.w + tA.w, 1e-6f);
        if (d2 * 0.999999f > -root_s + margin) continue;

        // fine subtile cull + scan
        #pragma unroll
        for (int sub = 0; sub < NSUB; sub++) {
            float4 sl = s_slo[t * NSUB + sub], sh = s_shi[t * NSUB + sub];
            float d2s = 0.f;
            {
                float d = fmaxf(fmaxf(sl.x - q.x, q.x - sh.x), 0.f); d2s = fmaf(d, d, d2s);
                d = fmaxf(fmaxf(sl.y - q.y, q.y - sh.y), 0.f);       d2s = fmaf(d, d, d2s);
                d = fmaxf(fmaxf(sl.z - q.z, q.z - sh.z), 0.f);       d2s = fmaf(d, d, d2s);
            }
            float margin_s = fmaf(2e-6f, q.w + sh.w, 1e-6f);
            if (d2s * 0.999999f > -root_s + margin_s) continue;

            const int cbase = b * NPT + t * TPT + sub * SUBP;
            #pragma unroll 4
            for (int j = 0; j < SUBP; j++) {
                float4 c = __ldg(&g_pts4[cbase + j]);
                float dot   = __fmaf_rn(q.z, c.z, __fmaf_rn(q.y, c.y, __fmul_rn(q.x, c.x)));
                float inner = __fmul_rn(-2.f, dot);
                float sc_   = __fsub_rn(__fsub_rn(nxxq, inner), c.w);
                if (sc_ >= root_s) {
                    int cid = __ldg(&g_pid[cbase + j]);
                    unsigned long long key =
                        ((unsigned long long)f32key(sc_) << 32) | (unsigned)(~cid);
                    if (key > rootk) {
                        int i2 = 0;
                        #pragma unroll
                        for (int lvl = 0; lvl < 5; lvl++) {
                            int l = 2 * i2 + 1;
                            if (l >= KNN) break;
                            int m = l;
                            unsigned long long dm = hk[l * QBLK + tid];
                            int r = l + 1;
                            if (r < KNN) {
                                unsigned long long dr = hk[r * QBLK + tid];
                                if (dr < dm) { m = r; dm = dr; }
                            }
                            if (dm >= key) break;
                            hk[i2 * QBLK + tid] = dm;
                            i2 = m;
                        }
                        hk[i2 * QBLK + tid] = key;
                        rootk = hk[tid];
                        root_s = (rootk == 0ull) ? -3.4e38f
                                                 : unkey((unsigned)(rootk >> 32));
                    }
                }
            }
        }
    }

    // in-place heapsort (min-heap) -> hk[0..31] descending by key
    for (int m = KNN - 1; m > 0; m--) {
        unsigned long long vm = hk[m * QBLK + tid];
        hk[m * QBLK + tid] = hk[tid];
        int i2 = 0;
        while (true) {
            int l = 2 * i2 + 1;
            if (l >= m) break;
            int mm = l;
            unsigned long long dm = hk[l * QBLK + tid];
            int r = l + 1;
            if (r < m) {
                unsigned long long dr = hk[r * QBLK + tid];
                if (dr < dm) { mm = r; dm = dr; }
            }
            if (dm >= vm) break;
            hk[i2 * QBLK + tid] = dm;
            i2 = mm;
        }
        hk[i2 * QBLK + tid] = vm;
    }

    int* op = out_idx + (long)(b * NPT + qid) * KNN;
    #pragma unroll
    for (int j = 0; j < KNN; j++)
        op[j] = (int)(~(unsigned)hk[j * QBLK + tid]);
}

// --------- geometry (cov eig features, double precision) + saliency + x ----
#define GEO_BLK 64

__global__ void geom_kernel(const float* __restrict__ points,
                            const int*   __restrict__ idx,
                            const float* __restrict__ sal_w1,
                            const float* __restrict__ sal_g, const float* __restrict__ sal_b,
                            const float* __restrict__ sal_m, const float* __restrict__ sal_v,
                            const float* __restrict__ sal_w2, const float* __restrict__ sal_b2,
                            float* __restrict__ xout)
{
    __shared__ float sx[KNN * GEO_BLK], sy[KNN * GEO_BLK], sz[KNN * GEO_BLK];
    const int tid = threadIdx.x;
    const int b   = blockIdx.y;
    const int q   = blockIdx.x * GEO_BLK + tid;
    const float* pb = points + (long)b * 3 * NPT;
    const int* ip = idx + (long)(b * NPT + q) * KNN;

    double mx = 0, my = 0, mz = 0;
    #pragma unroll
    for (int k = 0; k < KNN; k++) {
        int j = ip[k];
        float nx = pb[j], ny = pb[NPT + j], nz = pb[2 * NPT + j];
        sx[k * GEO_BLK + tid] = nx; sy[k * GEO_BLK + tid] = ny; sz[k * GEO_BLK + tid] = nz;
        mx += nx; my += ny; mz += nz;
    }
    mx *= (1.0 / KNN); my *= (1.0 / KNN); mz *= (1.0 / KNN);

    double cxx = 0, cxy = 0, cxz = 0, cyy = 0, cyz = 0, czz = 0;
    #pragma unroll
    for (int k = 0; k < KNN; k++) {
        double dx = (double)sx[k * GEO_BLK + tid] - mx;
        double dy = (double)sy[k * GEO_BLK + tid] - my;
        double dz = (double)sz[k * GEO_BLK + tid] - mz;
        cxx += dx * dx; cxy += dx * dy; cxz += dx * dz;
        cyy += dy * dy; cyz += dy * dz; czz += dz * dz;
    }
    const double invk = 1.0 / KNN;
    cxx *= invk; cxy *= invk; cxz *= invk; cyy *= invk; cyz *= invk; czz *= invk;

    double q3 = (cxx + cyy + czz) / 3.0;
    double p1 = cxy * cxy + cxz * cxz + cyz * cyz;
    double p2 = (cxx - q3) * (cxx - q3) + (cyy - q3) * (cyy - q3) + (czz - q3) * (czz - q3) + 2.0 * p1;
    double p = sqrt(p2 / 6.0);
    double e1, e2, e3;
    if (p < 1e-150) { e1 = e2 = e3 = q3; }
    else {
        double inv = 1.0 / p;
        double b00 = (cxx - q3) * inv, b11 = (cyy - q3) * inv, b22 = (czz - q3) * inv;
        double b01 = cxy * inv, b02 = cxz * inv, b12 = cyz * inv;
        double detB = b00 * (b11 * b22 - b12 * b12) - b01 * (b01 * b22 - b12 * b02)
                    + b02 * (b01 * b12 - b11 * b02);
        double r = 0.5 * detB;
        r = fmin(1.0, fmax(-1.0, r));
        double phi = acos(r) / 3.0;
        e1 = q3 + 2.0 * p * cos(phi);
        e3 = q3 + 2.0 * p * cos(phi + 2.0943951023931953);
        e2 = 3.0 * q3 - e1 - e3;
    }
    double l0 = e3, l1 = e2, l2 = e1;
    const double eps = 1e-8;
    float geomf[5];
    geomf[0] = (float)((l2 - l1) / (l2 + eps));
    geomf[1] = (float)((l1 - l0) / (l2 + eps));
    geomf[2] = (float)(l0 / (l2 + eps));
    geomf[3] = (float)(l0 / (l0 + l1 + l2 + eps));
    geomf[4] = (float)((l2 - l0) / (l2 + eps));

    float dot = 0.f;
    #pragma unroll
    for (int o = 0; o < 16; o++) {
        float h = 0.f;
        #pragma unroll
        for (int f = 0; f < 5; f++) h = fmaf(sal_w1[o * 5 + f], geomf[f], h);
        float s = sal_g[o] * rsqrtf(sal_v[o] + 1e-5f);
        float t = sal_b[o] - sal_m[o] * s;
        h = leakyf(fmaf(h, s, t));
        dot = fmaf(h, sal_w2[o], dot);
    }
    float sal = 1.f / (1.f + expf(-(dot + sal_b2[0])));

    float* xr = xout + (long)(b * NPT + q) * 9;
    xr[0] = pb[q]; xr[1] = pb[NPT + q]; xr[2] = pb[2 * NPT + q];
    xr[3] = geomf[0]; xr[4] = geomf[1]; xr[5] = geomf[2]; xr[6] = geomf[3]; xr[7] = geomf[4];
    xr[8] = sal;
}

// ------- per-node edge_conv precompute: ys = s*(Wd x), zc = s*((Wc-Wd)x)+t --
template<int CIN>
__global__ void convpre_kernel(const float* __restrict__ xin,
                               const float* __restrict__ w,
                               const float* __restrict__ bng, const float* __restrict__ bnb,
                               const float* __restrict__ bnm, const float* __restrict__ bnv,
                               float* __restrict__ ys, float* __restrict__ zc)
{
    long T = (long)blockIdx.x * blockDim.x + threadIdx.x;
    int  o = (int)(T & 63);
    long p = T >> 6;
    if (p >= (long)BATCH * NPT) return;
    const float* xr = xin + p * CIN;
    const float* wd = w + (long)o * 2 * CIN;
    const float* wc = wd + CIN;
    float ad = 0.f, ac = 0.f;
    #pragma unroll
    for (int c = 0; c < CIN; c++) {
        float xv = xr[c];
        float a = wd[c];
        ad = fmaf(a, xv, ad);
        ac = fmaf(wc[c] - a, xv, ac);
    }
    float s = bng[o] * rsqrtf(bnv[o] + 1e-5f);
    float t = bnb[o] - bnm[o] * s;
    ys[p * 64 + o] = s * ad;
    zc[p * 64 + o] = fmaf(s, ac, t);
}

// ------- edge_conv reduce: x_out[i] = leaky(max_k (ys[idx[i,k]] + zc[i])) ---
__global__ void edge_reduce_kernel(const float* __restrict__ ys, const float* __restrict__ zc,
                                   const int* __restrict__ idx, float* __restrict__ xout)
{
    long warp = ((long)blockIdx.x * blockDim.x + threadIdx.x) >> 5;
    int  lane = threadIdx.x & 31;
    if (warp >= (long)BATCH * NPT) return;
    const long bbase = (warp >> 13) << 13;
    int myj = idx[warp * KNN + lane];
    const float2* ysp = (const float2*)ys;
    float2 z = ((const float2*)zc)[warp * 32 + lane];
    float2 best = make_float2(-3.4e38f, -3.4e38f);
    #pragma unroll
    for (int k = 0; k < KNN; k++) {
        long j = bbase + __shfl_sync(0xffffffffu, myj, k);
        float2 v = ysp[j * 32 + lane];
        best.x = fmaxf(best.x, v.x + z.x);
        best.y = fmaxf(best.y, v.y + z.y);
    }
    best.x = leakyf(best.x);
    best.y = leakyf(best.y);
    ((float2*)xout)[warp * 32 + lane] = best;
}

// --------- classifier: h = leaky(bn(g@W1^T)); logits = h@W2^T + b2 ---------
#define CLS_GRID 256
#define CLS_PPB  ((BATCH*NPT)/CLS_GRID)

__global__ void cls_kernel(const float* __restrict__ x1, const float* __restrict__ x2,
                           const float* __restrict__ w1,
                           const float* __restrict__ bg, const float* __restrict__ bb,
                           const float* __restrict__ bm, const float* __restrict__ bv,
                           const float* __restrict__ w2, const float* __restrict__ b2,
                           float* __restrict__ out)
{
    extern __shared__ float sm[];
    float* WsT  = sm;
    float* Ts   = WsT + 128 * 256;
    float* W2s  = Ts + 256;
    float* gbuf = W2s + 512;
    float* red  = gbuf + 128;

    const int tid = threadIdx.x;
    {
        float s = bg[tid] * rsqrtf(bv[tid] + 1e-5f);
        Ts[tid] = bb[tid] - bm[tid] * s;
        for (int c = 0; c < 128; c++) WsT[c * 256 + tid] = w1[tid * 128 + c] * s;
        W2s[tid] = w2[tid]; W2s[256 + tid] = w2[256 + tid];
    }
    __syncthreads();

    for (int it = 0; it < CLS_PPB; it++) {
        long P = (long)blockIdx.x * CLS_PPB + it;
        if (tid < 64)       gbuf[tid] = x1[P * 64 + tid];
        else if (tid < 128) gbuf[tid] = x2[P * 64 + tid - 64];
        __syncthreads();

        float acc = Ts[tid];
        #pragma unroll 8
        for (int c = 0; c < 128; c++) acc = fmaf(WsT[c * 256 + tid], gbuf[c], acc);
        float h = leakyf(acc);
        float p0 = h * W2s[tid], p1 = h * W2s[256 + tid];
        #pragma unroll
        for (int off = 16; off; off >>= 1) {
            p0 += __shfl_down_sync(0xffffffffu, p0, off);
            p1 += __shfl_down_sync(0xffffffffu, p1, off);
        }
        int w = tid >> 5;
        if ((tid & 31) == 0) { red[w] = p0; red[8 + w] = p1; }
        __syncthreads();
        if (tid == 0) {
            float l0 = b2[0], l1 = b2[1];
            #pragma unroll
            for (int i = 0; i < 8; i++) { l0 += red[i]; l1 += red[8 + i]; }
            long bbatch = P / NPT, nn = P % NPT;
            out[bbatch * 2 * NPT + nn]       = l0;
            out[bbatch * 2 * NPT + NPT + nn] = l1;
        }
        __syncthreads();
    }
}

// ---------------------------------------------------------------------------
static void run_knn(const float* coords, int sn, int sc, long bstride, int* out_idx)
{
    bounds_kernel<<<BATCH, 256>>>(coords, sn, sc, bstride);
    cellcount_kernel<<<dim3(NPT / 256, BATCH), 256>>>(coords, sn, sc, bstride);
    scan_kernel<<<BATCH, 1024>>>();
    scatter_kernel<<<dim3(NPT / 256, BATCH), 256>>>(coords, sn, sc, bstride);
    tilestats_kernel<<<dim3(NTILE, BATCH), TPT>>>();
    knn_query_kernel<<<dim3(NPT / QBLK, BATCH), QBLK>>>(out_idx);
}

extern "C" void kernel_launch(void* const* d_in, const int* in_sizes, int n_in,
                              void* d_out, int out_size)
{
    const float* points  = (const float*)d_in[0];
    const float* sal_w1  = (const float*)d_in[1];
    const float* sal_g   = (const float*)d_in[2];
    const float* sal_b   = (const float*)d_in[3];
    const float* sal_m   = (const float*)d_in[4];
    const float* sal_v   = (const float*)d_in[5];
    const float* sal_w2  = (const float*)d_in[6];
    const float* sal_b2  = (const float*)d_in[7];
    const float* c1_w    = (const float*)d_in[8];
    const float* c1_g    = (const float*)d_in[9];
    const float* c1_b    = (const float*)d_in[10];
    const float* c1_m    = (const float*)d_in[11];
    const float* c1_v    = (const float*)d_in[12];
    const float* c2_w    = (const float*)d_in[13];
    const float* c2_g    = (const float*)d_in[14];
    const float* c2_b    = (const float*)d_in[15];
    const float* c2_m    = (const float*)d_in[16];
    const float* c2_v    = (const float*)d_in[17];
    const float* cls_w1  = (const float*)d_in[18];
    const float* cls_g   = (const float*)d_in[19];
    const float* cls_b   = (const float*)d_in[20];
    const float* cls_m   = (const float*)d_in[21];
    const float* cls_v   = (const float*)d_in[22];
    const float* cls_w2  = (const float*)d_in[23];
    const float* cls_b2  = (const float*)d_in[24];
    float* out = (float*)d_out;

    int*   idx1; cudaGetSymbolAddress((void**)&idx1, g_idx1);
    int*   idx2; cudaGetSymbolAddress((void**)&idx2, g_idx2);
    float* xf  ; cudaGetSymbolAddress((void**)&xf , g_x  );
    float* ys1 ; cudaGetSymbolAddress((void**)&ys1, g_ys1);
    float* zc1 ; cudaGetSymbolAddress((void**)&zc1, g_zc1);
    float* x1  ; cudaGetSymbolAddress((void**)&x1 , g_x1 );
    float* ys2 ; cudaGetSymbolAddress((void**)&ys2, g_ys2);
    float* zc2 ; cudaGetSymbolAddress((void**)&zc2, g_zc2);
    float* x2  ; cudaGetSymbolAddress((void**)&x2 , g_x2 );

    // 1) knn on raw points (layout (B,3,N): sn=1, sc=N)
    run_knn(points, 1, NPT, (long)3 * NPT, idx1);

    // 2) geometry + saliency -> x (B,N,9)
    geom_kernel<<<dim3(NPT / GEO_BLK, BATCH), GEO_BLK>>>(
        points, idx1, sal_w1, sal_g, sal_b, sal_m, sal_v, sal_w2, sal_b2, xf);

    // 3) edge_conv1 -> x1
    {
        long total = (long)BATCH * NPT * 64;
        convpre_kernel<9><<<(unsigned)(total / 128), 128>>>(xf, c1_w, c1_g, c1_b, c1_m, c1_v, ys1, zc1);
        edge_reduce_kernel<<<(BATCH * NPT) / 4, 128>>>(ys1, zc1, idx1, x1);
    }

    // 4) knn on x1[...,0:3] (layout (B,N,64): sn=64, sc=1)
    run_knn(x1, 64, 1, (long)NPT * 64, idx2);

    // 5) edge_conv2 -> x2
    {
        long total = (long)BATCH * NPT * 64;
        convpre_kernel<64><<<(unsigned)(total / 128), 128>>>(x1, c2_w, c2_g, c2_b, c2_m, c2_v, ys2, zc2);
        edge_reduce_kernel<<<(BATCH * NPT) / 4, 128>>>(ys2, zc2, idx2, x2);
    }

    // 6) classifier
    {
        size_t smem = (128 * 256 + 256 + 512 + 128 + 16) * sizeof(float);
        cudaFuncSetAttribute(cls_kernel, cudaFuncAttributeMaxDynamicSharedMemorySize, (int)smem);
        cls_kernel<<<CLS_GRID, 256, smem>>>(x1, x2, cls_w1,
                                            cls_g, cls_b, cls_m, cls_v,
                                            cls_w2, cls_b2, out);
    }
}

// round 13
// speedup vs baseline: 1.5249x; 1.0661x over previous
#include <cuda_runtime.h>
#include <cuda_bf16.h>
#include <math.h>
#include <stdint.h>

#define BATCH 4
#define NPT   8192
#define KNN   32

#define GRES  16
#define NCELL (GRES*GRES*GRES)   // 4096
#define TPT   64                 // points per tile
#define NTILE (NPT/TPT)          // 128

// ---------------- scratch (__device__ globals; no allocations allowed) ------
__device__ int    g_idx1[BATCH*NPT*KNN];
__device__ int    g_idx2[BATCH*NPT*KNN];
__device__ float  g_x  [BATCH*NPT*9];
__device__ float  g_ys1[BATCH*NPT*64];
__device__ float  g_zc1[BATCH*NPT*64];
__device__ float  g_x1 [BATCH*NPT*64];
__device__ float  g_ys2[BATCH*NPT*64];
__device__ float  g_zc2[BATCH*NPT*64];
__device__ float  g_x2 [BATCH*NPT*64];
// knn spatial-structure scratch (reused by knn1 then knn2)
__device__ float4 g_pts4[BATCH*NPT];
__device__ int    g_pid [BATCH*NPT];
__device__ int    g_cellid[BATCH*NPT];
__device__ int    g_hist  [BATCH*NCELL];
__device__ int    g_cstart[BATCH*NCELL];
__device__ int    g_cursor[BATCH*NCELL];
__device__ float4 g_tlo4[BATCH*NTILE];          // tile lo.xyz, w = tile max xx
__device__ float4 g_thi4[BATCH*NTILE];          // tile hi.xyz
__device__ float  g_blo[BATCH*3];
__device__ float  g_bhi[BATCH*3];

__device__ __forceinline__ float leakyf(float x) { return x >= 0.f ? x : 0.2f * x; }

// sortable key helpers: lexicographic (score, -index), identical tie semantics
// to jax.lax.top_k (stable, lowest index wins).
__device__ __forceinline__ unsigned f32key(float s) {
    unsigned b = __float_as_uint(s);
    return (b & 0x80000000u) ? ~b : (b | 0x80000000u);
}
__device__ __forceinline__ float unkey(unsigned k) {
    unsigned b = (k & 0x80000000u) ? (k ^ 0x80000000u) : ~k;
    return __uint_as_float(b);
}

__device__ __forceinline__ int spread4(int v) {
    return (v & 1) | ((v & 2) << 2) | ((v & 4) << 4) | ((v & 8) << 6);
}
__device__ __forceinline__ int morton3(int x, int y, int z) {
    return spread4(x) | (spread4(y) << 1) | (spread4(z) << 2);
}

// exact fp32 score in the reference's association order -> 64-bit total key
__device__ __forceinline__ unsigned long long mk_key(const float4& q, float nxxq,
                                                     const float4& c, int cid)
{
    float dot   = __fmaf_rn(q.z, c.z, __fmaf_rn(q.y, c.y, __fmul_rn(q.x, c.x)));
    float inner = __fmul_rn(-2.f, dot);
    float s     = __fsub_rn(__fsub_rn(nxxq, inner), c.w);
    return ((unsigned long long)f32key(s) << 32) | (unsigned)(~cid);
}

// warp-wide bitonic sort ascending (one 64-bit key per lane)
__device__ __forceinline__ unsigned long long bitonic32_asc(unsigned long long v, int lane)
{
    #pragma unroll
    for (int k = 2; k <= 32; k <<= 1) {
        #pragma unroll
        for (int j = k >> 1; j > 0; j >>= 1) {
            unsigned long long o = __shfl_xor_sync(0xffffffffu, v, j);
            bool up    = ((lane & k) == 0);
            bool lower = ((lane & j) == 0);
            unsigned long long mn = v < o ? v : o;
            unsigned long long mx = v < o ? o : v;
            v = (up == lower) ? mn : mx;
        }
    }
    return v;
}

// min-heap replace-root + sift-down (32 entries, smem, single lane)
__device__ __forceinline__ void heap_replace(unsigned long long* h, unsigned long long key)
{
    int i2 = 0;
    #pragma unroll
    for (int lvl = 0; lvl < 5; lvl++) {
        int l = 2 * i2 + 1;
        if (l >= KNN) break;
        int m = l;
        unsigned long long dm = h[l];
        if (l + 1 < KNN) {
            unsigned long long dr = h[l + 1];
            if (dr < dm) { m = l + 1; dm = dr; }
        }
        if (dm >= key) break;
        h[i2] = dm;
        i2 = m;
    }
    h[i2] = key;
}

// ---------------- stage A: per-batch coordinate bounds (+ zero counters) ----
__global__ void bounds_kernel(const float* __restrict__ coords, int sn, int sc,
                              long bstride)
{
    __shared__ float slo[3][256], shi[3][256];
    const int b = blockIdx.x, tid = threadIdx.x;
    const float* cb = coords + (long)b * bstride;
    float l0 = 3.4e38f, l1 = 3.4e38f, l2 = 3.4e38f;
    float h0 = -3.4e38f, h1 = -3.4e38f, h2 = -3.4e38f;
    for (int n = tid; n < NPT; n += 256) {
        float x = cb[(long)n * sn], y = cb[(long)n * sn + sc], z = cb[(long)n * sn + 2 * sc];
        l0 = fminf(l0, x); h0 = fmaxf(h0, x);
        l1 = fminf(l1, y); h1 = fmaxf(h1, y);
        l2 = fminf(l2, z); h2 = fmaxf(h2, z);
    }
    slo[0][tid] = l0; slo[1][tid] = l1; slo[2][tid] = l2;
    shi[0][tid] = h0; shi[1][tid] = h1; shi[2][tid] = h2;
    __syncthreads();
    for (int off = 128; off; off >>= 1) {
        if (tid < off) {
            #pragma unroll
            for (int a = 0; a < 3; a++) {
                slo[a][tid] = fminf(slo[a][tid], slo[a][tid + off]);
                shi[a][tid] = fmaxf(shi[a][tid], shi[a][tid + off]);
            }
        }
        __syncthreads();
    }
    if (tid < 3) { g_blo[b * 3 + tid] = slo[tid][0]; g_bhi[b * 3 + tid] = shi[tid][0]; }
    for (int i = tid; i < NCELL; i += 256) {
        g_hist[b * NCELL + i] = 0;
        g_cursor[b * NCELL + i] = 0;
    }
}

// ---------------- stage B: cell ids + histogram -----------------------------
__global__ void cellcount_kernel(const float* __restrict__ coords, int sn, int sc,
                                 long bstride)
{
    const int b = blockIdx.y;
    const int n = blockIdx.x * 256 + threadIdx.x;
    const float* cb = coords + (long)b * bstride;
    float x = cb[(long)n * sn], y = cb[(long)n * sn + sc], z = cb[(long)n * sn + 2 * sc];
    float lo0 = g_blo[b * 3], lo1 = g_blo[b * 3 + 1], lo2 = g_blo[b * 3 + 2];
    float s0 = (float)GRES / fmaxf(g_bhi[b * 3]     - lo0, 1e-30f);
    float s1 = (float)GRES / fmaxf(g_bhi[b * 3 + 1] - lo1, 1e-30f);
    float s2 = (float)GRES / fmaxf(g_bhi[b * 3 + 2] - lo2, 1e-30f);
    int cx = min(GRES - 1, max(0, (int)((x - lo0) * s0)));
    int cy = min(GRES - 1, max(0, (int)((y - lo1) * s1)));
    int cz = min(GRES - 1, max(0, (int)((z - lo2) * s2)));
    int cell = morton3(cx, cy, cz);
    g_cellid[b * NPT + n] = cell;
    atomicAdd(&g_hist[b * NCELL + cell], 1);
}

// ---------------- stage C: per-batch exclusive scan over 4096 cells ---------
__global__ void scan_kernel()
{
    __shared__ int ss[1024];
    const int b = blockIdx.x, tid = threadIdx.x;
    int v[4]; int base = tid * 4; int s = 0;
    #pragma unroll
    for (int i = 0; i < 4; i++) { v[i] = g_hist[b * NCELL + base + i]; s += v[i]; }
    ss[tid] = s;
    __syncthreads();
    for (int off = 1; off < 1024; off <<= 1) {
        int t = (tid >= off) ? ss[tid - off] : 0;
        __syncthreads();
        ss[tid] += t;
        __syncthreads();
    }
    int ex = ss[tid] - s;
    #pragma unroll
    for (int i = 0; i < 4; i++) { g_cstart[b * NCELL + base + i] = ex; ex += v[i]; }
}

// ---------------- stage D: scatter into Morton order ------------------------
__global__ void scatter_kernel(const float* __restrict__ coords, int sn, int sc,
                               long bstride)
{
    const int b = blockIdx.y;
    const int n = blockIdx.x * 256 + threadIdx.x;
    const float* cb = coords + (long)b * bstride;
    float x = cb[(long)n * sn], y = cb[(long)n * sn + sc], z = cb[(long)n * sn + 2 * sc];
    int cell = g_cellid[b * NPT + n];
    int pos = g_cstart[b * NCELL + cell] + atomicAdd(&g_cursor[b * NCELL + cell], 1);
    float xx = __fadd_rn(__fadd_rn(__fmul_rn(x, x), __fmul_rn(y, y)), __fmul_rn(z, z));
    g_pts4[b * NPT + pos] = make_float4(x, y, z, xx);
    g_pid[b * NPT + pos] = n;
}

// ---------------- stage E: per-tile AABB + max xx ---------------------------
__global__ void tilestats_kernel()
{
    __shared__ float r[7][TPT];
    const int b = blockIdx.y, t = blockIdx.x, tid = threadIdx.x;
    float4 p = g_pts4[b * NPT + t * TPT + tid];
    r[0][tid] = p.x; r[1][tid] = p.y; r[2][tid] = p.z;
    r[3][tid] = p.x; r[4][tid] = p.y; r[5][tid] = p.z;
    r[6][tid] = p.w;
    __syncthreads();
    for (int off = TPT / 2; off; off >>= 1) {
        if (tid < off) {
            r[0][tid] = fminf(r[0][tid], r[0][tid + off]);
            r[1][tid] = fminf(r[1][tid], r[1][tid + off]);
            r[2][tid] = fminf(r[2][tid], r[2][tid + off]);
            r[3][tid] = fmaxf(r[3][tid], r[3][tid + off]);
            r[4][tid] = fmaxf(r[4][tid], r[4][tid + off]);
            r[5][tid] = fmaxf(r[5][tid], r[5][tid + off]);
            r[6][tid] = fmaxf(r[6][tid], r[6][tid + off]);
        }
        __syncthreads();
    }
    if (tid == 0) {
        g_tlo4[b * NTILE + t] = make_float4(r[0][0], r[1][0], r[2][0], r[6][0]);
        g_thi4[b * NTILE + t] = make_float4(r[3][0], r[4][0], r[5][0], 0.f);
    }
}

// ---------------- stage F: warp-per-query pruned exact KNN ------------------
// One warp owns one query. Seed = own tile (64 cands: 32 via bitonic sort ->
// min-heap, 32 via ballot-insert). Then all 128 tiles culled 32-wide (ballot,
// conservative margin), survivors scanned 32 candidates/round with rare
// serialized inserts through lane 0. Keys/scores bitwise identical to the
// brute-force kernel; selection is a total order -> result independent of
// insertion order. Output sorted desc (== top_k order) via bitonic.
#define QWARPS 8

__global__ void knn_query_warp_kernel(int* __restrict__ out_idx)
{
    __shared__ float4 s_tA[NTILE], s_tB[NTILE];
    __shared__ unsigned long long s_heap[QWARPS * KNN];
    __shared__ unsigned char s_surv[QWARPS][NTILE];

    const int lane = threadIdx.x & 31;
    const int w    = threadIdx.x >> 5;
    const int b    = blockIdx.y;
    const int p    = blockIdx.x * QWARPS + w;   // query position in sorted order

    for (int i = threadIdx.x; i < NTILE; i += QWARPS * 32) {
        s_tA[i] = g_tlo4[b * NTILE + i];
        s_tB[i] = g_thi4[b * NTILE + i];
    }
    __syncthreads();

    unsigned long long* hw = s_heap + w * KNN;

    const float4 q = g_pts4[b * NPT + p];
    const int qid = g_pid[b * NPT + p];
    const float nxxq = -q.w;
    const int t0 = p / TPT;

    // ---- seed from own tile ----
    const int base0 = b * NPT + t0 * TPT;
    float4 cA = __ldg(&g_pts4[base0 + lane]);
    unsigned long long keyA = mk_key(q, nxxq, cA, __ldg(&g_pid[base0 + lane]));
    float4 cB = __ldg(&g_pts4[base0 + 32 + lane]);
    unsigned long long keyB = mk_key(q, nxxq, cB, __ldg(&g_pid[base0 + 32 + lane]));

    unsigned long long sorted = bitonic32_asc(keyA, lane);
    hw[lane] = sorted;                       // ascending array == valid min-heap
    __syncwarp();
    unsigned long long rootk = hw[0];        // broadcast read

    // ballot-insert helper (uniform control flow; root broadcast via smem)
    {
        unsigned mask = __ballot_sync(0xffffffffu, keyB > rootk);
        while (mask) {
            int src = __ffs(mask) - 1; mask &= mask - 1;
            unsigned long long k = __shfl_sync(0xffffffffu, keyB, src);
            if (k > rootk) {
                if (lane == 0) heap_replace(hw, k);
                __syncwarp();
                rootk = hw[0];
            }
        }
    }

    // ---- cull all tiles 32-wide, build survivor list ----
    int nsurv = 0;
    {
        float root_s = unkey((unsigned)(rootk >> 32));
        #pragma unroll
        for (int r = 0; r < NTILE / 32; r++) {
            int t = r * 32 + lane;
            float4 tA = s_tA[t], tB = s_tB[t];
            float d2 = 0.f;
            float d = fmaxf(fmaxf(tA.x - q.x, q.x - tB.x), 0.f); d2 = fmaf(d, d, d2);
            d = fmaxf(fmaxf(tA.y - q.y, q.y - tB.y), 0.f);       d2 = fmaf(d, d, d2);
            d = fmaxf(fmaxf(tA.z - q.z, q.z - tB.z), 0.f);       d2 = fmaf(d, d, d2);
            float margin = fmaf(2e-6f, q.w + tA.w, 1e-6f);
            bool surv = (t != t0) && (d2 * 0.999999f <= -root_s + margin);
            unsigned m = __ballot_sync(0xffffffffu, surv);
            int mypos = nsurv + __popc(m & ((1u << lane) - 1));
            if (surv) s_surv[w][mypos] = (unsigned char)t;
            nsurv += __popc(m);
        }
    }
    __syncwarp();

    // ---- scan surviving tiles ----
    for (int i = 0; i < nsurv; i++) {
        int t = s_surv[w][i];
        // re-check with current (tighter) root — uniform branch
        float4 tA = s_tA[t], tB = s_tB[t];
        float root_s = unkey((unsigned)(rootk >> 32));
        float d2 = 0.f;
        {
            float d = fmaxf(fmaxf(tA.x - q.x, q.x - tB.x), 0.f); d2 = fmaf(d, d, d2);
            d = fmaxf(fmaxf(tA.y - q.y, q.y - tB.y), 0.f);       d2 = fmaf(d, d, d2);
            d = fmaxf(fmaxf(tA.z - q.z, q.z - tB.z), 0.f);       d2 = fmaf(d, d, d2);
        }
        float margin = fmaf(2e-6f, q.w + tA.w, 1e-6f);
        if (d2 * 0.999999f > -root_s + margin) continue;

        #pragma unroll
        for (int half = 0; half < 2; half++) {
            int ci = b * NPT + t * TPT + half * 32 + lane;
            float4 c = __ldg(&g_pts4[ci]);
            unsigned long long key = mk_key(q, nxxq, c, __ldg(&g_pid[ci]));
            unsigned mask = __ballot_sync(0xffffffffu, key > rootk);
            while (mask) {
                int src = __ffs(mask) - 1; mask &= mask - 1;
                unsigned long long k = __shfl_sync(0xffffffffu, key, src);
                if (k > rootk) {
                    if (lane == 0) heap_replace(hw, k);
                    __syncwarp();
                    rootk = hw[0];
                }
            }
        }
    }

    // ---- final sort (desc) + write in top_k order ----
    __syncwarp();
    unsigned long long v = hw[lane];
    v = bitonic32_asc(v, lane);
    int* op = out_idx + (long)(b * NPT + qid) * KNN;
    op[31 - lane] = (int)(~(unsigned)v);
}

// --------- geometry (cov eig features, double precision) + saliency + x ----
#define GEO_BLK 64

__global__ void geom_kernel(const float* __restrict__ points,
                            const int*   __restrict__ idx,
                            const float* __restrict__ sal_w1,
                            const float* __restrict__ sal_g, const float* __restrict__ sal_b,
                            const float* __restrict__ sal_m, const float* __restrict__ sal_v,
                            const float* __restrict__ sal_w2, const float* __restrict__ sal_b2,
                            float* __restrict__ xout)
{
    __shared__ float sx[KNN * GEO_BLK], sy[KNN * GEO_BLK], sz[KNN * GEO_BLK];
    const int tid = threadIdx.x;
    const int b   = blockIdx.y;
    const int q   = blockIdx.x * GEO_BLK + tid;
    const float* pb = points + (long)b * 3 * NPT;
    const int* ip = idx + (long)(b * NPT + q) * KNN;

    double mx = 0, my = 0, mz = 0;
    #pragma unroll
    for (int k = 0; k < KNN; k++) {
        int j = ip[k];
        float nx = pb[j], ny = pb[NPT + j], nz = pb[2 * NPT + j];
        sx[k * GEO_BLK + tid] = nx; sy[k * GEO_BLK + tid] = ny; sz[k * GEO_BLK + tid] = nz;
        mx += nx; my += ny; mz += nz;
    }
    mx *= (1.0 / KNN); my *= (1.0 / KNN); mz *= (1.0 / KNN);

    double cxx = 0, cxy = 0, cxz = 0, cyy = 0, cyz = 0, czz = 0;
    #pragma unroll
    for (int k = 0; k < KNN; k++) {
        double dx = (double)sx[k * GEO_BLK + tid] - mx;
        double dy = (double)sy[k * GEO_BLK + tid] - my;
        double dz = (double)sz[k * GEO_BLK + tid] - mz;
        cxx += dx * dx; cxy += dx * dy; cxz += dx * dz;
        cyy += dy * dy; cyz += dy * dz; czz += dz * dz;
    }
    const double invk = 1.0 / KNN;
    cxx *= invk; cxy *= invk; cxz *= invk; cyy *= invk; cyz *= invk; czz *= invk;

    double q3 = (cxx + cyy + czz) / 3.0;
    double p1 = cxy * cxy + cxz * cxz + cyz * cyz;
    double p2 = (cxx - q3) * (cxx - q3) + (cyy - q3) * (cyy - q3) + (czz - q3) * (czz - q3) + 2.0 * p1;
    double p = sqrt(p2 / 6.0);
    double e1, e2, e3;
    if (p < 1e-150) { e1 = e2 = e3 = q3; }
    else {
        double inv = 1.0 / p;
        double b00 = (cxx - q3) * inv, b11 = (cyy - q3) * inv, b22 = (czz - q3) * inv;
        double b01 = cxy * inv, b02 = cxz * inv, b12 = cyz * inv;
        double detB = b00 * (b11 * b22 - b12 * b12) - b01 * (b01 * b22 - b12 * b02)
                    + b02 * (b01 * b12 - b11 * b02);
        double r = 0.5 * detB;
        r = fmin(1.0, fmax(-1.0, r));
        double phi = acos(r) / 3.0;
        e1 = q3 + 2.0 * p * cos(phi);
        e3 = q3 + 2.0 * p * cos(phi + 2.0943951023931953);
        e2 = 3.0 * q3 - e1 - e3;
    }
    double l0 = e3, l1 = e2, l2 = e1;
    const double eps = 1e-8;
    float geomf[5];
    geomf[0] = (float)((l2 - l1) / (l2 + eps));
    geomf[1] = (float)((l1 - l0) / (l2 + eps));
    geomf[2] = (float)(l0 / (l2 + eps));
    geomf[3] = (float)(l0 / (l0 + l1 + l2 + eps));
    geomf[4] = (float)((l2 - l0) / (l2 + eps));

    float dot = 0.f;
    #pragma unroll
    for (int o = 0; o < 16; o++) {
        float h = 0.f;
        #pragma unroll
        for (int f = 0; f < 5; f++) h = fmaf(sal_w1[o * 5 + f], geomf[f], h);
        float s = sal_g[o] * rsqrtf(sal_v[o] + 1e-5f);
        float t = sal_b[o] - sal_m[o] * s;
        h = leakyf(fmaf(h, s, t));
        dot = fmaf(h, sal_w2[o], dot);
    }
    float sal = 1.f / (1.f + expf(-(dot + sal_b2[0])));

    float* xr = xout + (long)(b * NPT + q) * 9;
    xr[0] = pb[q]; xr[1] = pb[NPT + q]; xr[2] = pb[2 * NPT + q];
    xr[3] = geomf[0]; xr[4] = geomf[1]; xr[5] = geomf[2]; xr[6] = geomf[3]; xr[7] = geomf[4];
    xr[8] = sal;
}

// ------- per-node edge_conv precompute: ys = s*(Wd x), zc = s*((Wc-Wd)x)+t --
template<int CIN>
__global__ void convpre_kernel(const float* __restrict__ xin,
                               const float* __restrict__ w,
                               const float* __restrict__ bng, const float* __restrict__ bnb,
                               const float* __restrict__ bnm, const float* __restrict__ bnv,
                               float* __restrict__ ys, float* __restrict__ zc)
{
    long T = (long)blockIdx.x * blockDim.x + threadIdx.x;
    int  o = (int)(T & 63);
    long p = T >> 6;
    if (p >= (long)BATCH * NPT) return;
    const float* xr = xin + p * CIN;
    const float* wd = w + (long)o * 2 * CIN;
    const float* wc = wd + CIN;
    float ad = 0.f, ac = 0.f;
    #pragma unroll
    for (int c = 0; c < CIN; c++) {
        float xv = xr[c];
        float a = wd[c];
        ad = fmaf(a, xv, ad);
        ac = fmaf(wc[c] - a, xv, ac);
    }
    float s = bng[o] * rsqrtf(bnv[o] + 1e-5f);
    float t = bnb[o] - bnm[o] * s;
    ys[p * 64 + o] = s * ad;
    zc[p * 64 + o] = fmaf(s, ac, t);
}

// ------- edge_conv reduce: x_out[i] = leaky(max_k (ys[idx[i,k]] + zc[i])) ---
__global__ void edge_reduce_kernel(const float* __restrict__ ys, const float* __restrict__ zc,
                                   const int* __restrict__ idx, float* __restrict__ xout)
{
    long warp = ((long)blockIdx.x * blockDim.x + threadIdx.x) >> 5;
    int  lane = threadIdx.x & 31;
    if (warp >= (long)BATCH * NPT) return;
    const long bbase = (warp >> 13) << 13;
    int myj = idx[warp * KNN + lane];
    const float2* ysp = (const float2*)ys;
    float2 z = ((const float2*)zc)[warp * 32 + lane];
    float2 best = make_float2(-3.4e38f, -3.4e38f);
    #pragma unroll
    for (int k = 0; k < KNN; k++) {
        long j = bbase + __shfl_sync(0xffffffffu, myj, k);
        float2 v = ysp[j * 32 + lane];
        best.x = fmaxf(best.x, v.x + z.x);
        best.y = fmaxf(best.y, v.y + z.y);
    }
    best.x = leakyf(best.x);
    best.y = leakyf(best.y);
    ((float2*)xout)[warp * 32 + lane] = best;
}

// --------- classifier: h = leaky(bn(g@W1^T)); logits = h@W2^T + b2 ---------
#define CLS_GRID 256
#define CLS_PPB  ((BATCH*NPT)/CLS_GRID)

__global__ void cls_kernel(const float* __restrict__ x1, const float* __restrict__ x2,
                           const float* __restrict__ w1,
                           const float* __restrict__ bg, const float* __restrict__ bb,
                           const float* __restrict__ bm, const float* __restrict__ bv,
                           const float* __restrict__ w2, const float* __restrict__ b2,
                           float* __restrict__ out)
{
    extern __shared__ float sm[];
    float* WsT  = sm;
    float* Ts   = WsT + 128 * 256;
    float* W2s  = Ts + 256;
    float* gbuf = W2s + 512;
    float* red  = gbuf + 128;

    const int tid = threadIdx.x;
    {
        float s = bg[tid] * rsqrtf(bv[tid] + 1e-5f);
        Ts[tid] = bb[tid] - bm[tid] * s;
        for (int c = 0; c < 128; c++) WsT[c * 256 + tid] = w1[tid * 128 + c] * s;
        W2s[tid] = w2[tid]; W2s[256 + tid] = w2[256 + tid];
    }
    __syncthreads();

    for (int it = 0; it < CLS_PPB; it++) {
        long P = (long)blockIdx.x * CLS_PPB + it;
        if (tid < 64)       gbuf[tid] = x1[P * 64 + tid];
        else if (tid < 128) gbuf[tid] = x2[P * 64 + tid - 64];
        __syncthreads();

        float acc = Ts[tid];
        #pragma unroll 8
        for (int c = 0; c < 128; c++) acc = fmaf(WsT[c * 256 + tid], gbuf[c], acc);
        float h = leakyf(acc);
        float p0 = h * W2s[tid], p1 = h * W2s[256 + tid];
        #pragma unroll
        for (int off = 16; off; off >>= 1) {
            p0 += __shfl_down_sync(0xffffffffu, p0, off);
            p1 += __shfl_down_sync(0xffffffffu, p1, off);
        }
        int w = tid >> 5;
        if ((tid & 31) == 0) { red[w] = p0; red[8 + w] = p1; }
        __syncthreads();
        if (tid == 0) {
            float l0 = b2[0], l1 = b2[1];
            #pragma unroll
            for (int i = 0; i < 8; i++) { l0 += red[i]; l1 += red[8 + i]; }
            long bbatch = P / NPT, nn = P % NPT;
            out[bbatch * 2 * NPT + nn]       = l0;
            out[bbatch * 2 * NPT + NPT + nn] = l1;
        }
        __syncthreads();
    }
}

// ---------------------------------------------------------------------------
static void run_knn(const float* coords, int sn, int sc, long bstride, int* out_idx)
{
    bounds_kernel<<<BATCH, 256>>>(coords, sn, sc, bstride);
    cellcount_kernel<<<dim3(NPT / 256, BATCH), 256>>>(coords, sn, sc, bstride);
    scan_kernel<<<BATCH, 1024>>>();
    scatter_kernel<<<dim3(NPT / 256, BATCH), 256>>>(coords, sn, sc, bstride);
    tilestats_kernel<<<dim3(NTILE, BATCH), TPT>>>();
    knn_query_warp_kernel<<<dim3(NPT / QWARPS, BATCH), QWARPS * 32>>>(out_idx);
}

extern "C" void kernel_launch(void* const* d_in, const int* in_sizes, int n_in,
                              void* d_out, int out_size)
{
    const float* points  = (const float*)d_in[0];
    const float* sal_w1  = (const float*)d_in[1];
    const float* sal_g   = (const float*)d_in[2];
    const float* sal_b   = (const float*)d_in[3];
    const float* sal_m   = (const float*)d_in[4];
    const float* sal_v   = (const float*)d_in[5];
    const float* sal_w2  = (const float*)d_in[6];
    const float* sal_b2  = (const float*)d_in[7];
    const float* c1_w    = (const float*)d_in[8];
    const float* c1_g    = (const float*)d_in[9];
    const float* c1_b    = (const float*)d_in[10];
    const float* c1_m    = (const float*)d_in[11];
    const float* c1_v    = (const float*)d_in[12];
    const float* c2_w    = (const float*)d_in[13];
    const float* c2_g    = (const float*)d_in[14];
    const float* c2_b    = (const float*)d_in[15];
    const float* c2_m    = (const float*)d_in[16];
    const float* c2_v    = (const float*)d_in[17];
    const float* cls_w1  = (const float*)d_in[18];
    const float* cls_g   = (const float*)d_in[19];
    const float* cls_b   = (const float*)d_in[20];
    const float* cls_m   = (const float*)d_in[21];
    const float* cls_v   = (const float*)d_in[22];
    const float* cls_w2  = (const float*)d_in[23];
    const float* cls_b2  = (const float*)d_in[24];
    float* out = (float*)d_out;

    int*   idx1; cudaGetSymbolAddress((void**)&idx1, g_idx1);
    int*   idx2; cudaGetSymbolAddress((void**)&idx2, g_idx2);
    float* xf  ; cudaGetSymbolAddress((void**)&xf , g_x  );
    float* ys1 ; cudaGetSymbolAddress((void**)&ys1, g_ys1);
    float* zc1 ; cudaGetSymbolAddress((void**)&zc1, g_zc1);
    float* x1  ; cudaGetSymbolAddress((void**)&x1 , g_x1 );
    float* ys2 ; cudaGetSymbolAddress((void**)&ys2, g_ys2);
    float* zc2 ; cudaGetSymbolAddress((void**)&zc2, g_zc2);
    float* x2  ; cudaGetSymbolAddress((void**)&x2 , g_x2 );

    // 1) knn on raw points (layout (B,3,N): sn=1, sc=N)
    run_knn(points, 1, NPT, (long)3 * NPT, idx1);

    // 2) geometry + saliency -> x (B,N,9)
    geom_kernel<<<dim3(NPT / GEO_BLK, BATCH), GEO_BLK>>>(
        points, idx1, sal_w1, sal_g, sal_b, sal_m, sal_v, sal_w2, sal_b2, xf);

    // 3) edge_conv1 -> x1
    {
        long total = (long)BATCH * NPT * 64;
        convpre_kernel<9><<<(unsigned)(total / 128), 128>>>(xf, c1_w, c1_g, c1_b, c1_m, c1_v, ys1, zc1);
        edge_reduce_kernel<<<(BATCH * NPT) / 4, 128>>>(ys1, zc1, idx1, x1);
    }

    // 4) knn on x1[...,0:3] (layout (B,N,64): sn=64, sc=1)
    run_knn(x1, 64, 1, (long)NPT * 64, idx2);

    // 5) edge_conv2 -> x2
    {
        long total = (long)BATCH * NPT * 64;
        convpre_kernel<64><<<(unsigned)(total / 128), 128>>>(x1, c2_w, c2_g, c2_b, c2_m, c2_v, ys2, zc2);
        edge_reduce_kernel<<<(BATCH * NPT) / 4, 128>>>(ys2, zc2, idx2, x2);
    }

    // 6) classifier
    {
        size_t smem = (128 * 256 + 256 + 512 + 128 + 16) * sizeof(float);
        cudaFuncSetAttribute(cls_kernel, cudaFuncAttributeMaxDynamicSharedMemorySize, (int)smem);
        cls_kernel<<<CLS_GRID, 256, smem>>>(x1, x2, cls_w1,
                                            cls_g, cls_b, cls_m, cls_v,
                                            cls_w2, cls_b2, out);
    }
}

// round 14
// speedup vs baseline: 1.5442x; 1.0127x over previous
#include <cuda_runtime.h>
#include <cuda_bf16.h>
#include <math.h>
#include <stdint.h>

#define BATCH 4
#define NPT   8192
#define KNN   32

#define GRES  16
#define NCELL (GRES*GRES*GRES)   // 4096
#define TPT   64                 // points per tile
#define NTILE (NPT/TPT)          // 128

// ---------------- scratch (__device__ globals; no allocations allowed) ------
__device__ int    g_idx1[BATCH*NPT*KNN];
__device__ int    g_idx2[BATCH*NPT*KNN];
__device__ float  g_x  [BATCH*NPT*9];
__device__ float  g_ys1[BATCH*NPT*64];
__device__ float  g_zc1[BATCH*NPT*64];
__device__ float  g_x1 [BATCH*NPT*64];
__device__ float  g_ys2[BATCH*NPT*64];
__device__ float  g_zc2[BATCH*NPT*64];
__device__ float  g_x2 [BATCH*NPT*64];
// knn spatial-structure scratch (reused by knn1 then knn2)
__device__ float4 g_pts4[BATCH*NPT];
__device__ int    g_pid [BATCH*NPT];
__device__ int    g_cellid[BATCH*NPT];
__device__ int    g_hist  [BATCH*NCELL];
__device__ int    g_cstart[BATCH*NCELL];
__device__ int    g_cursor[BATCH*NCELL];
__device__ float4 g_tlo4[BATCH*NTILE];          // tile lo.xyz, w = tile max xx
__device__ float4 g_thi4[BATCH*NTILE];          // tile hi.xyz
__device__ float  g_blo[BATCH*3];
__device__ float  g_bhi[BATCH*3];

__device__ __forceinline__ float leakyf(float x) { return x >= 0.f ? x : 0.2f * x; }

// sortable key helpers: lexicographic (score, -index), identical tie semantics
// to jax.lax.top_k (stable, lowest index wins).
__device__ __forceinline__ unsigned f32key(float s) {
    unsigned b = __float_as_uint(s);
    return (b & 0x80000000u) ? ~b : (b | 0x80000000u);
}
__device__ __forceinline__ float unkey(unsigned k) {
    unsigned b = (k & 0x80000000u) ? (k ^ 0x80000000u) : ~k;
    return __uint_as_float(b);
}

__device__ __forceinline__ int spread4(int v) {
    return (v & 1) | ((v & 2) << 2) | ((v & 4) << 4) | ((v & 8) << 6);
}
__device__ __forceinline__ int morton3(int x, int y, int z) {
    return spread4(x) | (spread4(y) << 1) | (spread4(z) << 2);
}

// exact fp32 score in the reference's association order -> 64-bit total key
__device__ __forceinline__ unsigned long long mk_key(const float4& q, float nxxq,
                                                     const float4& c, int cid)
{
    float dot   = __fmaf_rn(q.z, c.z, __fmaf_rn(q.y, c.y, __fmul_rn(q.x, c.x)));
    float inner = __fmul_rn(-2.f, dot);
    float s     = __fsub_rn(__fsub_rn(nxxq, inner), c.w);
    return ((unsigned long long)f32key(s) << 32) | (unsigned)(~cid);
}

// warp-wide bitonic sort ascending (one 64-bit key per lane)
__device__ __forceinline__ unsigned long long bitonic32_asc(unsigned long long v, int lane)
{
    #pragma unroll
    for (int k = 2; k <= 32; k <<= 1) {
        #pragma unroll
        for (int j = k >> 1; j > 0; j >>= 1) {
            unsigned long long o = __shfl_xor_sync(0xffffffffu, v, j);
            bool up    = ((lane & k) == 0);
            bool lower = ((lane & j) == 0);
            unsigned long long mn = v < o ? v : o;
            unsigned long long mx = v < o ? o : v;
            v = (up == lower) ? mn : mx;
        }
    }
    return v;
}

// min-heap replace-root + sift-down (32 entries, smem, single lane)
__device__ __forceinline__ void heap_replace(unsigned long long* h, unsigned long long key)
{
    int i2 = 0;
    #pragma unroll
    for (int lvl = 0; lvl < 5; lvl++) {
        int l = 2 * i2 + 1;
        if (l >= KNN) break;
        int m = l;
        unsigned long long dm = h[l];
        if (l + 1 < KNN) {
            unsigned long long dr = h[l + 1];
            if (dr < dm) { m = l + 1; dm = dr; }
        }
        if (dm >= key) break;
        h[i2] = dm;
        i2 = m;
    }
    h[i2] = key;
}

// ---------------- stage A: per-batch coordinate bounds (+ zero counters) ----
__global__ void bounds_kernel(const float* __restrict__ coords, int sn, int sc,
                              long bstride)
{
    __shared__ float slo[3][256], shi[3][256];
    const int b = blockIdx.x, tid = threadIdx.x;
    const float* cb = coords + (long)b * bstride;
    float l0 = 3.4e38f, l1 = 3.4e38f, l2 = 3.4e38f;
    float h0 = -3.4e38f, h1 = -3.4e38f, h2 = -3.4e38f;
    for (int n = tid; n < NPT; n += 256) {
        float x = cb[(long)n * sn], y = cb[(long)n * sn + sc], z = cb[(long)n * sn + 2 * sc];
        l0 = fminf(l0, x); h0 = fmaxf(h0, x);
        l1 = fminf(l1, y); h1 = fmaxf(h1, y);
        l2 = fminf(l2, z); h2 = fmaxf(h2, z);
    }
    slo[0][tid] = l0; slo[1][tid] = l1; slo[2][tid] = l2;
    shi[0][tid] = h0; shi[1][tid] = h1; shi[2][tid] = h2;
    __syncthreads();
    for (int off = 128; off; off >>= 1) {
        if (tid < off) {
            #pragma unroll
            for (int a = 0; a < 3; a++) {
                slo[a][tid] = fminf(slo[a][tid], slo[a][tid + off]);
                shi[a][tid] = fmaxf(shi[a][tid], shi[a][tid + off]);
            }
        }
        __syncthreads();
    }
    if (tid < 3) { g_blo[b * 3 + tid] = slo[tid][0]; g_bhi[b * 3 + tid] = shi[tid][0]; }
    for (int i = tid; i < NCELL; i += 256) {
        g_hist[b * NCELL + i] = 0;
        g_cursor[b * NCELL + i] = 0;
    }
}

// ---------------- stage B: cell ids + histogram -----------------------------
__global__ void cellcount_kernel(const float* __restrict__ coords, int sn, int sc,
                                 long bstride)
{
    const int b = blockIdx.y;
    const int n = blockIdx.x * 256 + threadIdx.x;
    const float* cb = coords + (long)b * bstride;
    float x = cb[(long)n * sn], y = cb[(long)n * sn + sc], z = cb[(long)n * sn + 2 * sc];
    float lo0 = g_blo[b * 3], lo1 = g_blo[b * 3 + 1], lo2 = g_blo[b * 3 + 2];
    float s0 = (float)GRES / fmaxf(g_bhi[b * 3]     - lo0, 1e-30f);
    float s1 = (float)GRES / fmaxf(g_bhi[b * 3 + 1] - lo1, 1e-30f);
    float s2 = (float)GRES / fmaxf(g_bhi[b * 3 + 2] - lo2, 1e-30f);
    int cx = min(GRES - 1, max(0, (int)((x - lo0) * s0)));
    int cy = min(GRES - 1, max(0, (int)((y - lo1) * s1)));
    int cz = min(GRES - 1, max(0, (int)((z - lo2) * s2)));
    int cell = morton3(cx, cy, cz);
    g_cellid[b * NPT + n] = cell;
    atomicAdd(&g_hist[b * NCELL + cell], 1);
}

// ---------------- stage C: per-batch exclusive scan over 4096 cells ---------
__global__ void scan_kernel()
{
    __shared__ int ss[1024];
    const int b = blockIdx.x, tid = threadIdx.x;
    int v[4]; int base = tid * 4; int s = 0;
    #pragma unroll
    for (int i = 0; i < 4; i++) { v[i] = g_hist[b * NCELL + base + i]; s += v[i]; }
    ss[tid] = s;
    __syncthreads();
    for (int off = 1; off < 1024; off <<= 1) {
        int t = (tid >= off) ? ss[tid - off] : 0;
        __syncthreads();
        ss[tid] += t;
        __syncthreads();
    }
    int ex = ss[tid] - s;
    #pragma unroll
    for (int i = 0; i < 4; i++) { g_cstart[b * NCELL + base + i] = ex; ex += v[i]; }
}

// ---------------- stage D: scatter into Morton order ------------------------
__global__ void scatter_kernel(const float* __restrict__ coords, int sn, int sc,
                               long bstride)
{
    const int b = blockIdx.y;
    const int n = blockIdx.x * 256 + threadIdx.x;
    const float* cb = coords + (long)b * bstride;
    float x = cb[(long)n * sn], y = cb[(long)n * sn + sc], z = cb[(long)n * sn + 2 * sc];
    int cell = g_cellid[b * NPT + n];
    int pos = g_cstart[b * NCELL + cell] + atomicAdd(&g_cursor[b * NCELL + cell], 1);
    float xx = __fadd_rn(__fadd_rn(__fmul_rn(x, x), __fmul_rn(y, y)), __fmul_rn(z, z));
    g_pts4[b * NPT + pos] = make_float4(x, y, z, xx);
    g_pid[b * NPT + pos] = n;
}

// ---------------- stage E: per-tile AABB + max xx ---------------------------
__global__ void tilestats_kernel()
{
    __shared__ float r[7][TPT];
    const int b = blockIdx.y, t = blockIdx.x, tid = threadIdx.x;
    float4 p = g_pts4[b * NPT + t * TPT + tid];
    r[0][tid] = p.x; r[1][tid] = p.y; r[2][tid] = p.z;
    r[3][tid] = p.x; r[4][tid] = p.y; r[5][tid] = p.z;
    r[6][tid] = p.w;
    __syncthreads();
    for (int off = TPT / 2; off; off >>= 1) {
        if (tid < off) {
            r[0][tid] = fminf(r[0][tid], r[0][tid + off]);
            r[1][tid] = fminf(r[1][tid], r[1][tid + off]);
            r[2][tid] = fminf(r[2][tid], r[2][tid + off]);
            r[3][tid] = fmaxf(r[3][tid], r[3][tid + off]);
            r[4][tid] = fmaxf(r[4][tid], r[4][tid + off]);
            r[5][tid] = fmaxf(r[5][tid], r[5][tid + off]);
            r[6][tid] = fmaxf(r[6][tid], r[6][tid + off]);
        }
        __syncthreads();
    }
    if (tid == 0) {
        g_tlo4[b * NTILE + t] = make_float4(r[0][0], r[1][0], r[2][0], r[6][0]);
        g_thi4[b * NTILE + t] = make_float4(r[3][0], r[4][0], r[5][0], 0.f);
    }
}

// ---------------- stage F: warp-per-query pruned exact KNN ------------------
#define QWARPS 8

__global__ void knn_query_warp_kernel(int* __restrict__ out_idx)
{
    __shared__ float4 s_tA[NTILE], s_tB[NTILE];
    __shared__ unsigned long long s_heap[QWARPS * KNN];
    __shared__ unsigned char s_surv[QWARPS][NTILE];

    const int lane = threadIdx.x & 31;
    const int w    = threadIdx.x >> 5;
    const int b    = blockIdx.y;
    const int p    = blockIdx.x * QWARPS + w;   // query position in sorted order

    for (int i = threadIdx.x; i < NTILE; i += QWARPS * 32) {
        s_tA[i] = g_tlo4[b * NTILE + i];
        s_tB[i] = g_thi4[b * NTILE + i];
    }
    __syncthreads();

    unsigned long long* hw = s_heap + w * KNN;

    const float4 q = g_pts4[b * NPT + p];
    const int qid = g_pid[b * NPT + p];
    const float nxxq = -q.w;
    const int t0 = p / TPT;

    // ---- seed from own tile ----
    const int base0 = b * NPT + t0 * TPT;
    float4 cA = __ldg(&g_pts4[base0 + lane]);
    unsigned long long keyA = mk_key(q, nxxq, cA, __ldg(&g_pid[base0 + lane]));
    float4 cB = __ldg(&g_pts4[base0 + 32 + lane]);
    unsigned long long keyB = mk_key(q, nxxq, cB, __ldg(&g_pid[base0 + 32 + lane]));

    unsigned long long sorted = bitonic32_asc(keyA, lane);
    hw[lane] = sorted;                       // ascending array == valid min-heap
    __syncwarp();
    unsigned long long rootk = hw[0];        // broadcast read

    {
        unsigned mask = __ballot_sync(0xffffffffu, keyB > rootk);
        while (mask) {
            int src = __ffs(mask) - 1; mask &= mask - 1;
            unsigned long long k = __shfl_sync(0xffffffffu, keyB, src);
            if (k > rootk) {
                if (lane == 0) heap_replace(hw, k);
                __syncwarp();
                rootk = hw[0];
            }
        }
    }

    // ---- cull all tiles 32-wide, build survivor list ----
    int nsurv = 0;
    {
        float root_s = unkey((unsigned)(rootk >> 32));
        #pragma unroll
        for (int r = 0; r < NTILE / 32; r++) {
            int t = r * 32 + lane;
            float4 tA = s_tA[t], tB = s_tB[t];
            float d2 = 0.f;
            float d = fmaxf(fmaxf(tA.x - q.x, q.x - tB.x), 0.f); d2 = fmaf(d, d, d2);
            d = fmaxf(fmaxf(tA.y - q.y, q.y - tB.y), 0.f);       d2 = fmaf(d, d, d2);
            d = fmaxf(fmaxf(tA.z - q.z, q.z - tB.z), 0.f);       d2 = fmaf(d, d, d2);
            float margin = fmaf(2e-6f, q.w + tA.w, 1e-6f);
            bool surv = (t != t0) && (d2 * 0.999999f <= -root_s + margin);
            unsigned m = __ballot_sync(0xffffffffu, surv);
            int mypos = nsurv + __popc(m & ((1u << lane) - 1));
            if (surv) s_surv[w][mypos] = (unsigned char)t;
            nsurv += __popc(m);
        }
    }
    __syncwarp();

    // ---- scan surviving tiles ----
    for (int i = 0; i < nsurv; i++) {
        int t = s_surv[w][i];
        float4 tA = s_tA[t], tB = s_tB[t];
        float root_s = unkey((unsigned)(rootk >> 32));
        float d2 = 0.f;
        {
            float d = fmaxf(fmaxf(tA.x - q.x, q.x - tB.x), 0.f); d2 = fmaf(d, d, d2);
            d = fmaxf(fmaxf(tA.y - q.y, q.y - tB.y), 0.f);       d2 = fmaf(d, d, d2);
            d = fmaxf(fmaxf(tA.z - q.z, q.z - tB.z), 0.f);       d2 = fmaf(d, d, d2);
        }
        float margin = fmaf(2e-6f, q.w + tA.w, 1e-6f);
        if (d2 * 0.999999f > -root_s + margin) continue;

        #pragma unroll
        for (int half = 0; half < 2; half++) {
            int ci = b * NPT + t * TPT + half * 32 + lane;
            float4 c = __ldg(&g_pts4[ci]);
            unsigned long long key = mk_key(q, nxxq, c, __ldg(&g_pid[ci]));
            unsigned mask = __ballot_sync(0xffffffffu, key > rootk);
            while (mask) {
                int src = __ffs(mask) - 1; mask &= mask - 1;
                unsigned long long k = __shfl_sync(0xffffffffu, key, src);
                if (k > rootk) {
                    if (lane == 0) heap_replace(hw, k);
                    __syncwarp();
                    rootk = hw[0];
                }
            }
        }
    }

    // ---- final sort (desc) + write in top_k order ----
    __syncwarp();
    unsigned long long v = hw[lane];
    v = bitonic32_asc(v, lane);
    int* op = out_idx + (long)(b * NPT + qid) * KNN;
    op[31 - lane] = (int)(~(unsigned)v);
}

// --------- geometry (cov eig features, fp32 — sm_103a FP64 is ~8 ops/cyc
// chip-wide, the old double path alone cost >1ms) + saliency + x ------------
#define GEO_BLK 64

__global__ void geom_kernel(const float* __restrict__ points,
                            const int*   __restrict__ idx,
                            const float* __restrict__ sal_w1,
                            const float* __restrict__ sal_g, const float* __restrict__ sal_b,
                            const float* __restrict__ sal_m, const float* __restrict__ sal_v,
                            const float* __restrict__ sal_w2, const float* __restrict__ sal_b2,
                            float* __restrict__ xout)
{
    __shared__ float sx[KNN * GEO_BLK], sy[KNN * GEO_BLK], sz[KNN * GEO_BLK];
    const int tid = threadIdx.x;
    const int b   = blockIdx.y;
    const int q   = blockIdx.x * GEO_BLK + tid;
    const float* pb = points + (long)b * 3 * NPT;
    const int* ip = idx + (long)(b * NPT + q) * KNN;

    float mx = 0.f, my = 0.f, mz = 0.f;
    #pragma unroll
    for (int k = 0; k < KNN; k++) {
        int j = ip[k];
        float nx = pb[j], ny = pb[NPT + j], nz = pb[2 * NPT + j];
        sx[k * GEO_BLK + tid] = nx; sy[k * GEO_BLK + tid] = ny; sz[k * GEO_BLK + tid] = nz;
        mx += nx; my += ny; mz += nz;
    }
    mx *= (1.f / KNN); my *= (1.f / KNN); mz *= (1.f / KNN);

    float cxx = 0.f, cxy = 0.f, cxz = 0.f, cyy = 0.f, cyz = 0.f, czz = 0.f;
    #pragma unroll
    for (int k = 0; k < KNN; k++) {
        float dx = sx[k * GEO_BLK + tid] - mx;
        float dy = sy[k * GEO_BLK + tid] - my;
        float dz = sz[k * GEO_BLK + tid] - mz;
        cxx = fmaf(dx, dx, cxx); cxy = fmaf(dx, dy, cxy); cxz = fmaf(dx, dz, cxz);
        cyy = fmaf(dy, dy, cyy); cyz = fmaf(dy, dz, cyz); czz = fmaf(dz, dz, czz);
    }
    const float invk = 1.f / KNN;
    cxx *= invk; cxy *= invk; cxz *= invk; cyy *= invk; cyz *= invk; czz *= invk;

    // closed-form symmetric 3x3 eigenvalues (fp32 trig method)
    float q3 = (cxx + cyy + czz) * (1.f / 3.f);
    float p1 = cxy * cxy + cxz * cxz + cyz * cyz;
    float b00 = cxx - q3, b11 = cyy - q3, b22 = czz - q3;
    float p2 = b00 * b00 + b11 * b11 + b22 * b22 + 2.f * p1;
    float p = sqrtf(p2 * (1.f / 6.f));
    float e1, e2, e3;
    if (p < 1e-20f) { e1 = e2 = e3 = q3; }
    else {
        float inv = 1.f / p;
        float n00 = b00 * inv, n11 = b11 * inv, n22 = b22 * inv;
        float n01 = cxy * inv, n02 = cxz * inv, n12 = cyz * inv;
        float detB = n00 * (n11 * n22 - n12 * n12) - n01 * (n01 * n22 - n12 * n02)
                   + n02 * (n01 * n12 - n11 * n02);
        float r = 0.5f * detB;
        r = fminf(1.f, fmaxf(-1.f, r));
        float phi = acosf(r) * (1.f / 3.f);
        e1 = q3 + 2.f * p * cosf(phi);
        e3 = q3 + 2.f * p * cosf(phi + 2.09439510239f);
        e2 = 3.f * q3 - e1 - e3;
    }
    float l0 = e3, l1 = e2, l2 = e1;
    const float eps = 1e-8f;
    float geomf[5];
    float invl2 = 1.f / (l2 + eps);
    geomf[0] = (l2 - l1) * invl2;              // linearity
    geomf[1] = (l1 - l0) * invl2;              // planarity
    geomf[2] = l0 * invl2;                     // sphericity
    geomf[3] = l0 / (l0 + l1 + l2 + eps);      // curvature
    geomf[4] = (l2 - l0) * invl2;              // anisotropy

    // saliency MLP (5 -> 16 -> 1, sigmoid)
    float dot = 0.f;
    #pragma unroll
    for (int o = 0; o < 16; o++) {
        float h = 0.f;
        #pragma unroll
        for (int f = 0; f < 5; f++) h = fmaf(sal_w1[o * 5 + f], geomf[f], h);
        float s = sal_g[o] * rsqrtf(sal_v[o] + 1e-5f);
        float t = sal_b[o] - sal_m[o] * s;
        h = leakyf(fmaf(h, s, t));
        dot = fmaf(h, sal_w2[o], dot);
    }
    float sal = 1.f / (1.f + expf(-(dot + sal_b2[0])));

    float* xr = xout + (long)(b * NPT + q) * 9;
    xr[0] = pb[q]; xr[1] = pb[NPT + q]; xr[2] = pb[2 * NPT + q];
    xr[3] = geomf[0]; xr[4] = geomf[1]; xr[5] = geomf[2]; xr[6] = geomf[3]; xr[7] = geomf[4];
    xr[8] = sal;
}

// ------- per-node edge_conv precompute: ys = s*(Wd x), zc = s*((Wc-Wd)x)+t --
template<int CIN>
__global__ void convpre_kernel(const float* __restrict__ xin,
                               const float* __restrict__ w,
                               const float* __restrict__ bng, const float* __restrict__ bnb,
                               const float* __restrict__ bnm, const float* __restrict__ bnv,
                               float* __restrict__ ys, float* __restrict__ zc)
{
    long T = (long)blockIdx.x * blockDim.x + threadIdx.x;
    int  o = (int)(T & 63);
    long p = T >> 6;
    if (p >= (long)BATCH * NPT) return;
    const float* xr = xin + p * CIN;
    const float* wd = w + (long)o * 2 * CIN;
    const float* wc = wd + CIN;
    float ad = 0.f, ac = 0.f;
    #pragma unroll
    for (int c = 0; c < CIN; c++) {
        float xv = xr[c];
        float a = wd[c];
        ad = fmaf(a, xv, ad);
        ac = fmaf(wc[c] - a, xv, ac);
    }
    float s = bng[o] * rsqrtf(bnv[o] + 1e-5f);
    float t = bnb[o] - bnm[o] * s;
    ys[p * 64 + o] = s * ad;
    zc[p * 64 + o] = fmaf(s, ac, t);
}

// ------- edge_conv reduce: x_out[i] = leaky(max_k (ys[idx[i,k]] + zc[i])) ---
__global__ void edge_reduce_kernel(const float* __restrict__ ys, const float* __restrict__ zc,
                                   const int* __restrict__ idx, float* __restrict__ xout)
{
    long warp = ((long)blockIdx.x * blockDim.x + threadIdx.x) >> 5;
    int  lane = threadIdx.x & 31;
    if (warp >= (long)BATCH * NPT) return;
    const long bbase = (warp >> 13) << 13;
    int myj = idx[warp * KNN + lane];
    const float2* ysp = (const float2*)ys;
    float2 z = ((const float2*)zc)[warp * 32 + lane];
    float2 best = make_float2(-3.4e38f, -3.4e38f);
    #pragma unroll
    for (int k = 0; k < KNN; k++) {
        long j = bbase + __shfl_sync(0xffffffffu, myj, k);
        float2 v = ysp[j * 32 + lane];
        best.x = fmaxf(best.x, v.x + z.x);
        best.y = fmaxf(best.y, v.y + z.y);
    }
    best.x = leakyf(best.x);
    best.y = leakyf(best.y);
    ((float2*)xout)[warp * 32 + lane] = best;
}

// --------- classifier: h = leaky(bn(g@W1^T)); logits = h@W2^T + b2 ---------
#define CLS_GRID 256
#define CLS_PPB  ((BATCH*NPT)/CLS_GRID)

__global__ void cls_kernel(const float* __restrict__ x1, const float* __restrict__ x2,
                           const float* __restrict__ w1,
                           const float* __restrict__ bg, const float* __restrict__ bb,
                           const float* __restrict__ bm, const float* __restrict__ bv,
                           const float* __restrict__ w2, const float* __restrict__ b2,
                           float* __restrict__ out)
{
    extern __shared__ float sm[];
    float* WsT  = sm;
    float* Ts   = WsT + 128 * 256;
    float* W2s  = Ts + 256;
    float* gbuf = W2s + 512;
    float* red  = gbuf + 128;

    const int tid = threadIdx.x;
    {
        float s = bg[tid] * rsqrtf(bv[tid] + 1e-5f);
        Ts[tid] = bb[tid] - bm[tid] * s;
        for (int c = 0; c < 128; c++) WsT[c * 256 + tid] = w1[tid * 128 + c] * s;
        W2s[tid] = w2[tid]; W2s[256 + tid] = w2[256 + tid];
    }
    __syncthreads();

    for (int it = 0; it < CLS_PPB; it++) {
        long P = (long)blockIdx.x * CLS_PPB + it;
        if (tid < 64)       gbuf[tid] = x1[P * 64 + tid];
        else if (tid < 128) gbuf[tid] = x2[P * 64 + tid - 64];
        __syncthreads();

        float acc = Ts[tid];
        #pragma unroll 8
        for (int c = 0; c < 128; c++) acc = fmaf(WsT[c * 256 + tid], gbuf[c], acc);
        float h = leakyf(acc);
        float p0 = h * W2s[tid], p1 = h * W2s[256 + tid];
        #pragma unroll
        for (int off = 16; off; off >>= 1) {
            p0 += __shfl_down_sync(0xffffffffu, p0, off);
            p1 += __shfl_down_sync(0xffffffffu, p1, off);
        }
        int w = tid >> 5;
        if ((tid & 31) == 0) { red[w] = p0; red[8 + w] = p1; }
        __syncthreads();
        if (tid == 0) {
            float l0 = b2[0], l1 = b2[1];
            #pragma unroll
            for (int i = 0; i < 8; i++) { l0 += red[i]; l1 += red[8 + i]; }
            long bbatch = P / NPT, nn = P % NPT;
            out[bbatch * 2 * NPT + nn]       = l0;
            out[bbatch * 2 * NPT + NPT + nn] = l1;
        }
        __syncthreads();
    }
}

// ---------------------------------------------------------------------------
static void run_knn(const float* coords, int sn, int sc, long bstride, int* out_idx)
{
    bounds_kernel<<<BATCH, 256>>>(coords, sn, sc, bstride);
    cellcount_kernel<<<dim3(NPT / 256, BATCH), 256>>>(coords, sn, sc, bstride);
    scan_kernel<<<BATCH, 1024>>>();
    scatter_kernel<<<dim3(NPT / 256, BATCH), 256>>>(coords, sn, sc, bstride);
    tilestats_kernel<<<dim3(NTILE, BATCH), TPT>>>();
    knn_query_warp_kernel<<<dim3(NPT / QWARPS, BATCH), QWARPS * 32>>>(out_idx);
}

extern "C" void kernel_launch(void* const* d_in, const int* in_sizes, int n_in,
                              void* d_out, int out_size)
{
    const float* points  = (const float*)d_in[0];
    const float* sal_w1  = (const float*)d_in[1];
    const float* sal_g   = (const float*)d_in[2];
    const float* sal_b   = (const float*)d_in[3];
    const float* sal_m   = (const float*)d_in[4];
    const float* sal_v   = (const float*)d_in[5];
    const float* sal_w2  = (const float*)d_in[6];
    const float* sal_b2  = (const float*)d_in[7];
    const float* c1_w    = (const float*)d_in[8];
    const float* c1_g    = (const float*)d_in[9];
    const float* c1_b    = (const float*)d_in[10];
    const float* c1_m    = (const float*)d_in[11];
    const float* c1_v    = (const float*)d_in[12];
    const float* c2_w    = (const float*)d_in[13];
    const float* c2_g    = (const float*)d_in[14];
    const float* c2_b    = (const float*)d_in[15];
    const float* c2_m    = (const float*)d_in[16];
    const float* c2_v    = (const float*)d_in[17];
    const float* cls_w1  = (const float*)d_in[18];
    const float* cls_g   = (const float*)d_in[19];
    const float* cls_b   = (const float*)d_in[20];
    const float* cls_m   = (const float*)d_in[21];
    const float* cls_v   = (const float*)d_in[22];
    const float* cls_w2  = (const float*)d_in[23];
    const float* cls_b2  = (const float*)d_in[24];
    float* out = (float*)d_out;

    int*   idx1; cudaGetSymbolAddress((void**)&idx1, g_idx1);
    int*   idx2; cudaGetSymbolAddress((void**)&idx2, g_idx2);
    float* xf  ; cudaGetSymbolAddress((void**)&xf , g_x  );
    float* ys1 ; cudaGetSymbolAddress((void**)&ys1, g_ys1);
    float* zc1 ; cudaGetSymbolAddress((void**)&zc1, g_zc1);
    float* x1  ; cudaGetSymbolAddress((void**)&x1 , g_x1 );
    float* ys2 ; cudaGetSymbolAddress((void**)&ys2, g_ys2);
    float* zc2 ; cudaGetSymbolAddress((void**)&zc2, g_zc2);
    float* x2  ; cudaGetSymbolAddress((void**)&x2 , g_x2 );

    // 1) knn on raw points (layout (B,3,N): sn=1, sc=N)
    run_knn(points, 1, NPT, (long)3 * NPT, idx1);

    // 2) geometry + saliency -> x (B,N,9)
    geom_kernel<<<dim3(NPT / GEO_BLK, BATCH), GEO_BLK>>>(
        points, idx1, sal_w1, sal_g, sal_b, sal_m, sal_v, sal_w2, sal_b2, xf);

    // 3) edge_conv1 -> x1
    {
        long total = (long)BATCH * NPT * 64;
        convpre_kernel<9><<<(unsigned)(total / 128), 128>>>(xf, c1_w, c1_g, c1_b, c1_m, c1_v, ys1, zc1);
        edge_reduce_kernel<<<(BATCH * NPT) / 4, 128>>>(ys1, zc1, idx1, x1);
    }

    // 4) knn on x1[...,0:3] (layout (B,N,64): sn=64, sc=1)
    run_knn(x1, 64, 1, (long)NPT * 64, idx2);

    // 5) edge_conv2 -> x2
    {
        long total = (long)BATCH * NPT * 64;
        convpre_kernel<64><<<(unsigned)(total / 128), 128>>>(x1, c2_w, c2_g, c2_b, c2_m, c2_v, ys2, zc2);
        edge_reduce_kernel<<<(BATCH * NPT) / 4, 128>>>(ys2, zc2, idx2, x2);
    }

    // 6) classifier
    {
        size_t smem = (128 * 256 + 256 + 512 + 128 + 16) * sizeof(float);
        cudaFuncSetAttribute(cls_kernel, cudaFuncAttributeMaxDynamicSharedMemorySize, (int)smem);
        cls_kernel<<<CLS_GRID, 256, smem>>>(x1, x2, cls_w1,
                                            cls_g, cls_b, cls_m, cls_v,
                                            cls_w2, cls_b2, out);
    }
}

// round 15
// speedup vs baseline: 2.8525x; 1.8472x over previous
#include <cuda_runtime.h>
#include <cuda_bf16.h>
#include <math.h>
#include <stdint.h>

#define BATCH 4
#define NPT   8192
#define KNN   32

#define GRES  16
#define NCELL (GRES*GRES*GRES)   // 4096
#define TPT   64                 // points per tile
#define NTILE (NPT/TPT)          // 128

// ---------------- scratch (__device__ globals; no allocations allowed) ------
__device__ int    g_idx1[BATCH*NPT*KNN];
__device__ int    g_idx2[BATCH*NPT*KNN];
__device__ float  g_x  [BATCH*NPT*9];
__device__ float  g_ys1[BATCH*NPT*64];
__device__ float  g_zc1[BATCH*NPT*64];
__device__ float  g_x1 [BATCH*NPT*64];
__device__ float  g_ys2[BATCH*NPT*64];
__device__ float  g_zc2[BATCH*NPT*64];
__device__ float  g_x2 [BATCH*NPT*64];
// knn spatial-structure scratch (reused by knn1 then knn2)
__device__ float4 g_pts4[BATCH*NPT];
__device__ int    g_pid [BATCH*NPT];
__device__ int    g_cellid[BATCH*NPT];
__device__ int    g_hist  [BATCH*NCELL];
__device__ int    g_cstart[BATCH*NCELL];
__device__ int    g_cursor[BATCH*NCELL];
__device__ float4 g_tlo4[BATCH*NTILE];          // tile lo.xyz, w = tile max xx
__device__ float4 g_thi4[BATCH*NTILE];          // tile hi.xyz
__device__ float  g_blo[BATCH*3];
__device__ float  g_bhi[BATCH*3];

__device__ __forceinline__ float leakyf(float x) { return x >= 0.f ? x : 0.2f * x; }

// sortable key helpers: lexicographic (score, -index), identical tie semantics
// to jax.lax.top_k (stable, lowest index wins).
__device__ __forceinline__ unsigned f32key(float s) {
    unsigned b = __float_as_uint(s);
    return (b & 0x80000000u) ? ~b : (b | 0x80000000u);
}
__device__ __forceinline__ float unkey(unsigned k) {
    unsigned b = (k & 0x80000000u) ? (k ^ 0x80000000u) : ~k;
    return __uint_as_float(b);
}

__device__ __forceinline__ int spread4(int v) {
    return (v & 1) | ((v & 2) << 2) | ((v & 4) << 4) | ((v & 8) << 6);
}
__device__ __forceinline__ int morton3(int x, int y, int z) {
    return spread4(x) | (spread4(y) << 1) | (spread4(z) << 2);
}

// exact fp32 score in the reference's association order -> 64-bit total key
__device__ __forceinline__ unsigned long long mk_key(const float4& q, float nxxq,
                                                     const float4& c, int cid)
{
    float dot   = __fmaf_rn(q.z, c.z, __fmaf_rn(q.y, c.y, __fmul_rn(q.x, c.x)));
    float inner = __fmul_rn(-2.f, dot);
    float s     = __fsub_rn(__fsub_rn(nxxq, inner), c.w);
    return ((unsigned long long)f32key(s) << 32) | (unsigned)(~cid);
}

// warp-wide bitonic sort ascending (one 64-bit key per lane)
__device__ __forceinline__ unsigned long long bitonic32_asc(unsigned long long v, int lane)
{
    #pragma unroll
    for (int k = 2; k <= 32; k <<= 1) {
        #pragma unroll
        for (int j = k >> 1; j > 0; j >>= 1) {
            unsigned long long o = __shfl_xor_sync(0xffffffffu, v, j);
            bool up    = ((lane & k) == 0);
            bool lower = ((lane & j) == 0);
            unsigned long long mn = v < o ? v : o;
            unsigned long long mx = v < o ? o : v;
            v = (up == lower) ? mn : mx;
        }
    }
    return v;
}

// register sorted list (ascending across lanes): replace min with k, re-sort.
// Requires k > v[lane0]. ~8 warp-parallel instructions, no smem, no serialization.
__device__ __forceinline__ unsigned long long sorted_insert(unsigned long long v,
                                                            unsigned long long k,
                                                            int lane)
{
    unsigned long long vnext = __shfl_down_sync(0xffffffffu, v, 1);
    if (lane == 31) vnext = 0xFFFFFFFFFFFFFFFFull;
    unsigned long long vmax = v > k ? v : k;
    return (vnext <= k) ? vnext : vmax;
}

// ---------------- stage A: per-batch coordinate bounds (+ zero counters) ----
__global__ void bounds_kernel(const float* __restrict__ coords, int sn, int sc,
                              long bstride)
{
    __shared__ float slo[3][256], shi[3][256];
    const int b = blockIdx.x, tid = threadIdx.x;
    const float* cb = coords + (long)b * bstride;
    float l0 = 3.4e38f, l1 = 3.4e38f, l2 = 3.4e38f;
    float h0 = -3.4e38f, h1 = -3.4e38f, h2 = -3.4e38f;
    for (int n = tid; n < NPT; n += 256) {
        float x = cb[(long)n * sn], y = cb[(long)n * sn + sc], z = cb[(long)n * sn + 2 * sc];
        l0 = fminf(l0, x); h0 = fmaxf(h0, x);
        l1 = fminf(l1, y); h1 = fmaxf(h1, y);
        l2 = fminf(l2, z); h2 = fmaxf(h2, z);
    }
    slo[0][tid] = l0; slo[1][tid] = l1; slo[2][tid] = l2;
    shi[0][tid] = h0; shi[1][tid] = h1; shi[2][tid] = h2;
    __syncthreads();
    for (int off = 128; off; off >>= 1) {
        if (tid < off) {
            #pragma unroll
            for (int a = 0; a < 3; a++) {
                slo[a][tid] = fminf(slo[a][tid], slo[a][tid + off]);
                shi[a][tid] = fmaxf(shi[a][tid], shi[a][tid + off]);
            }
        }
        __syncthreads();
    }
    if (tid < 3) { g_blo[b * 3 + tid] = slo[tid][0]; g_bhi[b * 3 + tid] = shi[tid][0]; }
    for (int i = tid; i < NCELL; i += 256) {
        g_hist[b * NCELL + i] = 0;
        g_cursor[b * NCELL + i] = 0;
    }
}

// ---------------- stage B: cell ids + histogram -----------------------------
__global__ void cellcount_kernel(const float* __restrict__ coords, int sn, int sc,
                                 long bstride)
{
    const int b = blockIdx.y;
    const int n = blockIdx.x * 256 + threadIdx.x;
    const float* cb = coords + (long)b * bstride;
    float x = cb[(long)n * sn], y = cb[(long)n * sn + sc], z = cb[(long)n * sn + 2 * sc];
    float lo0 = g_blo[b * 3], lo1 = g_blo[b * 3 + 1], lo2 = g_blo[b * 3 + 2];
    float s0 = (float)GRES / fmaxf(g_bhi[b * 3]     - lo0, 1e-30f);
    float s1 = (float)GRES / fmaxf(g_bhi[b * 3 + 1] - lo1, 1e-30f);
    float s2 = (float)GRES / fmaxf(g_bhi[b * 3 + 2] - lo2, 1e-30f);
    int cx = min(GRES - 1, max(0, (int)((x - lo0) * s0)));
    int cy = min(GRES - 1, max(0, (int)((y - lo1) * s1)));
    int cz = min(GRES - 1, max(0, (int)((z - lo2) * s2)));
    int cell = morton3(cx, cy, cz);
    g_cellid[b * NPT + n] = cell;
    atomicAdd(&g_hist[b * NCELL + cell], 1);
}

// ---------------- stage C: per-batch exclusive scan over 4096 cells ---------
__global__ void scan_kernel()
{
    __shared__ int ss[1024];
    const int b = blockIdx.x, tid = threadIdx.x;
    int v[4]; int base = tid * 4; int s = 0;
    #pragma unroll
    for (int i = 0; i < 4; i++) { v[i] = g_hist[b * NCELL + base + i]; s += v[i]; }
    ss[tid] = s;
    __syncthreads();
    for (int off = 1; off < 1024; off <<= 1) {
        int t = (tid >= off) ? ss[tid - off] : 0;
        __syncthreads();
        ss[tid] += t;
        __syncthreads();
    }
    int ex = ss[tid] - s;
    #pragma unroll
    for (int i = 0; i < 4; i++) { g_cstart[b * NCELL + base + i] = ex; ex += v[i]; }
}

// ---------------- stage D: scatter into Morton order ------------------------
__global__ void scatter_kernel(const float* __restrict__ coords, int sn, int sc,
                               long bstride)
{
    const int b = blockIdx.y;
    const int n = blockIdx.x * 256 + threadIdx.x;
    const float* cb = coords + (long)b * bstride;
    float x = cb[(long)n * sn], y = cb[(long)n * sn + sc], z = cb[(long)n * sn + 2 * sc];
    int cell = g_cellid[b * NPT + n];
    int pos = g_cstart[b * NCELL + cell] + atomicAdd(&g_cursor[b * NCELL + cell], 1);
    float xx = __fadd_rn(__fadd_rn(__fmul_rn(x, x), __fmul_rn(y, y)), __fmul_rn(z, z));
    g_pts4[b * NPT + pos] = make_float4(x, y, z, xx);
    g_pid[b * NPT + pos] = n;
}

// ---------------- stage E: per-tile AABB + max xx ---------------------------
__global__ void tilestats_kernel()
{
    __shared__ float r[7][TPT];
    const int b = blockIdx.y, t = blockIdx.x, tid = threadIdx.x;
    float4 p = g_pts4[b * NPT + t * TPT + tid];
    r[0][tid] = p.x; r[1][tid] = p.y; r[2][tid] = p.z;
    r[3][tid] = p.x; r[4][tid] = p.y; r[5][tid] = p.z;
    r[6][tid] = p.w;
    __syncthreads();
    for (int off = TPT / 2; off; off >>= 1) {
        if (tid < off) {
            r[0][tid] = fminf(r[0][tid], r[0][tid + off]);
            r[1][tid] = fminf(r[1][tid], r[1][tid + off]);
            r[2][tid] = fminf(r[2][tid], r[2][tid + off]);
            r[3][tid] = fmaxf(r[3][tid], r[3][tid + off]);
            r[4][tid] = fmaxf(r[4][tid], r[4][tid + off]);
            r[5][tid] = fmaxf(r[5][tid], r[5][tid + off]);
            r[6][tid] = fmaxf(r[6][tid], r[6][tid + off]);
        }
        __syncthreads();
    }
    if (tid == 0) {
        g_tlo4[b * NTILE + t] = make_float4(r[0][0], r[1][0], r[2][0], r[6][0]);
        g_thi4[b * NTILE + t] = make_float4(r[3][0], r[4][0], r[5][0], 0.f);
    }
}

// ---------------- stage F: warp-per-query pruned exact KNN ------------------
// Top-32 kept as a register sorted list across lanes (no smem heap, no
// serialized inserts). Keys/scores bitwise identical to brute force; the
// replace-min policy on the same total order yields the identical set.
#define QWARPS 8

__global__ void knn_query_warp_kernel(int* __restrict__ out_idx)
{
    __shared__ float4 s_tA[NTILE], s_tB[NTILE];
    __shared__ unsigned char s_surv[QWARPS][NTILE];

    const int lane = threadIdx.x & 31;
    const int w    = threadIdx.x >> 5;
    const int b    = blockIdx.y;
    const int p    = blockIdx.x * QWARPS + w;   // query position in sorted order

    for (int i = threadIdx.x; i < NTILE; i += QWARPS * 32) {
        s_tA[i] = g_tlo4[b * NTILE + i];
        s_tB[i] = g_thi4[b * NTILE + i];
    }
    __syncthreads();

    const float4 q = g_pts4[b * NPT + p];
    const int qid = g_pid[b * NPT + p];
    const float nxxq = -q.w;
    const int t0 = p / TPT;

    // ---- seed from own tile ----
    const int base0 = b * NPT + t0 * TPT;
    float4 cA = __ldg(&g_pts4[base0 + lane]);
    unsigned long long keyA = mk_key(q, nxxq, cA, __ldg(&g_pid[base0 + lane]));
    float4 cB = __ldg(&g_pts4[base0 + 32 + lane]);
    unsigned long long keyB = mk_key(q, nxxq, cB, __ldg(&g_pid[base0 + 32 + lane]));

    unsigned long long v = bitonic32_asc(keyA, lane);
    unsigned long long rootk = __shfl_sync(0xffffffffu, v, 0);

    {
        unsigned mask = __ballot_sync(0xffffffffu, keyB > rootk);
        while (mask) {
            int src = __ffs(mask) - 1; mask &= mask - 1;
            unsigned long long k = __shfl_sync(0xffffffffu, keyB, src);
            if (k > rootk) {
                v = sorted_insert(v, k, lane);
                rootk = __shfl_sync(0xffffffffu, v, 0);
            }
        }
    }

    // ---- cull all tiles 32-wide, build survivor list ----
    int nsurv = 0;
    {
        float root_s = unkey((unsigned)(rootk >> 32));
        #pragma unroll
        for (int r = 0; r < NTILE / 32; r++) {
            int t = r * 32 + lane;
            float4 tA = s_tA[t], tB = s_tB[t];
            float d2 = 0.f;
            float d = fmaxf(fmaxf(tA.x - q.x, q.x - tB.x), 0.f); d2 = fmaf(d, d, d2);
            d = fmaxf(fmaxf(tA.y - q.y, q.y - tB.y), 0.f);       d2 = fmaf(d, d, d2);
            d = fmaxf(fmaxf(tA.z - q.z, q.z - tB.z), 0.f);       d2 = fmaf(d, d, d2);
            float margin = fmaf(2e-6f, q.w + tA.w, 1e-6f);
            bool surv = (t != t0) && (d2 * 0.999999f <= -root_s + margin);
            unsigned m = __ballot_sync(0xffffffffu, surv);
            int mypos = nsurv + __popc(m & ((1u << lane) - 1));
            if (surv) s_surv[w][mypos] = (unsigned char)t;
            nsurv += __popc(m);
        }
    }
    __syncwarp();

    // ---- scan surviving tiles ----
    for (int i = 0; i < nsurv; i++) {
        int t = s_surv[w][i];
        float4 tA = s_tA[t], tB = s_tB[t];
        float root_s = unkey((unsigned)(rootk >> 32));
        float d2 = 0.f;
        {
            float d = fmaxf(fmaxf(tA.x - q.x, q.x - tB.x), 0.f); d2 = fmaf(d, d, d2);
            d = fmaxf(fmaxf(tA.y - q.y, q.y - tB.y), 0.f);       d2 = fmaf(d, d, d2);
            d = fmaxf(fmaxf(tA.z - q.z, q.z - tB.z), 0.f);       d2 = fmaf(d, d, d2);
        }
        float margin = fmaf(2e-6f, q.w + tA.w, 1e-6f);
        if (d2 * 0.999999f > -root_s + margin) continue;

        #pragma unroll
        for (int half = 0; half < 2; half++) {
            int ci = b * NPT + t * TPT + half * 32 + lane;
            float4 c = __ldg(&g_pts4[ci]);
            unsigned long long key = mk_key(q, nxxq, c, __ldg(&g_pid[ci]));
            unsigned mask = __ballot_sync(0xffffffffu, key > rootk);
            while (mask) {
                int src = __ffs(mask) - 1; mask &= mask - 1;
                unsigned long long k = __shfl_sync(0xffffffffu, key, src);
                if (k > rootk) {
                    v = sorted_insert(v, k, lane);
                    rootk = __shfl_sync(0xffffffffu, v, 0);
                }
            }
        }
    }

    // ---- v already sorted ascending; write in top_k (desc) order ----
    int* op = out_idx + (long)(b * NPT + qid) * KNN;
    op[31 - lane] = (int)(~(unsigned)v);
}

// --------- geometry (cov eig features, fp32) + saliency + x ----------------
#define GEO_BLK 64

__global__ void geom_kernel(const float* __restrict__ points,
                            const int*   __restrict__ idx,
                            const float* __restrict__ sal_w1,
                            const float* __restrict__ sal_g, const float* __restrict__ sal_b,
                            const float* __restrict__ sal_m, const float* __restrict__ sal_v,
                            const float* __restrict__ sal_w2, const float* __restrict__ sal_b2,
                            float* __restrict__ xout)
{
    __shared__ float sx[KNN * GEO_BLK], sy[KNN * GEO_BLK], sz[KNN * GEO_BLK];
    const int tid = threadIdx.x;
    const int b   = blockIdx.y;
    const int q   = blockIdx.x * GEO_BLK + tid;
    const float* pb = points + (long)b * 3 * NPT;
    const int* ip = idx + (long)(b * NPT + q) * KNN;

    float mx = 0.f, my = 0.f, mz = 0.f;
    #pragma unroll
    for (int k = 0; k < KNN; k++) {
        int j = ip[k];
        float nx = pb[j], ny = pb[NPT + j], nz = pb[2 * NPT + j];
        sx[k * GEO_BLK + tid] = nx; sy[k * GEO_BLK + tid] = ny; sz[k * GEO_BLK + tid] = nz;
        mx += nx; my += ny; mz += nz;
    }
    mx *= (1.f / KNN); my *= (1.f / KNN); mz *= (1.f / KNN);

    float cxx = 0.f, cxy = 0.f, cxz = 0.f, cyy = 0.f, cyz = 0.f, czz = 0.f;
    #pragma unroll
    for (int k = 0; k < KNN; k++) {
        float dx = sx[k * GEO_BLK + tid] - mx;
        float dy = sy[k * GEO_BLK + tid] - my;
        float dz = sz[k * GEO_BLK + tid] - mz;
        cxx = fmaf(dx, dx, cxx); cxy = fmaf(dx, dy, cxy); cxz = fmaf(dx, dz, cxz);
        cyy = fmaf(dy, dy, cyy); cyz = fmaf(dy, dz, cyz); czz = fmaf(dz, dz, czz);
    }
    const float invk = 1.f / KNN;
    cxx *= invk; cxy *= invk; cxz *= invk; cyy *= invk; cyz *= invk; czz *= invk;

    float q3 = (cxx + cyy + czz) * (1.f / 3.f);
    float p1 = cxy * cxy + cxz * cxz + cyz * cyz;
    float b00 = cxx - q3, b11 = cyy - q3, b22 = czz - q3;
    float p2 = b00 * b00 + b11 * b11 + b22 * b22 + 2.f * p1;
    float p = sqrtf(p2 * (1.f / 6.f));
    float e1, e2, e3;
    if (p < 1e-20f) { e1 = e2 = e3 = q3; }
    else {
        float inv = 1.f / p;
        float n00 = b00 * inv, n11 = b11 * inv, n22 = b22 * inv;
        float n01 = cxy * inv, n02 = cxz * inv, n12 = cyz * inv;
        float detB = n00 * (n11 * n22 - n12 * n12) - n01 * (n01 * n22 - n12 * n02)
                   + n02 * (n01 * n12 - n11 * n02);
        float r = 0.5f * detB;
        r = fminf(1.f, fmaxf(-1.f, r));
        float phi = acosf(r) * (1.f / 3.f);
        e1 = q3 + 2.f * p * cosf(phi);
        e3 = q3 + 2.f * p * cosf(phi + 2.09439510239f);
        e2 = 3.f * q3 - e1 - e3;
    }
    float l0 = e3, l1 = e2, l2 = e1;
    const float eps = 1e-8f;
    float geomf[5];
    float invl2 = 1.f / (l2 + eps);
    geomf[0] = (l2 - l1) * invl2;
    geomf[1] = (l1 - l0) * invl2;
    geomf[2] = l0 * invl2;
    geomf[3] = l0 / (l0 + l1 + l2 + eps);
    geomf[4] = (l2 - l0) * invl2;

    float dot = 0.f;
    #pragma unroll
    for (int o = 0; o < 16; o++) {
        float h = 0.f;
        #pragma unroll
        for (int f = 0; f < 5; f++) h = fmaf(sal_w1[o * 5 + f], geomf[f], h);
        float s = sal_g[o] * rsqrtf(sal_v[o] + 1e-5f);
        float t = sal_b[o] - sal_m[o] * s;
        h = leakyf(fmaf(h, s, t));
        dot = fmaf(h, sal_w2[o], dot);
    }
    float sal = 1.f / (1.f + expf(-(dot + sal_b2[0])));

    float* xr = xout + (long)(b * NPT + q) * 9;
    xr[0] = pb[q]; xr[1] = pb[NPT + q]; xr[2] = pb[2 * NPT + q];
    xr[3] = geomf[0]; xr[4] = geomf[1]; xr[5] = geomf[2]; xr[6] = geomf[3]; xr[7] = geomf[4];
    xr[8] = sal;
}

// ------- edge_conv1 precompute (CIN=9, cheap): per-thread dot products ------
template<int CIN>
__global__ void convpre_kernel(const float* __restrict__ xin,
                               const float* __restrict__ w,
                               const float* __restrict__ bng, const float* __restrict__ bnb,
                               const float* __restrict__ bnm, const float* __restrict__ bnv,
                               float* __restrict__ ys, float* __restrict__ zc)
{
    long T = (long)blockIdx.x * blockDim.x + threadIdx.x;
    int  o = (int)(T & 63);
    long p = T >> 6;
    if (p >= (long)BATCH * NPT) return;
    const float* xr = xin + p * CIN;
    const float* wd = w + (long)o * 2 * CIN;
    const float* wc = wd + CIN;
    float ad = 0.f, ac = 0.f;
    #pragma unroll
    for (int c = 0; c < CIN; c++) {
        float xv = xr[c];
        float a = wd[c];
        ad = fmaf(a, xv, ad);
        ac = fmaf(wc[c] - a, xv, ac);
    }
    float s = bng[o] * rsqrtf(bnv[o] + 1e-5f);
    float t = bnb[o] - bnm[o] * s;
    ys[p * 64 + o] = s * ad;
    zc[p * 64 + o] = fmaf(s, ac, t);
}

// ------- edge_conv2 precompute (CIN=64): smem-transposed weights, 4 pts/blk -
// Bitwise-identical arithmetic order to convpre_kernel<64> (FMA chain over c
// ascending; wc-wd subtracted before FMA) — x1-dependent knn ties preserved.
#define CP_PTS 4

__global__ void convpre64_kernel(const float* __restrict__ xin,
                                 const float* __restrict__ w,
                                 const float* __restrict__ bng, const float* __restrict__ bnb,
                                 const float* __restrict__ bnm, const float* __restrict__ bnv,
                                 float* __restrict__ ys, float* __restrict__ zc)
{
    __shared__ float A[64][64];       // wd transposed: A[c][o]
    __shared__ float Bm[64][64];      // (wc - wd) transposed
    __shared__ float xs[CP_PTS][64];

    const int tid = threadIdx.x;      // 256
    for (int i = tid; i < 64 * 64; i += 256) {
        int o = i >> 6, c = i & 63;
        float wd = w[o * 128 + c];
        float wc = w[o * 128 + 64 + c];
        A[c][o]  = wd;
        Bm[c][o] = wc - wd;
    }
    long pbase = (long)blockIdx.x * CP_PTS;
    xs[tid >> 6][tid & 63] = xin[pbase * 64 + tid];
    __syncthreads();

    const int pl = tid >> 6, o = tid & 63;
    const float* xr = xs[pl];
    float ad = 0.f, ac = 0.f;
    #pragma unroll
    for (int c = 0; c < 64; c++) {
        float xv = xr[c];
        ad = fmaf(A[c][o], xv, ad);
        ac = fmaf(Bm[c][o], xv, ac);
    }
    float s = bng[o] * rsqrtf(bnv[o] + 1e-5f);
    float t = bnb[o] - bnm[o] * s;
    long p = pbase + pl;
    ys[p * 64 + o] = s * ad;
    zc[p * 64 + o] = fmaf(s, ac, t);
}

// ------- edge_conv reduce: x_out[i] = leaky(max_k (ys[idx[i,k]] + zc[i])) ---
__global__ void edge_reduce_kernel(const float* __restrict__ ys, const float* __restrict__ zc,
                                   const int* __restrict__ idx, float* __restrict__ xout)
{
    long warp = ((long)blockIdx.x * blockDim.x + threadIdx.x) >> 5;
    int  lane = threadIdx.x & 31;
    if (warp >= (long)BATCH * NPT) return;
    const long bbase = (warp >> 13) << 13;
    int myj = idx[warp * KNN + lane];
    const float2* ysp = (const float2*)ys;
    float2 z = ((const float2*)zc)[warp * 32 + lane];
    float2 best = make_float2(-3.4e38f, -3.4e38f);
    #pragma unroll
    for (int k = 0; k < KNN; k++) {
        long j = bbase + __shfl_sync(0xffffffffu, myj, k);
        float2 v = ysp[j * 32 + lane];
        best.x = fmaxf(best.x, v.x + z.x);
        best.y = fmaxf(best.y, v.y + z.y);
    }
    best.x = leakyf(best.x);
    best.y = leakyf(best.y);
    ((float2*)xout)[warp * 32 + lane] = best;
}

// --------- classifier: h = leaky(bn(g@W1^T)); logits = h@W2^T + b2 ---------
#define CLS_GRID 256
#define CLS_PPB  ((BATCH*NPT)/CLS_GRID)

__global__ void cls_kernel(const float* __restrict__ x1, const float* __restrict__ x2,
                           const float* __restrict__ w1,
                           const float* __restrict__ bg, const float* __restrict__ bb,
                           const float* __restrict__ bm, const float* __restrict__ bv,
                           const float* __restrict__ w2, const float* __restrict__ b2,
                           float* __restrict__ out)
{
    extern __shared__ float sm[];
    float* WsT  = sm;
    float* Ts   = WsT + 128 * 256;
    float* W2s  = Ts + 256;
    float* gbuf = W2s + 512;
    float* red  = gbuf + 128;

    const int tid = threadIdx.x;
    {
        float s = bg[tid] * rsqrtf(bv[tid] + 1e-5f);
        Ts[tid] = bb[tid] - bm[tid] * s;
        for (int c = 0; c < 128; c++) WsT[c * 256 + tid] = w1[tid * 128 + c] * s;
        W2s[tid] = w2[tid]; W2s[256 + tid] = w2[256 + tid];
    }
    __syncthreads();

    for (int it = 0; it < CLS_PPB; it++) {
        long P = (long)blockIdx.x * CLS_PPB + it;
        if (tid < 64)       gbuf[tid] = x1[P * 64 + tid];
        else if (tid < 128) gbuf[tid] = x2[P * 64 + tid - 64];
        __syncthreads();

        float acc = Ts[tid];
        #pragma unroll 8
        for (int c = 0; c < 128; c++) acc = fmaf(WsT[c * 256 + tid], gbuf[c], acc);
        float h = leakyf(acc);
        float p0 = h * W2s[tid], p1 = h * W2s[256 + tid];
        #pragma unroll
        for (int off = 16; off; off >>= 1) {
            p0 += __shfl_down_sync(0xffffffffu, p0, off);
            p1 += __shfl_down_sync(0xffffffffu, p1, off);
        }
        int w = tid >> 5;
        if ((tid & 31) == 0) { red[w] = p0; red[8 + w] = p1; }
        __syncthreads();
        if (tid == 0) {
            float l0 = b2[0], l1 = b2[1];
            #pragma unroll
            for (int i = 0; i < 8; i++) { l0 += red[i]; l1 += red[8 + i]; }
            long bbatch = P / NPT, nn = P % NPT;
            out[bbatch * 2 * NPT + nn]       = l0;
            out[bbatch * 2 * NPT + NPT + nn] = l1;
        }
        __syncthreads();
    }
}

// ---------------------------------------------------------------------------
static void run_knn(const float* coords, int sn, int sc, long bstride, int* out_idx)
{
    bounds_kernel<<<BATCH, 256>>>(coords, sn, sc, bstride);
    cellcount_kernel<<<dim3(NPT / 256, BATCH), 256>>>(coords, sn, sc, bstride);
    scan_kernel<<<BATCH, 1024>>>();
    scatter_kernel<<<dim3(NPT / 256, BATCH), 256>>>(coords, sn, sc, bstride);
    tilestats_kernel<<<dim3(NTILE, BATCH), TPT>>>();
    knn_query_warp_kernel<<<dim3(NPT / QWARPS, BATCH), QWARPS * 32>>>(out_idx);
}

extern "C" void kernel_launch(void* const* d_in, const int* in_sizes, int n_in,
                              void* d_out, int out_size)
{
    const float* points  = (const float*)d_in[0];
    const float* sal_w1  = (const float*)d_in[1];
    const float* sal_g   = (const float*)d_in[2];
    const float* sal_b   = (const float*)d_in[3];
    const float* sal_m   = (const float*)d_in[4];
    const float* sal_v   = (const float*)d_in[5];
    const float* sal_w2  = (const float*)d_in[6];
    const float* sal_b2  = (const float*)d_in[7];
    const float* c1_w    = (const float*)d_in[8];
    const float* c1_g    = (const float*)d_in[9];
    const float* c1_b    = (const float*)d_in[10];
    const float* c1_m    = (const float*)d_in[11];
    const float* c1_v    = (const float*)d_in[12];
    const float* c2_w    = (const float*)d_in[13];
    const float* c2_g    = (const float*)d_in[14];
    const float* c2_b    = (const float*)d_in[15];
    const float* c2_m    = (const float*)d_in[16];
    const float* c2_v    = (const float*)d_in[17];
    const float* cls_w1  = (const float*)d_in[18];
    const float* cls_g   = (const float*)d_in[19];
    const float* cls_b   = (const float*)d_in[20];
    const float* cls_m   = (const float*)d_in[21];
    const float* cls_v   = (const float*)d_in[22];
    const float* cls_w2  = (const float*)d_in[23];
    const float* cls_b2  = (const float*)d_in[24];
    float* out = (float*)d_out;

    int*   idx1; cudaGetSymbolAddress((void**)&idx1, g_idx1);
    int*   idx2; cudaGetSymbolAddress((void**)&idx2, g_idx2);
    float* xf  ; cudaGetSymbolAddress((void**)&xf , g_x  );
    float* ys1 ; cudaGetSymbolAddress((void**)&ys1, g_ys1);
    float* zc1 ; cudaGetSymbolAddress((void**)&zc1, g_zc1);
    float* x1  ; cudaGetSymbolAddress((void**)&x1 , g_x1 );
    float* ys2 ; cudaGetSymbolAddress((void**)&ys2, g_ys2);
    float* zc2 ; cudaGetSymbolAddress((void**)&zc2, g_zc2);
    float* x2  ; cudaGetSymbolAddress((void**)&x2 , g_x2 );

    // 1) knn on raw points (layout (B,3,N): sn=1, sc=N)
    run_knn(points, 1, NPT, (long)3 * NPT, idx1);

    // 2) geometry + saliency -> x (B,N,9)
    geom_kernel<<<dim3(NPT / GEO_BLK, BATCH), GEO_BLK>>>(
        points, idx1, sal_w1, sal_g, sal_b, sal_m, sal_v, sal_w2, sal_b2, xf);

    // 3) edge_conv1 -> x1
    {
        long total = (long)BATCH * NPT * 64;
        convpre_kernel<9><<<(unsigned)(total / 128), 128>>>(xf, c1_w, c1_g, c1_b, c1_m, c1_v, ys1, zc1);
        edge_reduce_kernel<<<(BATCH * NPT) / 4, 128>>>(ys1, zc1, idx1, x1);
    }

    // 4) knn on x1[...,0:3] (layout (B,N,64): sn=64, sc=1)
    run_knn(x1, 64, 1, (long)NPT * 64, idx2);

    // 5) edge_conv2 -> x2 (smem-transposed convpre)
    {
        convpre64_kernel<<<(BATCH * NPT) / CP_PTS, 256>>>(x1, c2_w, c2_g, c2_b, c2_m, c2_v, ys2, zc2);
        edge_reduce_kernel<<<(BATCH * NPT) / 4, 128>>>(ys2, zc2, idx2, x2);
    }

    // 6) classifier
    {
        size_t smem = (128 * 256 + 256 + 512 + 128 + 16) * sizeof(float);
        cudaFuncSetAttribute(cls_kernel, cudaFuncAttributeMaxDynamicSharedMemorySize, (int)smem);
        cls_kernel<<<CLS_GRID, 256, smem>>>(x1, x2, cls_w1,
                                            cls_g, cls_b, cls_m, cls_v,
                                            cls_w2, cls_b2, out);
    }
}

// round 16
// speedup vs baseline: 3.0791x; 1.0794x over previous
#include <cuda_runtime.h>
#include <cuda_bf16.h>
#include <math.h>
#include <stdint.h>

#define BATCH 4
#define NPT   8192
#define KNN   32

#define GRES  16
#define NCELL (GRES*GRES*GRES)   // 4096
#define TPT   64                 // points per tile
#define NTILE (NPT/TPT)          // 128

// ---------------- scratch (__device__ globals; no allocations allowed) ------
__device__ int    g_idx1[BATCH*NPT*KNN];
__device__ int    g_idx2[BATCH*NPT*KNN];
__device__ float  g_x  [BATCH*NPT*9];
__device__ float  g_ys1[BATCH*NPT*64];
__device__ float  g_zc1[BATCH*NPT*64];
__device__ float  g_x1 [BATCH*NPT*64];
__device__ float  g_ys2[BATCH*NPT*64];
__device__ float  g_zc2[BATCH*NPT*64];
__device__ float  g_x2 [BATCH*NPT*64];
// knn spatial-structure scratch (reused by knn1 then knn2)
__device__ float4 g_pts4[BATCH*NPT];
__device__ int    g_pid [BATCH*NPT];
__device__ int    g_cellid[BATCH*NPT];
__device__ int    g_hist  [BATCH*NCELL];
__device__ int    g_cstart[BATCH*NCELL];
__device__ int    g_cursor[BATCH*NCELL];
__device__ float4 g_tlo4[BATCH*NTILE];          // tile lo.xyz, w = tile max xx
__device__ float4 g_thi4[BATCH*NTILE];          // tile hi.xyz
__device__ float  g_blo[BATCH*3];
__device__ float  g_bhi[BATCH*3];

__device__ __forceinline__ float leakyf(float x) { return x >= 0.f ? x : 0.2f * x; }

// sortable key helpers: lexicographic (score, -index), identical tie semantics
// to jax.lax.top_k (stable, lowest index wins).
__device__ __forceinline__ unsigned f32key(float s) {
    unsigned b = __float_as_uint(s);
    return (b & 0x80000000u) ? ~b : (b | 0x80000000u);
}
__device__ __forceinline__ float unkey(unsigned k) {
    unsigned b = (k & 0x80000000u) ? (k ^ 0x80000000u) : ~k;
    return __uint_as_float(b);
}

__device__ __forceinline__ int spread4(int v) {
    return (v & 1) | ((v & 2) << 2) | ((v & 4) << 4) | ((v & 8) << 6);
}
__device__ __forceinline__ int morton3(int x, int y, int z) {
    return spread4(x) | (spread4(y) << 1) | (spread4(z) << 2);
}

// exact fp32 score in the reference's association order -> 64-bit total key
__device__ __forceinline__ unsigned long long mk_key(const float4& q, float nxxq,
                                                     const float4& c, int cid)
{
    float dot   = __fmaf_rn(q.z, c.z, __fmaf_rn(q.y, c.y, __fmul_rn(q.x, c.x)));
    float inner = __fmul_rn(-2.f, dot);
    float s     = __fsub_rn(__fsub_rn(nxxq, inner), c.w);
    return ((unsigned long long)f32key(s) << 32) | (unsigned)(~cid);
}

// warp-wide bitonic sort ascending (one 64-bit key per lane)
__device__ __forceinline__ unsigned long long bitonic32_asc(unsigned long long v, int lane)
{
    #pragma unroll
    for (int k = 2; k <= 32; k <<= 1) {
        #pragma unroll
        for (int j = k >> 1; j > 0; j >>= 1) {
            unsigned long long o = __shfl_xor_sync(0xffffffffu, v, j);
            bool up    = ((lane & k) == 0);
            bool lower = ((lane & j) == 0);
            unsigned long long mn = v < o ? v : o;
            unsigned long long mx = v < o ? o : v;
            v = (up == lower) ? mn : mx;
        }
    }
    return v;
}

// register sorted list (ascending across lanes): replace min with k, re-sort.
// Requires k > v[lane0].
__device__ __forceinline__ unsigned long long sorted_insert(unsigned long long v,
                                                            unsigned long long k,
                                                            int lane)
{
    unsigned long long vnext = __shfl_down_sync(0xffffffffu, v, 1);
    if (lane == 31) vnext = 0xFFFFFFFFFFFFFFFFull;
    unsigned long long vmax = v > k ? v : k;
    return (vnext <= k) ? vnext : vmax;
}

// batch merge (WarpSelect pattern): v ascending, c arbitrary. Sort c DESC,
// elementwise max(v, c_desc) = top-32 of union (bitonic), then 5-stage
// half-cleaner -> ascending. Identical set to sequential replace-min inserts.
__device__ __forceinline__ unsigned long long merge_topk(unsigned long long v,
                                                         unsigned long long c,
                                                         int lane)
{
    // bitonic sort c descending
    #pragma unroll
    for (int k = 2; k <= 32; k <<= 1) {
        #pragma unroll
        for (int j = k >> 1; j > 0; j >>= 1) {
            unsigned long long o = __shfl_xor_sync(0xffffffffu, c, j);
            bool up    = ((lane & k) == 0);
            bool lower = ((lane & j) == 0);
            unsigned long long mn = c < o ? c : o;
            unsigned long long mx = c < o ? o : c;
            c = (up == lower) ? mx : mn;    // descending
        }
    }
    unsigned long long m = v > c ? v : c;   // bitonic, holds top-32 of union
    #pragma unroll
    for (int j = 16; j > 0; j >>= 1) {      // half-cleaner -> ascending
        unsigned long long o = __shfl_xor_sync(0xffffffffu, m, j);
        bool lower = ((lane & j) == 0);
        unsigned long long mn = m < o ? m : o;
        unsigned long long mx = m < o ? o : m;
        m = lower ? mn : mx;
    }
    return m;
}

// ---------------- stage A: per-batch coordinate bounds (+ zero counters) ----
__global__ void bounds_kernel(const float* __restrict__ coords, int sn, int sc,
                              long bstride)
{
    __shared__ float slo[3][256], shi[3][256];
    const int b = blockIdx.x, tid = threadIdx.x;
    const float* cb = coords + (long)b * bstride;
    float l0 = 3.4e38f, l1 = 3.4e38f, l2 = 3.4e38f;
    float h0 = -3.4e38f, h1 = -3.4e38f, h2 = -3.4e38f;
    for (int n = tid; n < NPT; n += 256) {
        float x = cb[(long)n * sn], y = cb[(long)n * sn + sc], z = cb[(long)n * sn + 2 * sc];
        l0 = fminf(l0, x); h0 = fmaxf(h0, x);
        l1 = fminf(l1, y); h1 = fmaxf(h1, y);
        l2 = fminf(l2, z); h2 = fmaxf(h2, z);
    }
    slo[0][tid] = l0; slo[1][tid] = l1; slo[2][tid] = l2;
    shi[0][tid] = h0; shi[1][tid] = h1; shi[2][tid] = h2;
    __syncthreads();
    for (int off = 128; off; off >>= 1) {
        if (tid < off) {
            #pragma unroll
            for (int a = 0; a < 3; a++) {
                slo[a][tid] = fminf(slo[a][tid], slo[a][tid + off]);
                shi[a][tid] = fmaxf(shi[a][tid], shi[a][tid + off]);
            }
        }
        __syncthreads();
    }
    if (tid < 3) { g_blo[b * 3 + tid] = slo[tid][0]; g_bhi[b * 3 + tid] = shi[tid][0]; }
    for (int i = tid; i < NCELL; i += 256) {
        g_hist[b * NCELL + i] = 0;
        g_cursor[b * NCELL + i] = 0;
    }
}

// ---------------- stage B: cell ids + histogram -----------------------------
__global__ void cellcount_kernel(const float* __restrict__ coords, int sn, int sc,
                                 long bstride)
{
    const int b = blockIdx.y;
    const int n = blockIdx.x * 256 + threadIdx.x;
    const float* cb = coords + (long)b * bstride;
    float x = cb[(long)n * sn], y = cb[(long)n * sn + sc], z = cb[(long)n * sn + 2 * sc];
    float lo0 = g_blo[b * 3], lo1 = g_blo[b * 3 + 1], lo2 = g_blo[b * 3 + 2];
    float s0 = (float)GRES / fmaxf(g_bhi[b * 3]     - lo0, 1e-30f);
    float s1 = (float)GRES / fmaxf(g_bhi[b * 3 + 1] - lo1, 1e-30f);
    float s2 = (float)GRES / fmaxf(g_bhi[b * 3 + 2] - lo2, 1e-30f);
    int cx = min(GRES - 1, max(0, (int)((x - lo0) * s0)));
    int cy = min(GRES - 1, max(0, (int)((y - lo1) * s1)));
    int cz = min(GRES - 1, max(0, (int)((z - lo2) * s2)));
    int cell = morton3(cx, cy, cz);
    g_cellid[b * NPT + n] = cell;
    atomicAdd(&g_hist[b * NCELL + cell], 1);
}

// ---------------- stage C: per-batch exclusive scan over 4096 cells ---------
__global__ void scan_kernel()
{
    __shared__ int ss[1024];
    const int b = blockIdx.x, tid = threadIdx.x;
    int v[4]; int base = tid * 4; int s = 0;
    #pragma unroll
    for (int i = 0; i < 4; i++) { v[i] = g_hist[b * NCELL + base + i]; s += v[i]; }
    ss[tid] = s;
    __syncthreads();
    for (int off = 1; off < 1024; off <<= 1) {
        int t = (tid >= off) ? ss[tid - off] : 0;
        __syncthreads();
        ss[tid] += t;
        __syncthreads();
    }
    int ex = ss[tid] - s;
    #pragma unroll
    for (int i = 0; i < 4; i++) { g_cstart[b * NCELL + base + i] = ex; ex += v[i]; }
}

// ---------------- stage D: scatter into Morton order ------------------------
__global__ void scatter_kernel(const float* __restrict__ coords, int sn, int sc,
                               long bstride)
{
    const int b = blockIdx.y;
    const int n = blockIdx.x * 256 + threadIdx.x;
    const float* cb = coords + (long)b * bstride;
    float x = cb[(long)n * sn], y = cb[(long)n * sn + sc], z = cb[(long)n * sn + 2 * sc];
    int cell = g_cellid[b * NPT + n];
    int pos = g_cstart[b * NCELL + cell] + atomicAdd(&g_cursor[b * NCELL + cell], 1);
    float xx = __fadd_rn(__fadd_rn(__fmul_rn(x, x), __fmul_rn(y, y)), __fmul_rn(z, z));
    g_pts4[b * NPT + pos] = make_float4(x, y, z, xx);
    g_pid[b * NPT + pos] = n;
}

// ---------------- stage E: per-tile AABB + max xx ---------------------------
__global__ void tilestats_kernel()
{
    __shared__ float r[7][TPT];
    const int b = blockIdx.y, t = blockIdx.x, tid = threadIdx.x;
    float4 p = g_pts4[b * NPT + t * TPT + tid];
    r[0][tid] = p.x; r[1][tid] = p.y; r[2][tid] = p.z;
    r[3][tid] = p.x; r[4][tid] = p.y; r[5][tid] = p.z;
    r[6][tid] = p.w;
    __syncthreads();
    for (int off = TPT / 2; off; off >>= 1) {
        if (tid < off) {
            r[0][tid] = fminf(r[0][tid], r[0][tid + off]);
            r[1][tid] = fminf(r[1][tid], r[1][tid + off]);
            r[2][tid] = fminf(r[2][tid], r[2][tid + off]);
            r[3][tid] = fmaxf(r[3][tid], r[3][tid + off]);
            r[4][tid] = fmaxf(r[4][tid], r[4][tid + off]);
            r[5][tid] = fmaxf(r[5][tid], r[5][tid + off]);
            r[6][tid] = fmaxf(r[6][tid], r[6][tid + off]);
        }
        __syncthreads();
    }
    if (tid == 0) {
        g_tlo4[b * NTILE + t] = make_float4(r[0][0], r[1][0], r[2][0], r[6][0]);
        g_thi4[b * NTILE + t] = make_float4(r[3][0], r[4][0], r[5][0], 0.f);
    }
}

// ---------------- stage F: warp-per-query pruned exact KNN ------------------
// Register sorted top-32; batch updates via bitonic merge when >=6 candidates
// pass, else sequential sorted_insert. Survivors processed outward from t0 so
// the root tightens early and the per-tile re-check culls far tiles.
#define QWARPS 8
#define MERGE_THRESH 6

__global__ void knn_query_warp_kernel(int* __restrict__ out_idx)
{
    __shared__ float4 s_tA[NTILE], s_tB[NTILE];
    __shared__ unsigned char s_surv[QWARPS][NTILE];

    const int lane = threadIdx.x & 31;
    const int w    = threadIdx.x >> 5;
    const int b    = blockIdx.y;
    const int p    = blockIdx.x * QWARPS + w;   // query position in sorted order

    for (int i = threadIdx.x; i < NTILE; i += QWARPS * 32) {
        s_tA[i] = g_tlo4[b * NTILE + i];
        s_tB[i] = g_thi4[b * NTILE + i];
    }
    __syncthreads();

    const float4 q = g_pts4[b * NPT + p];
    const int qid = g_pid[b * NPT + p];
    const float nxxq = -q.w;
    const int t0 = p / TPT;

    // ---- seed from own tile: top-32 of 64 via sort + merge ----
    const int base0 = b * NPT + t0 * TPT;
    float4 cA = __ldg(&g_pts4[base0 + lane]);
    unsigned long long keyA = mk_key(q, nxxq, cA, __ldg(&g_pid[base0 + lane]));
    float4 cB = __ldg(&g_pts4[base0 + 32 + lane]);
    unsigned long long keyB = mk_key(q, nxxq, cB, __ldg(&g_pid[base0 + 32 + lane]));

    unsigned long long v = bitonic32_asc(keyA, lane);
    v = merge_topk(v, keyB, lane);
    unsigned long long rootk = __shfl_sync(0xffffffffu, v, 0);

    // ---- cull all tiles 32-wide, build survivor list (ascending t) ----
    int nsurv = 0, nbelow = 0;
    {
        float root_s = unkey((unsigned)(rootk >> 32));
        #pragma unroll
        for (int r = 0; r < NTILE / 32; r++) {
            int t = r * 32 + lane;
            float4 tA = s_tA[t], tB = s_tB[t];
            float d2 = 0.f;
            float d = fmaxf(fmaxf(tA.x - q.x, q.x - tB.x), 0.f); d2 = fmaf(d, d, d2);
            d = fmaxf(fmaxf(tA.y - q.y, q.y - tB.y), 0.f);       d2 = fmaf(d, d, d2);
            d = fmaxf(fmaxf(tA.z - q.z, q.z - tB.z), 0.f);       d2 = fmaf(d, d, d2);
            float margin = fmaf(2e-6f, q.w + tA.w, 1e-6f);
            bool surv = (t != t0) && (d2 * 0.999999f <= -root_s + margin);
            unsigned m = __ballot_sync(0xffffffffu, surv);
            int mypos = nsurv + __popc(m & ((1u << lane) - 1));
            if (surv) s_surv[w][mypos] = (unsigned char)t;
            nsurv += __popc(m);
            nbelow += __popc(m & __ballot_sync(0xffffffffu, t < t0));
        }
    }
    __syncwarp();

    // ---- scan surviving tiles outward from t0 (two-pointer) ----
    int lo = nbelow - 1, hi = nbelow;
    for (int i = 0; i < nsurv; i++) {
        int t;
        bool use_hi = ((i & 1) == 0) ? (hi < nsurv) : (lo < 0);
        if (use_hi) t = s_surv[w][hi++];
        else        t = s_surv[w][lo--];

        // re-check with current (tighter) root — uniform branch
        float4 tA = s_tA[t], tB = s_tB[t];
        float root_s = unkey((unsigned)(rootk >> 32));
        float d2 = 0.f;
        {
            float d = fmaxf(fmaxf(tA.x - q.x, q.x - tB.x), 0.f); d2 = fmaf(d, d, d2);
            d = fmaxf(fmaxf(tA.y - q.y, q.y - tB.y), 0.f);       d2 = fmaf(d, d, d2);
            d = fmaxf(fmaxf(tA.z - q.z, q.z - tB.z), 0.f);       d2 = fmaf(d, d, d2);
        }
        float margin = fmaf(2e-6f, q.w + tA.w, 1e-6f);
        if (d2 * 0.999999f > -root_s + margin) continue;

        #pragma unroll
        for (int half = 0; half < 2; half++) {
            int ci = b * NPT + t * TPT + half * 32 + lane;
            float4 c = __ldg(&g_pts4[ci]);
            unsigned long long key = mk_key(q, nxxq, c, __ldg(&g_pid[ci]));
            unsigned mask = __ballot_sync(0xffffffffu, key > rootk);
            int cnt = __popc(mask);
            if (cnt == 0) continue;
            if (cnt >= MERGE_THRESH) {
                v = merge_topk(v, key, lane);
                rootk = __shfl_sync(0xffffffffu, v, 0);
            } else {
                while (mask) {
                    int src = __ffs(mask) - 1; mask &= mask - 1;
                    unsigned long long k = __shfl_sync(0xffffffffu, key, src);
                    if (k > rootk) {
                        v = sorted_insert(v, k, lane);
                        rootk = __shfl_sync(0xffffffffu, v, 0);
                    }
                }
            }
        }
    }

    // ---- v sorted ascending; write in top_k (desc) order ----
    int* op = out_idx + (long)(b * NPT + qid) * KNN;
    op[31 - lane] = (int)(~(unsigned)v);
}

// --------- geometry (cov eig features, fp32) + saliency + x ----------------
#define GEO_BLK 64

__global__ void geom_kernel(const float* __restrict__ points,
                            const int*   __restrict__ idx,
                            const float* __restrict__ sal_w1,
                            const float* __restrict__ sal_g, const float* __restrict__ sal_b,
                            const float* __restrict__ sal_m, const float* __restrict__ sal_v,
                            const float* __restrict__ sal_w2, const float* __restrict__ sal_b2,
                            float* __restrict__ xout)
{
    __shared__ float sx[KNN * GEO_BLK], sy[KNN * GEO_BLK], sz[KNN * GEO_BLK];
    const int tid = threadIdx.x;
    const int b   = blockIdx.y;
    const int q   = blockIdx.x * GEO_BLK + tid;
    const float* pb = points + (long)b * 3 * NPT;
    const int* ip = idx + (long)(b * NPT + q) * KNN;

    float mx = 0.f, my = 0.f, mz = 0.f;
    #pragma unroll
    for (int k = 0; k < KNN; k++) {
        int j = ip[k];
        float nx = pb[j], ny = pb[NPT + j], nz = pb[2 * NPT + j];
        sx[k * GEO_BLK + tid] = nx; sy[k * GEO_BLK + tid] = ny; sz[k * GEO_BLK + tid] = nz;
        mx += nx; my += ny; mz += nz;
    }
    mx *= (1.f / KNN); my *= (1.f / KNN); mz *= (1.f / KNN);

    float cxx = 0.f, cxy = 0.f, cxz = 0.f, cyy = 0.f, cyz = 0.f, czz = 0.f;
    #pragma unroll
    for (int k = 0; k < KNN; k++) {
        float dx = sx[k * GEO_BLK + tid] - mx;
        float dy = sy[k * GEO_BLK + tid] - my;
        float dz = sz[k * GEO_BLK + tid] - mz;
        cxx = fmaf(dx, dx, cxx); cxy = fmaf(dx, dy, cxy); cxz = fmaf(dx, dz, cxz);
        cyy = fmaf(dy, dy, cyy); cyz = fmaf(dy, dz, cyz); czz = fmaf(dz, dz, czz);
    }
    const float invk = 1.f / KNN;
    cxx *= invk; cxy *= invk; cxz *= invk; cyy *= invk; cyz *= invk; czz *= invk;

    float q3 = (cxx + cyy + czz) * (1.f / 3.f);
    float p1 = cxy * cxy + cxz * cxz + cyz * cyz;
    float b00 = cxx - q3, b11 = cyy - q3, b22 = czz - q3;
    float p2 = b00 * b00 + b11 * b11 + b22 * b22 + 2.f * p1;
    float p = sqrtf(p2 * (1.f / 6.f));
    float e1, e2, e3;
    if (p < 1e-20f) { e1 = e2 = e3 = q3; }
    else {
        float inv = 1.f / p;
        float n00 = b00 * inv, n11 = b11 * inv, n22 = b22 * inv;
        float n01 = cxy * inv, n02 = cxz * inv, n12 = cyz * inv;
        float detB = n00 * (n11 * n22 - n12 * n12) - n01 * (n01 * n22 - n12 * n02)
                   + n02 * (n01 * n12 - n11 * n02);
        float r = 0.5f * detB;
        r = fminf(1.f, fmaxf(-1.f, r));
        float phi = acosf(r) * (1.f / 3.f);
        e1 = q3 + 2.f * p * cosf(phi);
        e3 = q3 + 2.f * p * cosf(phi + 2.09439510239f);
        e2 = 3.f * q3 - e1 - e3;
    }
    float l0 = e3, l1 = e2, l2 = e1;
    const float eps = 1e-8f;
    float geomf[5];
    float invl2 = 1.f / (l2 + eps);
    geomf[0] = (l2 - l1) * invl2;
    geomf[1] = (l1 - l0) * invl2;
    geomf[2] = l0 * invl2;
    geomf[3] = l0 / (l0 + l1 + l2 + eps);
    geomf[4] = (l2 - l0) * invl2;

    float dot = 0.f;
    #pragma unroll
    for (int o = 0; o < 16; o++) {
        float h = 0.f;
        #pragma unroll
        for (int f = 0; f < 5; f++) h = fmaf(sal_w1[o * 5 + f], geomf[f], h);
        float s = sal_g[o] * rsqrtf(sal_v[o] + 1e-5f);
        float t = sal_b[o] - sal_m[o] * s;
        h = leakyf(fmaf(h, s, t));
        dot = fmaf(h, sal_w2[o], dot);
    }
    float sal = 1.f / (1.f + expf(-(dot + sal_b2[0])));

    float* xr = xout + (long)(b * NPT + q) * 9;
    xr[0] = pb[q]; xr[1] = pb[NPT + q]; xr[2] = pb[2 * NPT + q];
    xr[3] = geomf[0]; xr[4] = geomf[1]; xr[5] = geomf[2]; xr[6] = geomf[3]; xr[7] = geomf[4];
    xr[8] = sal;
}

// ------- edge_conv1 precompute (CIN=9, cheap): per-thread dot products ------
template<int CIN>
__global__ void convpre_kernel(const float* __restrict__ xin,
                               const float* __restrict__ w,
                               const float* __restrict__ bng, const float* __restrict__ bnb,
                               const float* __restrict__ bnm, const float* __restrict__ bnv,
                               float* __restrict__ ys, float* __restrict__ zc)
{
    long T = (long)blockIdx.x * blockDim.x + threadIdx.x;
    int  o = (int)(T & 63);
    long p = T >> 6;
    if (p >= (long)BATCH * NPT) return;
    const float* xr = xin + p * CIN;
    const float* wd = w + (long)o * 2 * CIN;
    const float* wc = wd + CIN;
    float ad = 0.f, ac = 0.f;
    #pragma unroll
    for (int c = 0; c < CIN; c++) {
        float xv = xr[c];
        float a = wd[c];
        ad = fmaf(a, xv, ad);
        ac = fmaf(wc[c] - a, xv, ac);
    }
    float s = bng[o] * rsqrtf(bnv[o] + 1e-5f);
    float t = bnb[o] - bnm[o] * s;
    ys[p * 64 + o] = s * ad;
    zc[p * 64 + o] = fmaf(s, ac, t);
}

// ------- edge_conv2 precompute (CIN=64): smem-transposed weights, 4 pts/blk -
#define CP_PTS 4

__global__ void convpre64_kernel(const float* __restrict__ xin,
                                 const float* __restrict__ w,
                                 const float* __restrict__ bng, const float* __restrict__ bnb,
                                 const float* __restrict__ bnm, const float* __restrict__ bnv,
                                 float* __restrict__ ys, float* __restrict__ zc)
{
    __shared__ float A[64][64];       // wd transposed: A[c][o]
    __shared__ float Bm[64][64];      // (wc - wd) transposed
    __shared__ float xs[CP_PTS][64];

    const int tid = threadIdx.x;      // 256
    for (int i = tid; i < 64 * 64; i += 256) {
        int o = i >> 6, c = i & 63;
        float wd = w[o * 128 + c];
        float wc = w[o * 128 + 64 + c];
        A[c][o]  = wd;
        Bm[c][o] = wc - wd;
    }
    long pbase = (long)blockIdx.x * CP_PTS;
    xs[tid >> 6][tid & 63] = xin[pbase * 64 + tid];
    __syncthreads();

    const int pl = tid >> 6, o = tid & 63;
    const float* xr = xs[pl];
    float ad = 0.f, ac = 0.f;
    #pragma unroll
    for (int c = 0; c < 64; c++) {
        float xv = xr[c];
        ad = fmaf(A[c][o], xv, ad);
        ac = fmaf(Bm[c][o], xv, ac);
    }
    float s = bng[o] * rsqrtf(bnv[o] + 1e-5f);
    float t = bnb[o] - bnm[o] * s;
    long p = pbase + pl;
    ys[p * 64 + o] = s * ad;
    zc[p * 64 + o] = fmaf(s, ac, t);
}

// ------- edge_conv reduce: x_out[i] = leaky(max_k (ys[idx[i,k]] + zc[i])) ---
__global__ void edge_reduce_kernel(const float* __restrict__ ys, const float* __restrict__ zc,
                                   const int* __restrict__ idx, float* __restrict__ xout)
{
    long warp = ((long)blockIdx.x * blockDim.x + threadIdx.x) >> 5;
    int  lane = threadIdx.x & 31;
    if (warp >= (long)BATCH * NPT) return;
    const long bbase = (warp >> 13) << 13;
    int myj = idx[warp * KNN + lane];
    const float2* ysp = (const float2*)ys;
    float2 z = ((const float2*)zc)[warp * 32 + lane];
    float2 best = make_float2(-3.4e38f, -3.4e38f);
    #pragma unroll
    for (int k = 0; k < KNN; k++) {
        long j = bbase + __shfl_sync(0xffffffffu, myj, k);
        float2 v = ysp[j * 32 + lane];
        best.x = fmaxf(best.x, v.x + z.x);
        best.y = fmaxf(best.y, v.y + z.y);
    }
    best.x = leakyf(best.x);
    best.y = leakyf(best.y);
    ((float2*)xout)[warp * 32 + lane] = best;
}

// --------- classifier: h = leaky(bn(g@W1^T)); logits = h@W2^T + b2 ---------
#define CLS_GRID 256
#define CLS_PPB  ((BATCH*NPT)/CLS_GRID)

__global__ void cls_kernel(const float* __restrict__ x1, const float* __restrict__ x2,
                           const float* __restrict__ w1,
                           const float* __restrict__ bg, const float* __restrict__ bb,
                           const float* __restrict__ bm, const float* __restrict__ bv,
                           const float* __restrict__ w2, const float* __restrict__ b2,
                           float* __restrict__ out)
{
    extern __shared__ float sm[];
    float* WsT  = sm;
    float* Ts   = WsT + 128 * 256;
    float* W2s  = Ts + 256;
    float* gbuf = W2s + 512;
    float* red  = gbuf + 128;

    const int tid = threadIdx.x;
    {
        float s = bg[tid] * rsqrtf(bv[tid] + 1e-5f);
        Ts[tid] = bb[tid] - bm[tid] * s;
        for (int c = 0; c < 128; c++) WsT[c * 256 + tid] = w1[tid * 128 + c] * s;
        W2s[tid] = w2[tid]; W2s[256 + tid] = w2[256 + tid];
    }
    __syncthreads();

    for (int it = 0; it < CLS_PPB; it++) {
        long P = (long)blockIdx.x * CLS_PPB + it;
        if (tid < 64)       gbuf[tid] = x1[P * 64 + tid];
        else if (tid < 128) gbuf[tid] = x2[P * 64 + tid - 64];
        __syncthreads();

        float acc = Ts[tid];
        #pragma unroll 8
        for (int c = 0; c < 128; c++) acc = fmaf(WsT[c * 256 + tid], gbuf[c], acc);
        float h = leakyf(acc);
        float p0 = h * W2s[tid], p1 = h * W2s[256 + tid];
        #pragma unroll
        for (int off = 16; off; off >>= 1) {
            p0 += __shfl_down_sync(0xffffffffu, p0, off);
            p1 += __shfl_down_sync(0xffffffffu, p1, off);
        }
        int w = tid >> 5;
        if ((tid & 31) == 0) { red[w] = p0; red[8 + w] = p1; }
        __syncthreads();
        if (tid == 0) {
            float l0 = b2[0], l1 = b2[1];
            #pragma unroll
            for (int i = 0; i < 8; i++) { l0 += red[i]; l1 += red[8 + i]; }
            long bbatch = P / NPT, nn = P % NPT;
            out[bbatch * 2 * NPT + nn]       = l0;
            out[bbatch * 2 * NPT + NPT + nn] = l1;
        }
        __syncthreads();
    }
}

// ---------------------------------------------------------------------------
static void run_knn(const float* coords, int sn, int sc, long bstride, int* out_idx)
{
    bounds_kernel<<<BATCH, 256>>>(coords, sn, sc, bstride);
    cellcount_kernel<<<dim3(NPT / 256, BATCH), 256>>>(coords, sn, sc, bstride);
    scan_kernel<<<BATCH, 1024>>>();
    scatter_kernel<<<dim3(NPT / 256, BATCH), 256>>>(coords, sn, sc, bstride);
    tilestats_kernel<<<dim3(NTILE, BATCH), TPT>>>();
    knn_query_warp_kernel<<<dim3(NPT / QWARPS, BATCH), QWARPS * 32>>>(out_idx);
}

extern "C" void kernel_launch(void* const* d_in, const int* in_sizes, int n_in,
                              void* d_out, int out_size)
{
    const float* points  = (const float*)d_in[0];
    const float* sal_w1  = (const float*)d_in[1];
    const float* sal_g   = (const float*)d_in[2];
    const float* sal_b   = (const float*)d_in[3];
    const float* sal_m   = (const float*)d_in[4];
    const float* sal_v   = (const float*)d_in[5];
    const float* sal_w2  = (const float*)d_in[6];
    const float* sal_b2  = (const float*)d_in[7];
    const float* c1_w    = (const float*)d_in[8];
    const float* c1_g    = (const float*)d_in[9];
    const float* c1_b    = (const float*)d_in[10];
    const float* c1_m    = (const float*)d_in[11];
    const float* c1_v    = (const float*)d_in[12];
    const float* c2_w    = (const float*)d_in[13];
    const float* c2_g    = (const float*)d_in[14];
    const float* c2_b    = (const float*)d_in[15];
    const float* c2_m    = (const float*)d_in[16];
    const float* c2_v    = (const float*)d_in[17];
    const float* cls_w1  = (const float*)d_in[18];
    const float* cls_g   = (const float*)d_in[19];
    const float* cls_b   = (const float*)d_in[20];
    const float* cls_m   = (const float*)d_in[21];
    const float* cls_v   = (const float*)d_in[22];
    const float* cls_w2  = (const float*)d_in[23];
    const float* cls_b2  = (const float*)d_in[24];
    float* out = (float*)d_out;

    int*   idx1; cudaGetSymbolAddress((void**)&idx1, g_idx1);
    int*   idx2; cudaGetSymbolAddress((void**)&idx2, g_idx2);
    float* xf  ; cudaGetSymbolAddress((void**)&xf , g_x  );
    float* ys1 ; cudaGetSymbolAddress((void**)&ys1, g_ys1);
    float* zc1 ; cudaGetSymbolAddress((void**)&zc1, g_zc1);
    float* x1  ; cudaGetSymbolAddress((void**)&x1 , g_x1 );
    float* ys2 ; cudaGetSymbolAddress((void**)&ys2, g_ys2);
    float* zc2 ; cudaGetSymbolAddress((void**)&zc2, g_zc2);
    float* x2  ; cudaGetSymbolAddress((void**)&x2 , g_x2 );

    // 1) knn on raw points (layout (B,3,N): sn=1, sc=N)
    run_knn(points, 1, NPT, (long)3 * NPT, idx1);

    // 2) geometry + saliency -> x (B,N,9)
    geom_kernel<<<dim3(NPT / GEO_BLK, BATCH), GEO_BLK>>>(
        points, idx1, sal_w1, sal_g, sal_b, sal_m, sal_v, sal_w2, sal_b2, xf);

    // 3) edge_conv1 -> x1
    {
        long total = (long)BATCH * NPT * 64;
        convpre_kernel<9><<<(unsigned)(total / 128), 128>>>(xf, c1_w, c1_g, c1_b, c1_m, c1_v, ys1, zc1);
        edge_reduce_kernel<<<(BATCH * NPT) / 4, 128>>>(ys1, zc1, idx1, x1);
    }

    // 4) knn on x1[...,0:3] (layout (B,N,64): sn=64, sc=1)
    run_knn(x1, 64, 1, (long)NPT * 64, idx2);

    // 5) edge_conv2 -> x2 (smem-transposed convpre)
    {
        convpre64_kernel<<<(BATCH * NPT) / CP_PTS, 256>>>(x1, c2_w, c2_g, c2_b, c2_m, c2_v, ys2, zc2);
        edge_reduce_kernel<<<(BATCH * NPT) / 4, 128>>>(ys2, zc2, idx2, x2);
    }

    // 6) classifier
    {
        size_t smem = (128 * 256 + 256 + 512 + 128 + 16) * sizeof(float);
        cudaFuncSetAttribute(cls_kernel, cudaFuncAttributeMaxDynamicSharedMemorySize, (int)smem);
        cls_kernel<<<CLS_GRID, 256, smem>>>(x1, x2, cls_w1,
                                            cls_g, cls_b, cls_m, cls_v,
                                            cls_w2, cls_b2, out);
    }
}

// round 17
// speedup vs baseline: 3.6099x; 1.1724x over previous
#include <cuda_runtime.h>
#include <cuda_bf16.h>
#include <math.h>
#include <stdint.h>

#define BATCH 4
#define NPT   8192
#define KNN   32

#define GRES  16
#define NCELL (GRES*GRES*GRES)   // 4096
#define TPT   64                 // points per tile
#define NTILE (NPT/TPT)          // 128

// ---------------- scratch (__device__ globals; no allocations allowed) ------
__device__ int    g_idx1[BATCH*NPT*KNN];
__device__ int    g_idx2[BATCH*NPT*KNN];
__device__ float  g_x  [BATCH*NPT*9];
__device__ float  g_ys1[BATCH*NPT*64];
__device__ float  g_zc1[BATCH*NPT*64];
__device__ float  g_x1 [BATCH*NPT*64];
__device__ float  g_ys2[BATCH*NPT*64];
__device__ float  g_zc2[BATCH*NPT*64];
__device__ float  g_x2 [BATCH*NPT*64];
// knn spatial-structure scratch (reused by knn1 then knn2)
__device__ float4 g_pts4[BATCH*NPT];
__device__ int    g_pid [BATCH*NPT];
__device__ int    g_cellid[BATCH*NPT];
__device__ int    g_hist  [BATCH*NCELL];
__device__ int    g_cstart[BATCH*NCELL];
__device__ int    g_cursor[BATCH*NCELL];
__device__ float4 g_tlo4[BATCH*NTILE];          // tile lo.xyz, w = tile max xx
__device__ float4 g_thi4[BATCH*NTILE];          // tile hi.xyz
__device__ float  g_blo[BATCH*3];
__device__ float  g_bhi[BATCH*3];

__device__ __forceinline__ float leakyf(float x) { return x >= 0.f ? x : 0.2f * x; }

// sortable key helpers: lexicographic (score, -index), identical tie semantics
// to jax.lax.top_k (stable, lowest index wins).
__device__ __forceinline__ unsigned f32key(float s) {
    unsigned b = __float_as_uint(s);
    return (b & 0x80000000u) ? ~b : (b | 0x80000000u);
}
__device__ __forceinline__ float unkey(unsigned k) {
    unsigned b = (k & 0x80000000u) ? (k ^ 0x80000000u) : ~k;
    return __uint_as_float(b);
}

__device__ __forceinline__ int spread4(int v) {
    return (v & 1) | ((v & 2) << 2) | ((v & 4) << 4) | ((v & 8) << 6);
}
__device__ __forceinline__ int morton3(int x, int y, int z) {
    return spread4(x) | (spread4(y) << 1) | (spread4(z) << 2);
}

// exact fp32 score in the reference's association order -> 64-bit total key
__device__ __forceinline__ unsigned long long mk_key(const float4& q, float nxxq,
                                                     const float4& c, int cid)
{
    float dot   = __fmaf_rn(q.z, c.z, __fmaf_rn(q.y, c.y, __fmul_rn(q.x, c.x)));
    float inner = __fmul_rn(-2.f, dot);
    float s     = __fsub_rn(__fsub_rn(nxxq, inner), c.w);
    return ((unsigned long long)f32key(s) << 32) | (unsigned)(~cid);
}

// warp-wide bitonic sort ascending (one 64-bit key per lane)
__device__ __forceinline__ unsigned long long bitonic32_asc(unsigned long long v, int lane)
{
    #pragma unroll
    for (int k = 2; k <= 32; k <<= 1) {
        #pragma unroll
        for (int j = k >> 1; j > 0; j >>= 1) {
            unsigned long long o = __shfl_xor_sync(0xffffffffu, v, j);
            bool up    = ((lane & k) == 0);
            bool lower = ((lane & j) == 0);
            unsigned long long mn = v < o ? v : o;
            unsigned long long mx = v < o ? o : v;
            v = (up == lower) ? mn : mx;
        }
    }
    return v;
}

// register sorted list (ascending across lanes): replace min with k, re-sort.
// Requires k > v[lane0].
__device__ __forceinline__ unsigned long long sorted_insert(unsigned long long v,
                                                            unsigned long long k,
                                                            int lane)
{
    unsigned long long vnext = __shfl_down_sync(0xffffffffu, v, 1);
    if (lane == 31) vnext = 0xFFFFFFFFFFFFFFFFull;
    unsigned long long vmax = v > k ? v : k;
    return (vnext <= k) ? vnext : vmax;
}

// batch merge (WarpSelect pattern): v ascending, c arbitrary. Sort c DESC,
// elementwise max(v, c_desc) = top-32 of union (bitonic), then half-cleaner.
__device__ __forceinline__ unsigned long long merge_topk(unsigned long long v,
                                                         unsigned long long c,
                                                         int lane)
{
    #pragma unroll
    for (int k = 2; k <= 32; k <<= 1) {
        #pragma unroll
        for (int j = k >> 1; j > 0; j >>= 1) {
            unsigned long long o = __shfl_xor_sync(0xffffffffu, c, j);
            bool up    = ((lane & k) == 0);
            bool lower = ((lane & j) == 0);
            unsigned long long mn = c < o ? c : o;
            unsigned long long mx = c < o ? o : c;
            c = (up == lower) ? mx : mn;    // descending
        }
    }
    unsigned long long m = v > c ? v : c;
    #pragma unroll
    for (int j = 16; j > 0; j >>= 1) {
        unsigned long long o = __shfl_xor_sync(0xffffffffu, m, j);
        bool lower = ((lane & j) == 0);
        unsigned long long mn = m < o ? m : o;
        unsigned long long mx = m < o ? o : m;
        m = lower ? mn : mx;
    }
    return m;
}

// ---------------- stage A: per-batch coordinate bounds (+ zero counters) ----
__global__ void bounds_kernel(const float* __restrict__ coords, int sn, int sc,
                              long bstride)
{
    __shared__ float slo[3][256], shi[3][256];
    const int b = blockIdx.x, tid = threadIdx.x;
    const float* cb = coords + (long)b * bstride;
    float l0 = 3.4e38f, l1 = 3.4e38f, l2 = 3.4e38f;
    float h0 = -3.4e38f, h1 = -3.4e38f, h2 = -3.4e38f;
    for (int n = tid; n < NPT; n += 256) {
        float x = cb[(long)n * sn], y = cb[(long)n * sn + sc], z = cb[(long)n * sn + 2 * sc];
        l0 = fminf(l0, x); h0 = fmaxf(h0, x);
        l1 = fminf(l1, y); h1 = fmaxf(h1, y);
        l2 = fminf(l2, z); h2 = fmaxf(h2, z);
    }
    slo[0][tid] = l0; slo[1][tid] = l1; slo[2][tid] = l2;
    shi[0][tid] = h0; shi[1][tid] = h1; shi[2][tid] = h2;
    __syncthreads();
    for (int off = 128; off; off >>= 1) {
        if (tid < off) {
            #pragma unroll
            for (int a = 0; a < 3; a++) {
                slo[a][tid] = fminf(slo[a][tid], slo[a][tid + off]);
                shi[a][tid] = fmaxf(shi[a][tid], shi[a][tid + off]);
            }
        }
        __syncthreads();
    }
    if (tid < 3) { g_blo[b * 3 + tid] = slo[tid][0]; g_bhi[b * 3 + tid] = shi[tid][0]; }
    for (int i = tid; i < NCELL; i += 256) {
        g_hist[b * NCELL + i] = 0;
        g_cursor[b * NCELL + i] = 0;
    }
}

// ---------------- stage B: cell ids + histogram -----------------------------
__global__ void cellcount_kernel(const float* __restrict__ coords, int sn, int sc,
                                 long bstride)
{
    const int b = blockIdx.y;
    const int n = blockIdx.x * 256 + threadIdx.x;
    const float* cb = coords + (long)b * bstride;
    float x = cb[(long)n * sn], y = cb[(long)n * sn + sc], z = cb[(long)n * sn + 2 * sc];
    float lo0 = g_blo[b * 3], lo1 = g_blo[b * 3 + 1], lo2 = g_blo[b * 3 + 2];
    float s0 = (float)GRES / fmaxf(g_bhi[b * 3]     - lo0, 1e-30f);
    float s1 = (float)GRES / fmaxf(g_bhi[b * 3 + 1] - lo1, 1e-30f);
    float s2 = (float)GRES / fmaxf(g_bhi[b * 3 + 2] - lo2, 1e-30f);
    int cx = min(GRES - 1, max(0, (int)((x - lo0) * s0)));
    int cy = min(GRES - 1, max(0, (int)((y - lo1) * s1)));
    int cz = min(GRES - 1, max(0, (int)((z - lo2) * s2)));
    int cell = morton3(cx, cy, cz);
    g_cellid[b * NPT + n] = cell;
    atomicAdd(&g_hist[b * NCELL + cell], 1);
}

// ---------------- stage C: per-batch exclusive scan over 4096 cells ---------
__global__ void scan_kernel()
{
    __shared__ int ss[1024];
    const int b = blockIdx.x, tid = threadIdx.x;
    int v[4]; int base = tid * 4; int s = 0;
    #pragma unroll
    for (int i = 0; i < 4; i++) { v[i] = g_hist[b * NCELL + base + i]; s += v[i]; }
    ss[tid] = s;
    __syncthreads();
    for (int off = 1; off < 1024; off <<= 1) {
        int t = (tid >= off) ? ss[tid - off] : 0;
        __syncthreads();
        ss[tid] += t;
        __syncthreads();
    }
    int ex = ss[tid] - s;
    #pragma unroll
    for (int i = 0; i < 4; i++) { g_cstart[b * NCELL + base + i] = ex; ex += v[i]; }
}

// ---------------- stage D: scatter into Morton order ------------------------
__global__ void scatter_kernel(const float* __restrict__ coords, int sn, int sc,
                               long bstride)
{
    const int b = blockIdx.y;
    const int n = blockIdx.x * 256 + threadIdx.x;
    const float* cb = coords + (long)b * bstride;
    float x = cb[(long)n * sn], y = cb[(long)n * sn + sc], z = cb[(long)n * sn + 2 * sc];
    int cell = g_cellid[b * NPT + n];
    int pos = g_cstart[b * NCELL + cell] + atomicAdd(&g_cursor[b * NCELL + cell], 1);
    float xx = __fadd_rn(__fadd_rn(__fmul_rn(x, x), __fmul_rn(y, y)), __fmul_rn(z, z));
    g_pts4[b * NPT + pos] = make_float4(x, y, z, xx);
    g_pid[b * NPT + pos] = n;
}

// ---------------- stage E: per-tile AABB + max xx ---------------------------
__global__ void tilestats_kernel()
{
    __shared__ float r[7][TPT];
    const int b = blockIdx.y, t = blockIdx.x, tid = threadIdx.x;
    float4 p = g_pts4[b * NPT + t * TPT + tid];
    r[0][tid] = p.x; r[1][tid] = p.y; r[2][tid] = p.z;
    r[3][tid] = p.x; r[4][tid] = p.y; r[5][tid] = p.z;
    r[6][tid] = p.w;
    __syncthreads();
    for (int off = TPT / 2; off; off >>= 1) {
        if (tid < off) {
            r[0][tid] = fminf(r[0][tid], r[0][tid + off]);
            r[1][tid] = fminf(r[1][tid], r[1][tid + off]);
            r[2][tid] = fminf(r[2][tid], r[2][tid + off]);
            r[3][tid] = fmaxf(r[3][tid], r[3][tid + off]);
            r[4][tid] = fmaxf(r[4][tid], r[4][tid + off]);
            r[5][tid] = fmaxf(r[5][tid], r[5][tid + off]);
            r[6][tid] = fmaxf(r[6][tid], r[6][tid + off]);
        }
        __syncthreads();
    }
    if (tid == 0) {
        g_tlo4[b * NTILE + t] = make_float4(r[0][0], r[1][0], r[2][0], r[6][0]);
        g_thi4[b * NTILE + t] = make_float4(r[3][0], r[4][0], r[5][0], 0.f);
    }
}

// ---------------- stage F: warp-per-query pruned exact KNN ------------------
#define QWARPS 8
#define MERGE_THRESH 6

__global__ void knn_query_warp_kernel(int* __restrict__ out_idx)
{
    __shared__ float4 s_tA[NTILE], s_tB[NTILE];
    __shared__ unsigned char s_surv[QWARPS][NTILE];

    const int lane = threadIdx.x & 31;
    const int w    = threadIdx.x >> 5;
    const int b    = blockIdx.y;
    const int p    = blockIdx.x * QWARPS + w;   // query position in sorted order

    for (int i = threadIdx.x; i < NTILE; i += QWARPS * 32) {
        s_tA[i] = g_tlo4[b * NTILE + i];
        s_tB[i] = g_thi4[b * NTILE + i];
    }
    __syncthreads();

    const float4 q = g_pts4[b * NPT + p];
    const int qid = g_pid[b * NPT + p];
    const float nxxq = -q.w;
    const int t0 = p / TPT;

    // ---- seed from own tile: top-32 of 64 via sort + merge ----
    const int base0 = b * NPT + t0 * TPT;
    float4 cA = __ldg(&g_pts4[base0 + lane]);
    float4 cB = __ldg(&g_pts4[base0 + 32 + lane]);
    int    iA = __ldg(&g_pid[base0 + lane]);
    int    iB = __ldg(&g_pid[base0 + 32 + lane]);
    unsigned long long keyA = mk_key(q, nxxq, cA, iA);
    unsigned long long keyB = mk_key(q, nxxq, cB, iB);

    unsigned long long v = bitonic32_asc(keyA, lane);
    v = merge_topk(v, keyB, lane);
    unsigned long long rootk = __shfl_sync(0xffffffffu, v, 0);

    // ---- cull all tiles 32-wide, build survivor list (ascending t) ----
    int nsurv = 0, nbelow = 0;
    {
        float root_s = unkey((unsigned)(rootk >> 32));
        #pragma unroll
        for (int r = 0; r < NTILE / 32; r++) {
            int t = r * 32 + lane;
            float4 tA = s_tA[t], tB = s_tB[t];
            float d2 = 0.f;
            float d = fmaxf(fmaxf(tA.x - q.x, q.x - tB.x), 0.f); d2 = fmaf(d, d, d2);
            d = fmaxf(fmaxf(tA.y - q.y, q.y - tB.y), 0.f);       d2 = fmaf(d, d, d2);
            d = fmaxf(fmaxf(tA.z - q.z, q.z - tB.z), 0.f);       d2 = fmaf(d, d, d2);
            float margin = fmaf(2e-6f, q.w + tA.w, 1e-6f);
            bool surv = (t != t0) && (d2 * 0.999999f <= -root_s + margin);
            unsigned m = __ballot_sync(0xffffffffu, surv);
            int mypos = nsurv + __popc(m & ((1u << lane) - 1));
            if (surv) s_surv[w][mypos] = (unsigned char)t;
            nsurv += __popc(m);
            nbelow += __popc(m & __ballot_sync(0xffffffffu, t < t0));
        }
    }
    __syncwarp();

    // ---- scan surviving tiles outward from t0 (two-pointer) ----
    int lo = nbelow - 1, hi = nbelow;
    for (int i = 0; i < nsurv; i++) {
        int t;
        bool use_hi = ((i & 1) == 0) ? (hi < nsurv) : (lo < 0);
        if (use_hi) t = s_surv[w][hi++];
        else        t = s_surv[w][lo--];

        // re-check with current (tighter) root — uniform branch
        float4 tA = s_tA[t], tB = s_tB[t];
        float root_s = unkey((unsigned)(rootk >> 32));
        float d2 = 0.f;
        {
            float d = fmaxf(fmaxf(tA.x - q.x, q.x - tB.x), 0.f); d2 = fmaf(d, d, d2);
            d = fmaxf(fmaxf(tA.y - q.y, q.y - tB.y), 0.f);       d2 = fmaf(d, d, d2);
            d = fmaxf(fmaxf(tA.z - q.z, q.z - tB.z), 0.f);       d2 = fmaf(d, d, d2);
        }
        float margin = fmaf(2e-6f, q.w + tA.w, 1e-6f);
        if (d2 * 0.999999f > -root_s + margin) continue;

        // issue both half-loads before dependent work (latency overlap)
        const int cb0 = b * NPT + t * TPT;
        float4 c0 = __ldg(&g_pts4[cb0 + lane]);
        float4 c1 = __ldg(&g_pts4[cb0 + 32 + lane]);
        int    i0 = __ldg(&g_pid[cb0 + lane]);
        int    i1 = __ldg(&g_pid[cb0 + 32 + lane]);
        unsigned long long k0 = mk_key(q, nxxq, c0, i0);
        unsigned long long k1 = mk_key(q, nxxq, c1, i1);

        #pragma unroll
        for (int half = 0; half < 2; half++) {
            unsigned long long key = half ? k1 : k0;
            unsigned mask = __ballot_sync(0xffffffffu, key > rootk);
            int cnt = __popc(mask);
            if (cnt == 0) continue;
            if (cnt >= MERGE_THRESH) {
                v = merge_topk(v, key, lane);
                rootk = __shfl_sync(0xffffffffu, v, 0);
            } else {
                while (mask) {
                    int src = __ffs(mask) - 1; mask &= mask - 1;
                    unsigned long long k = __shfl_sync(0xffffffffu, key, src);
                    if (k > rootk) {
                        v = sorted_insert(v, k, lane);
                        rootk = __shfl_sync(0xffffffffu, v, 0);
                    }
                }
            }
        }
    }

    // ---- v sorted ascending; write in top_k (desc) order ----
    int* op = out_idx + (long)(b * NPT + qid) * KNN;
    op[31 - lane] = (int)(~(unsigned)v);
}

// --------- geometry (cov eig features, fp32) + saliency + x ----------------
#define GEO_BLK 64

__global__ void geom_kernel(const float* __restrict__ points,
                            const int*   __restrict__ idx,
                            const float* __restrict__ sal_w1,
                            const float* __restrict__ sal_g, const float* __restrict__ sal_b,
                            const float* __restrict__ sal_m, const float* __restrict__ sal_v,
                            const float* __restrict__ sal_w2, const float* __restrict__ sal_b2,
                            float* __restrict__ xout)
{
    __shared__ float sx[KNN * GEO_BLK], sy[KNN * GEO_BLK], sz[KNN * GEO_BLK];
    const int tid = threadIdx.x;
    const int b   = blockIdx.y;
    const int q   = blockIdx.x * GEO_BLK + tid;
    const float* pb = points + (long)b * 3 * NPT;
    const int* ip = idx + (long)(b * NPT + q) * KNN;

    float mx = 0.f, my = 0.f, mz = 0.f;
    #pragma unroll
    for (int k = 0; k < KNN; k++) {
        int j = ip[k];
        float nx = pb[j], ny = pb[NPT + j], nz = pb[2 * NPT + j];
        sx[k * GEO_BLK + tid] = nx; sy[k * GEO_BLK + tid] = ny; sz[k * GEO_BLK + tid] = nz;
        mx += nx; my += ny; mz += nz;
    }
    mx *= (1.f / KNN); my *= (1.f / KNN); mz *= (1.f / KNN);

    float cxx = 0.f, cxy = 0.f, cxz = 0.f, cyy = 0.f, cyz = 0.f, czz = 0.f;
    #pragma unroll
    for (int k = 0; k < KNN; k++) {
        float dx = sx[k * GEO_BLK + tid] - mx;
        float dy = sy[k * GEO_BLK + tid] - my;
        float dz = sz[k * GEO_BLK + tid] - mz;
        cxx = fmaf(dx, dx, cxx); cxy = fmaf(dx, dy, cxy); cxz = fmaf(dx, dz, cxz);
        cyy = fmaf(dy, dy, cyy); cyz = fmaf(dy, dz, cyz); czz = fmaf(dz, dz, czz);
    }
    const float invk = 1.f / KNN;
    cxx *= invk; cxy *= invk; cxz *= invk; cyy *= invk; cyz *= invk; czz *= invk;

    float q3 = (cxx + cyy + czz) * (1.f / 3.f);
    float p1 = cxy * cxy + cxz * cxz + cyz * cyz;
    float b00 = cxx - q3, b11 = cyy - q3, b22 = czz - q3;
    float p2 = b00 * b00 + b11 * b11 + b22 * b22 + 2.f * p1;
    float p = sqrtf(p2 * (1.f / 6.f));
    float e1, e2, e3;
    if (p < 1e-20f) { e1 = e2 = e3 = q3; }
    else {
        float inv = 1.f / p;
        float n00 = b00 * inv, n11 = b11 * inv, n22 = b22 * inv;
        float n01 = cxy * inv, n02 = cxz * inv, n12 = cyz * inv;
        float detB = n00 * (n11 * n22 - n12 * n12) - n01 * (n01 * n22 - n12 * n02)
                   + n02 * (n01 * n12 - n11 * n02);
        float r = 0.5f * detB;
        r = fminf(1.f, fmaxf(-1.f, r));
        float phi = acosf(r) * (1.f / 3.f);
        e1 = q3 + 2.f * p * cosf(phi);
        e3 = q3 + 2.f * p * cosf(phi + 2.09439510239f);
        e2 = 3.f * q3 - e1 - e3;
    }
    float l0 = e3, l1 = e2, l2 = e1;
    const float eps = 1e-8f;
    float geomf[5];
    float invl2 = 1.f / (l2 + eps);
    geomf[0] = (l2 - l1) * invl2;
    geomf[1] = (l1 - l0) * invl2;
    geomf[2] = l0 * invl2;
    geomf[3] = l0 / (l0 + l1 + l2 + eps);
    geomf[4] = (l2 - l0) * invl2;

    float dot = 0.f;
    #pragma unroll
    for (int o = 0; o < 16; o++) {
        float h = 0.f;
        #pragma unroll
        for (int f = 0; f < 5; f++) h = fmaf(sal_w1[o * 5 + f], geomf[f], h);
        float s = sal_g[o] * rsqrtf(sal_v[o] + 1e-5f);
        float t = sal_b[o] - sal_m[o] * s;
        h = leakyf(fmaf(h, s, t));
        dot = fmaf(h, sal_w2[o], dot);
    }
    float sal = 1.f / (1.f + expf(-(dot + sal_b2[0])));

    float* xr = xout + (long)(b * NPT + q) * 9;
    xr[0] = pb[q]; xr[1] = pb[NPT + q]; xr[2] = pb[2 * NPT + q];
    xr[3] = geomf[0]; xr[4] = geomf[1]; xr[5] = geomf[2]; xr[6] = geomf[3]; xr[7] = geomf[4];
    xr[8] = sal;
}

// ------- edge_conv1 precompute (CIN=9, cheap): per-thread dot products ------
template<int CIN>
__global__ void convpre_kernel(const float* __restrict__ xin,
                               const float* __restrict__ w,
                               const float* __restrict__ bng, const float* __restrict__ bnb,
                               const float* __restrict__ bnm, const float* __restrict__ bnv,
                               float* __restrict__ ys, float* __restrict__ zc)
{
    long T = (long)blockIdx.x * blockDim.x + threadIdx.x;
    int  o = (int)(T & 63);
    long p = T >> 6;
    if (p >= (long)BATCH * NPT) return;
    const float* xr = xin + p * CIN;
    const float* wd = w + (long)o * 2 * CIN;
    const float* wc = wd + CIN;
    float ad = 0.f, ac = 0.f;
    #pragma unroll
    for (int c = 0; c < CIN; c++) {
        float xv = xr[c];
        float a = wd[c];
        ad = fmaf(a, xv, ad);
        ac = fmaf(wc[c] - a, xv, ac);
    }
    float s = bng[o] * rsqrtf(bnv[o] + 1e-5f);
    float t = bnb[o] - bnm[o] * s;
    ys[p * 64 + o] = s * ad;
    zc[p * 64 + o] = fmaf(s, ac, t);
}

// ------- edge_conv2 precompute (CIN=64): smem-transposed weights, 4 pts/blk -
#define CP_PTS 4

__global__ void convpre64_kernel(const float* __restrict__ xin,
                                 const float* __restrict__ w,
                                 const float* __restrict__ bng, const float* __restrict__ bnb,
                                 const float* __restrict__ bnm, const float* __restrict__ bnv,
                                 float* __restrict__ ys, float* __restrict__ zc)
{
    __shared__ float A[64][64];
    __shared__ float Bm[64][64];
    __shared__ float xs[CP_PTS][64];

    const int tid = threadIdx.x;      // 256
    for (int i = tid; i < 64 * 64; i += 256) {
        int o = i >> 6, c = i & 63;
        float wd = w[o * 128 + c];
        float wc = w[o * 128 + 64 + c];
        A[c][o]  = wd;
        Bm[c][o] = wc - wd;
    }
    long pbase = (long)blockIdx.x * CP_PTS;
    xs[tid >> 6][tid & 63] = xin[pbase * 64 + tid];
    __syncthreads();

    const int pl = tid >> 6, o = tid & 63;
    const float* xr = xs[pl];
    float ad = 0.f, ac = 0.f;
    #pragma unroll
    for (int c = 0; c < 64; c++) {
        float xv = xr[c];
        ad = fmaf(A[c][o], xv, ad);
        ac = fmaf(Bm[c][o], xv, ac);
    }
    float s = bng[o] * rsqrtf(bnv[o] + 1e-5f);
    float t = bnb[o] - bnm[o] * s;
    long p = pbase + pl;
    ys[p * 64 + o] = s * ad;
    zc[p * 64 + o] = fmaf(s, ac, t);
}

// ------- edge_conv reduce: x_out[i] = leaky(max_k (ys[idx[i,k]] + zc[i])) ---
__global__ void edge_reduce_kernel(const float* __restrict__ ys, const float* __restrict__ zc,
                                   const int* __restrict__ idx, float* __restrict__ xout)
{
    long warp = ((long)blockIdx.x * blockDim.x + threadIdx.x) >> 5;
    int  lane = threadIdx.x & 31;
    if (warp >= (long)BATCH * NPT) return;
    const long bbase = (warp >> 13) << 13;
    int myj = idx[warp * KNN + lane];
    const float2* ysp = (const float2*)ys;
    float2 z = ((const float2*)zc)[warp * 32 + lane];
    float2 best = make_float2(-3.4e38f, -3.4e38f);
    #pragma unroll
    for (int k = 0; k < KNN; k++) {
        long j = bbase + __shfl_sync(0xffffffffu, myj, k);
        float2 v = ysp[j * 32 + lane];
        best.x = fmaxf(best.x, v.x + z.x);
        best.y = fmaxf(best.y, v.y + z.y);
    }
    best.x = leakyf(best.x);
    best.y = leakyf(best.y);
    ((float2*)xout)[warp * 32 + lane] = best;
}

// --------- classifier: 4-point register blocking, exact per-point numerics --
#define CLS_GRID 256
#define CLS_PTS  4
#define CLS_PPB  ((BATCH*NPT)/CLS_GRID)     // 128 points per block
#define CLS_IT   (CLS_PPB/CLS_PTS)          // 32 iterations

__global__ void cls_kernel(const float* __restrict__ x1, const float* __restrict__ x2,
                           const float* __restrict__ w1,
                           const float* __restrict__ bg, const float* __restrict__ bb,
                           const float* __restrict__ bm, const float* __restrict__ bv,
                           const float* __restrict__ w2, const float* __restrict__ b2,
                           float* __restrict__ out)
{
    extern __shared__ float sm[];
    float* WsT  = sm;                   // [128][256]
    float* Ts   = WsT + 128 * 256;      // 256
    float* W2s  = Ts + 256;             // 2*256
    float* gbuf = W2s + 512;            // [128][CLS_PTS]
    float* red  = gbuf + 128 * CLS_PTS; // [CLS_PTS][16]

    const int tid = threadIdx.x;        // 256 threads, tid == output channel o
    {
        float s = bg[tid] * rsqrtf(bv[tid] + 1e-5f);
        Ts[tid] = bb[tid] - bm[tid] * s;
        for (int c = 0; c < 128; c++) WsT[c * 256 + tid] = w1[tid * 128 + c] * s;
        W2s[tid] = w2[tid]; W2s[256 + tid] = w2[256 + tid];
    }
    __syncthreads();

    for (int it = 0; it < CLS_IT; it++) {
        long P = (long)blockIdx.x * CLS_PPB + it * CLS_PTS;
        // load 4 points' 128-ch activations into gbuf[c][p]
        #pragma unroll
        for (int i = tid; i < 128 * CLS_PTS; i += 256) {
            int pp = i >> 7, c = i & 127;
            float val = (c < 64) ? x1[(P + pp) * 64 + c] : x2[(P + pp) * 64 + c - 64];
            gbuf[c * CLS_PTS + pp] = val;
        }
        __syncthreads();

        float a0 = Ts[tid], a1 = a0, a2 = a0, a3 = a0;
        #pragma unroll 4
        for (int c = 0; c < 128; c++) {
            float wv = WsT[c * 256 + tid];
            float4 g = *(const float4*)&gbuf[c * CLS_PTS];
            a0 = fmaf(wv, g.x, a0);
            a1 = fmaf(wv, g.y, a1);
            a2 = fmaf(wv, g.z, a2);
            a3 = fmaf(wv, g.w, a3);
        }
        float h[CLS_PTS] = { leakyf(a0), leakyf(a1), leakyf(a2), leakyf(a3) };

        int wp = tid >> 5;
        #pragma unroll
        for (int pp = 0; pp < CLS_PTS; pp++) {
            float p0 = h[pp] * W2s[tid], p1 = h[pp] * W2s[256 + tid];
            #pragma unroll
            for (int off = 16; off; off >>= 1) {
                p0 += __shfl_down_sync(0xffffffffu, p0, off);
                p1 += __shfl_down_sync(0xffffffffu, p1, off);
            }
            if ((tid & 31) == 0) { red[pp * 16 + wp] = p0; red[pp * 16 + 8 + wp] = p1; }
        }
        __syncthreads();
        if (tid < CLS_PTS) {
            float l0 = b2[0], l1 = b2[1];
            #pragma unroll
            for (int i = 0; i < 8; i++) { l0 += red[tid * 16 + i]; l1 += red[tid * 16 + 8 + i]; }
            long Pp = P + tid;
            long bbatch = Pp / NPT, nn = Pp % NPT;
            out[bbatch * 2 * NPT + nn]       = l0;
            out[bbatch * 2 * NPT + NPT + nn] = l1;
        }
        __syncthreads();
    }
}

// ---------------------------------------------------------------------------
static void run_knn(const float* coords, int sn, int sc, long bstride, int* out_idx)
{
    bounds_kernel<<<BATCH, 256>>>(coords, sn, sc, bstride);
    cellcount_kernel<<<dim3(NPT / 256, BATCH), 256>>>(coords, sn, sc, bstride);
    scan_kernel<<<BATCH, 1024>>>();
    scatter_kernel<<<dim3(NPT / 256, BATCH), 256>>>(coords, sn, sc, bstride);
    tilestats_kernel<<<dim3(NTILE, BATCH), TPT>>>();
    knn_query_warp_kernel<<<dim3(NPT / QWARPS, BATCH), QWARPS * 32>>>(out_idx);
}

extern "C" void kernel_launch(void* const* d_in, const int* in_sizes, int n_in,
                              void* d_out, int out_size)
{
    const float* points  = (const float*)d_in[0];
    const float* sal_w1  = (const float*)d_in[1];
    const float* sal_g   = (const float*)d_in[2];
    const float* sal_b   = (const float*)d_in[3];
    const float* sal_m   = (const float*)d_in[4];
    const float* sal_v   = (const float*)d_in[5];
    const float* sal_w2  = (const float*)d_in[6];
    const float* sal_b2  = (const float*)d_in[7];
    const float* c1_w    = (const float*)d_in[8];
    const float* c1_g    = (const float*)d_in[9];
    const float* c1_b    = (const float*)d_in[10];
    const float* c1_m    = (const float*)d_in[11];
    const float* c1_v    = (const float*)d_in[12];
    const float* c2_w    = (const float*)d_in[13];
    const float* c2_g    = (const float*)d_in[14];
    const float* c2_b    = (const float*)d_in[15];
    const float* c2_m    = (const float*)d_in[16];
    const float* c2_v    = (const float*)d_in[17];
    const float* cls_w1  = (const float*)d_in[18];
    const float* cls_g   = (const float*)d_in[19];
    const float* cls_b   = (const float*)d_in[20];
    const float* cls_m   = (const float*)d_in[21];
    const float* cls_v   = (const float*)d_in[22];
    const float* cls_w2  = (const float*)d_in[23];
    const float* cls_b2  = (const float*)d_in[24];
    float* out = (float*)d_out;

    int*   idx1; cudaGetSymbolAddress((void**)&idx1, g_idx1);
    int*   idx2; cudaGetSymbolAddress((void**)&idx2, g_idx2);
    float* xf  ; cudaGetSymbolAddress((void**)&xf , g_x  );
    float* ys1 ; cudaGetSymbolAddress((void**)&ys1, g_ys1);
    float* zc1 ; cudaGetSymbolAddress((void**)&zc1, g_zc1);
    float* x1  ; cudaGetSymbolAddress((void**)&x1 , g_x1 );
    float* ys2 ; cudaGetSymbolAddress((void**)&ys2, g_ys2);
    float* zc2 ; cudaGetSymbolAddress((void**)&zc2, g_zc2);
    float* x2  ; cudaGetSymbolAddress((void**)&x2 , g_x2 );

    // 1) knn on raw points (layout (B,3,N): sn=1, sc=N)
    run_knn(points, 1, NPT, (long)3 * NPT, idx1);

    // 2) geometry + saliency -> x (B,N,9)
    geom_kernel<<<dim3(NPT / GEO_BLK, BATCH), GEO_BLK>>>(
        points, idx1, sal_w1, sal_g, sal_b, sal_m, sal_v, sal_w2, sal_b2, xf);

    // 3) edge_conv1 -> x1
    {
        long total = (long)BATCH * NPT * 64;
        convpre_kernel<9><<<(unsigned)(total / 128), 128>>>(xf, c1_w, c1_g, c1_b, c1_m, c1_v, ys1, zc1);
        edge_reduce_kernel<<<(BATCH * NPT) / 4, 128>>>(ys1, zc1, idx1, x1);
    }

    // 4) knn on x1[...,0:3] (layout (B,N,64): sn=64, sc=1)
    run_knn(x1, 64, 1, (long)NPT * 64, idx2);

    // 5) edge_conv2 -> x2 (smem-transposed convpre)
    {
        convpre64_kernel<<<(BATCH * NPT) / CP_PTS, 256>>>(x1, c2_w, c2_g, c2_b, c2_m, c2_v, ys2, zc2);
        edge_reduce_kernel<<<(BATCH * NPT) / 4, 128>>>(ys2, zc2, idx2, x2);
    }

    // 6) classifier
    {
        size_t smem = (128 * 256 + 256 + 512 + 128 * CLS_PTS + 16 * CLS_PTS) * sizeof(float);
        cudaFuncSetAttribute(cls_kernel, cudaFuncAttributeMaxDynamicSharedMemorySize, (int)smem);
        cls_kernel<<<CLS_GRID, 256, smem>>>(x1, x2, cls_w1,
                                            cls_g, cls_b, cls_m, cls_v,
                                            cls_w2, cls_b2, out);
    }
}